// round 4
// baseline (speedup 1.0000x reference)
#include <cuda_runtime.h>
#include <math.h>

#define TN   32768
#define C_   256
#define B_   64
#define N_   512
#define H_   4
#define DH_  64
#define M_   266
#define MP_  272
#define E_   524288
#define L_   5

typedef unsigned long long ull;

// ---------------- scratch ----------------
__device__ float g_atoms[TN * C_];
__device__ float g_h0[TN * C_];
__device__ float g_t1[TN * 2 * C_];
__device__ float g_hloc[TN * C_];
__device__ float g_q[TN * C_];
__device__ float g_k[TN * C_];
__device__ float g_v[TN * C_];
__device__ float g_att[TN * C_];
__device__ float g_out[TN * C_];
__device__ int   g_deg[TN];
__device__ int   g_indptr[TN + 1];
__device__ int   g_cursor[TN];
__device__ int   g_eadj[E_];

// ---------------- helpers ----------------
__device__ __forceinline__ ull f2pack(float x, float y) {
    ull r; asm("mov.b64 %0, {%1, %2};" : "=l"(r) : "f"(x), "f"(y)); return r;
}
__device__ __forceinline__ void f2unpack(ull p, float &x, float &y) {
    asm("mov.b64 {%0, %1}, %2;" : "=f"(x), "=f"(y) : "l"(p));
}
__device__ __forceinline__ ull ffma2(ull a, ull b, ull c) {
    ull d; asm("fma.rn.f32x2 %0, %1, %2, %3;" : "=l"(d) : "l"(a), "l"(b), "l"(c)); return d;
}
__device__ __forceinline__ float gelu_exact(float x) {
    return 0.5f * x * (1.0f + erff(x * 0.70710678118654752f));
}

// ---------------- node embedding ----------------
__global__ void node_embed_kernel(const float* __restrict__ x,
                                  const float* __restrict__ w,
                                  const float* __restrict__ b) {
    __shared__ float lx[11];
    int row = blockIdx.x;
    int t = threadIdx.x;
    if (t < 11) lx[t] = log1pf(x[row * 11 + t]);
    __syncthreads();
    float s = b[t];
#pragma unroll
    for (int j = 0; j < 11; j++) s += lx[j] * w[j * C_ + t];
    g_atoms[row * C_ + t] = s;
}

// ---------------- CSR build ----------------
__global__ void zero_deg_kernel() {
    int i = blockIdx.x * blockDim.x + threadIdx.x;
    if (i < TN) g_deg[i] = 0;
}
__global__ void count_deg_kernel(const int* __restrict__ dst) {
    int e = blockIdx.x * blockDim.x + threadIdx.x;
    if (e < E_) atomicAdd(&g_deg[dst[e]], 1);
}
__global__ void scan_deg_kernel() {
    __shared__ int sh[1024];
    __shared__ int carry;
    int t = threadIdx.x;
    if (t == 0) carry = 0;
    __syncthreads();
    for (int base = 0; base < TN; base += 1024) {
        int v = g_deg[base + t];
        sh[t] = v;
        __syncthreads();
        for (int off = 1; off < 1024; off <<= 1) {
            int add = (t >= off) ? sh[t - off] : 0;
            __syncthreads();
            sh[t] += add;
            __syncthreads();
        }
        int ip = carry + sh[t] - v;
        g_indptr[base + t] = ip;
        g_cursor[base + t] = ip;
        __syncthreads();
        if (t == 0) carry += sh[1023];
        __syncthreads();
    }
    if (t == 0) g_indptr[TN] = carry;
}
__global__ void fill_adj_kernel(const int* __restrict__ dst) {
    int e = blockIdx.x * blockDim.x + threadIdx.x;
    if (e < E_) {
        int p = atomicAdd(&g_cursor[dst[e]], 1);
        g_eadj[p] = e;
    }
}

// ---------------- GINE aggregation ----------------
__global__ void __launch_bounds__(256) gine_kernel(const int* __restrict__ src,
                                                   const float* __restrict__ eattr,
                                                   const float* __restrict__ ew,
                                                   const float* __restrict__ eb) {
    __shared__ float sew[4][C_];
    __shared__ float seb[C_];
    int tid = threadIdx.x;
    for (int i = tid; i < 4 * C_; i += 256) sew[i >> 8][i & 255] = ew[i];
    seb[tid] = eb[tid];
    __syncthreads();
    int warp = tid >> 5, lane = tid & 31;
    int v = blockIdx.x * 8 + warp;
    float acc[8];
#pragma unroll
    for (int k = 0; k < 8; k++) acc[k] = g_atoms[v * C_ + lane + 32 * k];
    int p0 = g_indptr[v], p1 = g_indptr[v + 1];
    for (int p = p0; p < p1; p++) {
        int e = g_eadj[p];
        int s = src[e];
        float4 ea4 = *reinterpret_cast<const float4*>(&eattr[e * 4]);
        const float* arow = &g_atoms[s * C_];
#pragma unroll
        for (int k = 0; k < 8; k++) {
            int c = lane + 32 * k;
            float eac = seb[c] + ea4.x * sew[0][c] + ea4.y * sew[1][c]
                               + ea4.z * sew[2][c] + ea4.w * sew[3][c];
            acc[k] += fmaxf(arow[c] + eac, 0.0f);
        }
    }
#pragma unroll
    for (int k = 0; k < 8; k++) g_h0[v * C_ + lane + 32 * k] = acc[k];
}

// ---------------- fused GEMM (64x256 tile) ----------------
// MODE 0: +bias   MODE 1: gelu(+bias)
// MODE 2: LN(+bias+res)   MODE 3: LN(+bias+res)+add2     (MODE>=2: Ntot==256)
template <int MODE>
__global__ void __launch_bounds__(256) gemm_kernel(const float* __restrict__ A,
                                                   const float* __restrict__ W,
                                                   const float* __restrict__ bias,
                                                   const float* __restrict__ res,
                                                   const float* __restrict__ add2,
                                                   const float* __restrict__ lng,
                                                   const float* __restrict__ lnb,
                                                   float* __restrict__ Out,
                                                   int K, int Ntot) {
    __shared__ float Bs[16][256];
    __shared__ float As[64][17];
    const int rowbase = blockIdx.x * 64;
    const int colbase = blockIdx.y * 256;
    const int tid = threadIdx.x;
    const int tx = tid & 31, ty = tid >> 5;

    ull acc[8][4];
#pragma unroll
    for (int i = 0; i < 8; i++)
#pragma unroll
        for (int q = 0; q < 4; q++) acc[i][q] = 0ull;

    const int kkA = tid & 15;
    const int r0 = (tid >> 4) << 2;

    for (int k0 = 0; k0 < K; k0 += 16) {
#pragma unroll
        for (int i = 0; i < 4; i++)
            As[r0 + i][kkA] = A[(rowbase + r0 + i) * K + k0 + kkA];
#pragma unroll
        for (int t = 0; t < 4; t++) {
            int L4 = tid + t * 256;
            int kb = L4 >> 6;
            int c4 = (L4 & 63) << 2;
            *reinterpret_cast<float4*>(&Bs[kb][c4]) =
                *reinterpret_cast<const float4*>(&W[(k0 + kb) * Ntot + colbase + c4]);
        }
        __syncthreads();
#pragma unroll
        for (int kk = 0; kk < 16; kk++) {
            ull b2[4];
#pragma unroll
            for (int q = 0; q < 4; q++)
                b2[q] = *reinterpret_cast<const ull*>(&Bs[kk][tx * 2 + 64 * q]);
#pragma unroll
            for (int i = 0; i < 8; i++) {
                float av = As[ty * 8 + i][kk];
                ull a2 = f2pack(av, av);
#pragma unroll
                for (int q = 0; q < 4; q++)
                    acc[i][q] = ffma2(a2, b2[q], acc[i][q]);
            }
        }
        __syncthreads();
    }

    const int row0 = rowbase + ty * 8;
    const int c0 = colbase + tx * 2;
    float bb[8], gg[8], bt[8];
#pragma unroll
    for (int q = 0; q < 4; q++) {
#pragma unroll
        for (int r = 0; r < 2; r++) {
            int col = c0 + 64 * q + r;
            bb[2 * q + r] = bias ? bias[col] : 0.0f;
            if (MODE >= 2) { gg[2 * q + r] = lng[col]; bt[2 * q + r] = lnb[col]; }
        }
    }

#pragma unroll
    for (int i = 0; i < 8; i++) {
        int row = row0 + i;
        float vv[8];
#pragma unroll
        for (int q = 0; q < 4; q++) f2unpack(acc[i][q], vv[2 * q], vv[2 * q + 1]);
#pragma unroll
        for (int j = 0; j < 8; j++) vv[j] += bb[j];

        if (MODE == 0) {
#pragma unroll
            for (int q = 0; q < 4; q++)
                *reinterpret_cast<float2*>(&Out[row * Ntot + c0 + 64 * q]) =
                    make_float2(vv[2 * q], vv[2 * q + 1]);
        } else if (MODE == 1) {
#pragma unroll
            for (int q = 0; q < 4; q++)
                *reinterpret_cast<float2*>(&Out[row * Ntot + c0 + 64 * q]) =
                    make_float2(gelu_exact(vv[2 * q]), gelu_exact(vv[2 * q + 1]));
        } else {
#pragma unroll
            for (int q = 0; q < 4; q++) {
                float2 rr = *reinterpret_cast<const float2*>(&res[row * 256 + c0 + 64 * q]);
                vv[2 * q] += rr.x; vv[2 * q + 1] += rr.y;
            }
            float s1 = 0.0f, s2 = 0.0f;
#pragma unroll
            for (int j = 0; j < 8; j++) { s1 += vv[j]; s2 += vv[j] * vv[j]; }
#pragma unroll
            for (int off = 16; off > 0; off >>= 1) {
                s1 += __shfl_xor_sync(0xffffffffu, s1, off);
                s2 += __shfl_xor_sync(0xffffffffu, s2, off);
            }
            float mean = s1 * (1.0f / 256.0f);
            float var = s2 * (1.0f / 256.0f) - mean * mean;
            float rstd = rsqrtf(var + 1e-5f);
#pragma unroll
            for (int q = 0; q < 4; q++) {
                float y0 = (vv[2 * q] - mean) * rstd * gg[2 * q] + bt[2 * q];
                float y1 = (vv[2 * q + 1] - mean) * rstd * gg[2 * q + 1] + bt[2 * q + 1];
                if (MODE == 3) {
                    float2 aa = *reinterpret_cast<const float2*>(&add2[row * 256 + c0 + 64 * q]);
                    y0 += aa.x; y1 += aa.y;
                }
                *reinterpret_cast<float2*>(&Out[row * 256 + c0 + 64 * q]) = make_float2(y0, y1);
            }
        }
    }
}

// ---------------- Performer attention: one CTA per (b,h) ----------------
#define PERF_SMEM_FLOATS (64 * MP_ + MP_ * 64 + 32 * MP_ + 2048 + 2048 + MP_ + 32)

__device__ __forceinline__ void phi_chunk(const float* __restrict__ ks,
                                          const float* __restrict__ projT,
                                          float* __restrict__ kp, int tid) {
    for (int t = tid; t < 32 * 68; t += 512) {
        int n = t / 68;
        int m0 = (t - n * 68) * 4;
        ull a01 = 0ull, a23 = 0ull;
        const float* krow = &ks[n * 64];
        const float* pT = &projT[m0];
#pragma unroll 8
        for (int d = 0; d < 64; d++) {
            float a = krow[d];
            ull a2 = f2pack(a, a);
            const ull* pp = reinterpret_cast<const ull*>(pT + d * MP_);
            a01 = ffma2(a2, pp[0], a01);
            a23 = ffma2(a2, pp[1], a23);
        }
        float r0, r1, r2, r3;
        f2unpack(a01, r0, r1);
        f2unpack(a23, r2, r3);
        float* kpr = &kp[n * MP_ + m0];
        kpr[0] = (m0 + 0 < M_) ? fmaxf(r0, 0.0f) + 1e-3f : 0.0f;
        kpr[1] = (m0 + 1 < M_) ? fmaxf(r1, 0.0f) + 1e-3f : 0.0f;
        kpr[2] = (m0 + 2 < M_) ? fmaxf(r2, 0.0f) + 1e-3f : 0.0f;
        kpr[3] = (m0 + 3 < M_) ? fmaxf(r3, 0.0f) + 1e-3f : 0.0f;
    }
}

__global__ void __launch_bounds__(512, 1) performer_kernel(const float* __restrict__ Q,
                                                           const float* __restrict__ Kb,
                                                           const float* __restrict__ V,
                                                           const float* __restrict__ proj_l,
                                                           float* __restrict__ Att) {
    extern __shared__ float sm[];
    float* projT = sm;                    // 64*272 : projT[d*MP_+m]
    float* ctx = projT + 64 * MP_;        // 272*64
    float* kp = ctx + MP_ * 64;           // 32*272
    float* ks = kp + 32 * MP_;            // 32*64
    float* vs = ks + 2048;                // 32*64
    float* ksum = vs + 2048;              // 272
    float* den = ksum + MP_;              // 32

    const int tid = threadIdx.x;
    const int bh = blockIdx.x;
    const int b = bh >> 2;
    const int h = bh & 3;
    const int coff = h * 64;

    for (int idx = tid; idx < M_ * 64; idx += 512) {
        int m = idx >> 6, d = idx & 63;
        projT[d * MP_ + m] = proj_l[idx];
    }
    for (int idx = tid; idx < 64 * (MP_ - M_); idx += 512) {
        int d = idx / (MP_ - M_);
        int m = M_ + idx % (MP_ - M_);
        projT[d * MP_ + m] = 0.0f;
    }
    for (int idx = tid; idx < MP_ * 64; idx += 512) ctx[idx] = 0.0f;
    if (tid < MP_) ksum[tid] = 0.0f;
    __syncthreads();

    // pass 1: ksum + ctx
    for (int c = 0; c < 16; c++) {
        int n0 = c * 32;
        for (int idx = tid; idx < 2048; idx += 512) {
            int n = idx >> 6, d = idx & 63;
            int gr = b * N_ + n0 + n;
            ks[idx] = Kb[gr * 256 + coff + d];
            vs[idx] = V[gr * 256 + coff + d];
        }
        __syncthreads();
        phi_chunk(ks, projT, kp, tid);
        __syncthreads();
        for (int m = tid; m < MP_; m += 512) {
            float s = 0.0f;
#pragma unroll 8
            for (int n = 0; n < 32; n++) s += kp[n * MP_ + m];
            ksum[m] += s;
        }
        for (int t = tid; t < 68 * 16; t += 512) {
            int m0 = (t >> 4) << 2;
            int d0 = (t & 15) << 2;
            ull a[4][2];
#pragma unroll
            for (int q = 0; q < 4; q++) { a[q][0] = 0ull; a[q][1] = 0ull; }
#pragma unroll 4
            for (int n = 0; n < 32; n++) {
                float4 kv = *reinterpret_cast<const float4*>(&kp[n * MP_ + m0]);
                const ull* vvp = reinterpret_cast<const ull*>(&vs[n * 64 + d0]);
                ull v01 = vvp[0], v23 = vvp[1];
                a[0][0] = ffma2(f2pack(kv.x, kv.x), v01, a[0][0]);
                a[0][1] = ffma2(f2pack(kv.x, kv.x), v23, a[0][1]);
                a[1][0] = ffma2(f2pack(kv.y, kv.y), v01, a[1][0]);
                a[1][1] = ffma2(f2pack(kv.y, kv.y), v23, a[1][1]);
                a[2][0] = ffma2(f2pack(kv.z, kv.z), v01, a[2][0]);
                a[2][1] = ffma2(f2pack(kv.z, kv.z), v23, a[2][1]);
                a[3][0] = ffma2(f2pack(kv.w, kv.w), v01, a[3][0]);
                a[3][1] = ffma2(f2pack(kv.w, kv.w), v23, a[3][1]);
            }
#pragma unroll
            for (int q = 0; q < 4; q++) {
                float f0, f1, f2v, f3v;
                f2unpack(a[q][0], f0, f1);
                f2unpack(a[q][1], f2v, f3v);
                float* cp = &ctx[(m0 + q) * 64 + d0];
                cp[0] += f0; cp[1] += f1; cp[2] += f2v; cp[3] += f3v;
            }
        }
        __syncthreads();
    }

    // pass 2: qp, denom, att
    for (int c = 0; c < 16; c++) {
        int n0 = c * 32;
        for (int idx = tid; idx < 2048; idx += 512) {
            int n = idx >> 6, d = idx & 63;
            int gr = b * N_ + n0 + n;
            ks[idx] = Q[gr * 256 + coff + d];
        }
        __syncthreads();
        phi_chunk(ks, projT, kp, tid);
        __syncthreads();
        if (tid < 32) {
            int n = tid;
            float s = 0.0f;
            const float* kpn = &kp[n * MP_];
#pragma unroll 8
            for (int m = 0; m < MP_; m++) s += kpn[m] * ksum[m];
            den[n] = 1.0f / s;
        }
        __syncthreads();
        {
            int n = tid >> 4;
            int d0 = (tid & 15) << 2;
            ull a01 = 0ull, a23 = 0ull;
            const float* kpn = &kp[n * MP_];
#pragma unroll 8
            for (int m = 0; m < MP_; m++) {
                float qv = kpn[m];
                ull q2 = f2pack(qv, qv);
                const ull* cp = reinterpret_cast<const ull*>(&ctx[m * 64 + d0]);
                a01 = ffma2(q2, cp[0], a01);
                a23 = ffma2(q2, cp[1], a23);
            }
            float f0, f1, f2v, f3v;
            f2unpack(a01, f0, f1);
            f2unpack(a23, f2v, f3v);
            float dn = den[n];
            int gr = b * N_ + n0 + n;
            *reinterpret_cast<float4*>(&Att[gr * 256 + coff + d0]) =
                make_float4(f0 * dn, f1 * dn, f2v * dn, f3v * dn);
        }
        __syncthreads();
    }
}

// ---------------- final mean pool ----------------
__global__ void pool_kernel(float* __restrict__ out) {
    int b = blockIdx.x;
    int cix = threadIdx.x;
    float s = 0.0f;
    for (int n = 0; n < N_; n++) s += g_atoms[(b * N_ + n) * C_ + cix];
    out[b * C_ + cix] = s * (1.0f / (float)N_);
}

// ---------------- host launcher ----------------
extern "C" void kernel_launch(void* const* d_in, const int* in_sizes, int n_in,
                              void* d_out, int out_size) {
    const float* x      = (const float*)d_in[0];
    const float* eattr  = (const float*)d_in[1];
    const int*   eidx   = (const int*)d_in[2];
    const float* node_w = (const float*)d_in[4];
    const float* node_b = (const float*)d_in[5];
    const float* edge_w = (const float*)d_in[6];
    const float* edge_b = (const float*)d_in[7];
    const float* gw1    = (const float*)d_in[8];
    const float* gb1    = (const float*)d_in[9];
    const float* gw2    = (const float*)d_in[10];
    const float* gb2    = (const float*)d_in[11];
    const float* qw     = (const float*)d_in[12];
    const float* kw     = (const float*)d_in[13];
    const float* vw     = (const float*)d_in[14];
    const float* ow     = (const float*)d_in[15];
    const float* ob     = (const float*)d_in[16];
    const float* proj   = (const float*)d_in[17];
    const float* n1g    = (const float*)d_in[18];
    const float* n1b    = (const float*)d_in[19];
    const float* n2g    = (const float*)d_in[20];
    const float* n2b    = (const float*)d_in[21];
    const float* n3g    = (const float*)d_in[22];
    const float* n3b    = (const float*)d_in[23];
    const float* mw1    = (const float*)d_in[24];
    const float* mb1    = (const float*)d_in[25];
    const float* mw2    = (const float*)d_in[26];
    const float* mb2    = (const float*)d_in[27];

    const int* src = eidx;
    const int* dst = eidx + E_;

    float *p_atoms, *p_h0, *p_t1, *p_hloc, *p_q, *p_k, *p_v, *p_att, *p_out;
    cudaGetSymbolAddress((void**)&p_atoms, g_atoms);
    cudaGetSymbolAddress((void**)&p_h0,    g_h0);
    cudaGetSymbolAddress((void**)&p_t1,    g_t1);
    cudaGetSymbolAddress((void**)&p_hloc,  g_hloc);
    cudaGetSymbolAddress((void**)&p_q,     g_q);
    cudaGetSymbolAddress((void**)&p_k,     g_k);
    cudaGetSymbolAddress((void**)&p_v,     g_v);
    cudaGetSymbolAddress((void**)&p_att,   g_att);
    cudaGetSymbolAddress((void**)&p_out,   g_out);

    static_assert(PERF_SMEM_FLOATS * 4 < 227 * 1024, "smem");
    cudaFuncSetAttribute(performer_kernel,
                         cudaFuncAttributeMaxDynamicSharedMemorySize,
                         PERF_SMEM_FLOATS * 4);

    // node embedding + CSR build (once)
    node_embed_kernel<<<TN, 256>>>(x, node_w, node_b);
    zero_deg_kernel<<<(TN + 255) / 256, 256>>>();
    count_deg_kernel<<<E_ / 256, 256>>>(dst);
    scan_deg_kernel<<<1, 1024>>>();
    fill_adj_kernel<<<E_ / 256, 256>>>(dst);

    dim3 g1(TN / 64, 1), g2(TN / 64, 2);
    for (int l = 0; l < L_; l++) {
        const float* gw1l = gw1 + l * C_ * C_;
        const float* gw2l = gw2 + l * C_ * C_;
        const float* mw1l = mw1 + l * C_ * 2 * C_;
        const float* mw2l = mw2 + l * 2 * C_ * C_;

        // GINE conv
        gine_kernel<<<TN / 8, 256>>>(src, eattr, edge_w, edge_b);
        gemm_kernel<1><<<g1, 256>>>(p_h0, gw1l, gb1 + l * C_, nullptr, nullptr,
                                    nullptr, nullptr, p_t1, 256, 256);
        gemm_kernel<2><<<g1, 256>>>(p_t1, gw2l, gb2 + l * C_, p_atoms, nullptr,
                                    n1g + l * C_, n1b + l * C_, p_hloc, 256, 256);
        // QKV
        gemm_kernel<0><<<g1, 256>>>(p_atoms, qw + l * C_ * C_, nullptr, nullptr, nullptr,
                                    nullptr, nullptr, p_q, 256, 256);
        gemm_kernel<0><<<g1, 256>>>(p_atoms, kw + l * C_ * C_, nullptr, nullptr, nullptr,
                                    nullptr, nullptr, p_k, 256, 256);
        gemm_kernel<0><<<g1, 256>>>(p_atoms, vw + l * C_ * C_, nullptr, nullptr, nullptr,
                                    nullptr, nullptr, p_v, 256, 256);
        // Performer attention
        performer_kernel<<<B_ * H_, 512, PERF_SMEM_FLOATS * 4>>>(
            p_q, p_k, p_v, proj + l * M_ * DH_, p_att);
        // O-proj + LN + combine (out = LN(att@ow+ob+atoms) + hloc)
        gemm_kernel<3><<<g1, 256>>>(p_att, ow + l * C_ * C_, ob + l * C_, p_atoms, p_hloc,
                                    n2g + l * C_, n2b + l * C_, p_out, 256, 256);
        // FFN
        gemm_kernel<1><<<g2, 256>>>(p_out, mw1l, mb1 + l * 2 * C_, nullptr, nullptr,
                                    nullptr, nullptr, p_t1, 256, 512);
        gemm_kernel<2><<<g1, 256>>>(p_t1, mw2l, mb2 + l * C_, p_out, nullptr,
                                    n3g + l * C_, n3b + l * C_, p_atoms, 512, 256);
    }
    pool_kernel<<<B_, 256>>>((float*)d_out);
}

// round 6
// speedup vs baseline: 1.4910x; 1.4910x over previous
#include <cuda_runtime.h>
#include <math.h>
#include <stdint.h>

#define TN   32768
#define C_   256
#define B_   64
#define N_   512
#define H_   4
#define DH_  64
#define M_   266
#define MP_  272
#define E_   524288
#define L_   5

typedef unsigned long long ull;

// ---------------- scratch ----------------
__device__ float g_atoms[TN * C_];
__device__ float g_h0[TN * C_];
__device__ float g_t1[TN * 2 * C_];
__device__ float g_t2[TN * C_];
__device__ float g_hloc[TN * C_];
__device__ float g_q[TN * C_];
__device__ float g_k[TN * C_];
__device__ float g_v[TN * C_];
__device__ float g_att[TN * C_];
__device__ float g_out[TN * C_];
__device__ float g_wt[L_ * 655360];      // transposed tf32-rounded weights, [n][k]
__device__ int   g_deg[TN];
__device__ int   g_indptr[TN + 1];
__device__ int   g_cursor[TN];
__device__ int   g_eadj[E_];

// ---------------- helpers ----------------
__device__ __forceinline__ ull f2pack(float x, float y) {
    ull r; asm("mov.b64 %0, {%1, %2};" : "=l"(r) : "f"(x), "f"(y)); return r;
}
__device__ __forceinline__ void f2unpack(ull p, float &x, float &y) {
    asm("mov.b64 {%0, %1}, %2;" : "=f"(x), "=f"(y) : "l"(p));
}
__device__ __forceinline__ ull ffma2(ull a, ull b, ull c) {
    ull d; asm("fma.rn.f32x2 %0, %1, %2, %3;" : "=l"(d) : "l"(a), "l"(b), "l"(c)); return d;
}
__device__ __forceinline__ float gelu_exact(float x) {
    return 0.5f * x * (1.0f + erff(x * 0.70710678118654752f));
}
__device__ __forceinline__ uint32_t tf32r(float f) {
    uint32_t r; asm("cvt.rna.tf32.f32 %0, %1;" : "=r"(r) : "f"(f)); return r;
}
__device__ __forceinline__ uint32_t smem_u32(const void* p) {
    uint32_t a;
    asm("{ .reg .u64 t; cvta.to.shared.u64 t, %1; cvt.u32.u64 %0, t; }" : "=r"(a) : "l"(p));
    return a;
}
__device__ __forceinline__ void mma_tf32_16x8x8(float* d, const uint32_t* a, const uint32_t* b) {
    asm volatile(
        "mma.sync.aligned.m16n8k8.row.col.f32.tf32.tf32.f32 "
        "{%0,%1,%2,%3}, {%4,%5,%6,%7}, {%8,%9}, {%0,%1,%2,%3};"
        : "+f"(d[0]), "+f"(d[1]), "+f"(d[2]), "+f"(d[3])
        : "r"(a[0]), "r"(a[1]), "r"(a[2]), "r"(a[3]), "r"(b[0]), "r"(b[1]));
}
__device__ __forceinline__ void cp_async16(uint32_t saddr, const void* gptr) {
    asm volatile("cp.async.cg.shared.global [%0], [%1], 16;" :: "r"(saddr), "l"(gptr));
}
#define CP_COMMIT() asm volatile("cp.async.commit_group;" ::: "memory")
#define CP_WAIT0()  asm volatile("cp.async.wait_group 0;" ::: "memory")

// ---------------- weight transpose (once): WT[n*K+k] = tf32(W[k*N+n]) ----------------
struct WPtrs { const float* p[8]; };

__global__ void transpose_kernel(WPtrs wp) {
    int z = blockIdx.z;
    int t = z & 7, l = z >> 3;
    int K = (t == 7) ? 512 : 256;
    int N = (t == 6) ? 512 : 256;
    int n0 = blockIdx.x * 32, k0 = blockIdx.y * 32;
    if (n0 >= N || k0 >= K) return;
    const float* src = wp.p[t] + ((t >= 6) ? l * 131072 : l * 65536);
    int doff = (t < 6) ? t * 65536 : (t == 6 ? 393216 : 524288);
    float* dst = g_wt + l * 655360 + doff;
    __shared__ float s[32][33];
    int tx = threadIdx.x, ty = threadIdx.y;
#pragma unroll
    for (int i = 0; i < 4; i++)
        s[ty + 8 * i][tx] = src[(k0 + ty + 8 * i) * N + n0 + tx];
    __syncthreads();
#pragma unroll
    for (int i = 0; i < 4; i++)
        dst[(n0 + ty + 8 * i) * K + k0 + tx] =
            __uint_as_float(tf32r(s[tx][ty + 8 * i]));
}

// ---------------- mma.sync tf32 GEMM ----------------
// Out[64,256-tile] = A[64,K] @ WT^T (+bias) (+res, MODE0) / gelu (MODE1)
// smem layout (floats): As[2][64*36] | Bs[2][256*36]
#define GEMM_SMEM_FLOATS (2 * 2304 + 2 * 9216)

template <int MODE>
__global__ void __launch_bounds__(256, 2) mma_gemm(const float* __restrict__ A,
                                                   const float* __restrict__ WT,
                                                   const float* __restrict__ bias,
                                                   const float* __restrict__ res,
                                                   float* __restrict__ Out,
                                                   int K, int Ntot) {
    extern __shared__ float smf[];
    const int tid = threadIdx.x;
    const int lane = tid & 31, wid = tid >> 5;
    const int g = lane >> 2, t = lane & 3;
    const int wm = (wid & 1) * 32;        // 2 warps over M
    const int wn = (wid >> 1) * 64;       // 4 warps over N
    const int rowbase = blockIdx.x * 64;
    const int colbase = blockIdx.y * 256;

    const int am = tid >> 3;              // A load: row (tid<512/... idx below)
    const int nk = K >> 5;

    float acc[2][8][4];
#pragma unroll
    for (int mt = 0; mt < 2; mt++)
#pragma unroll
        for (int nt = 0; nt < 8; nt++)
#pragma unroll
            for (int j = 0; j < 4; j++) acc[mt][nt][j] = 0.0f;

    float4 areg[2];
    uint32_t sb = smem_u32(smf);

    // ---- prologue: stage 0 ----
#pragma unroll
    for (int i = 0; i < 2; i++) {
        int idx = tid + i * 256;
        int m = idx >> 3, kq = idx & 7;
        areg[i] = *reinterpret_cast<const float4*>(&A[(size_t)(rowbase + m) * K + kq * 4]);
    }
#pragma unroll
    for (int i = 0; i < 8; i++) {
        int idx = tid + i * 256;
        int n = idx >> 3, kq = idx & 7;
        cp_async16(sb + (4608 + n * 36 + kq * 4) * 4,
                   &WT[(size_t)(colbase + n) * K + kq * 4]);
    }
    CP_COMMIT();
#pragma unroll
    for (int i = 0; i < 2; i++) {
        int idx = tid + i * 256;
        int m = idx >> 3, kq = idx & 7;
        uint32_t addr = sb + (m * 36 + kq * 4) * 4;
        asm volatile("st.shared.v4.b32 [%0], {%1,%2,%3,%4};" :: "r"(addr),
                     "r"(tf32r(areg[i].x)), "r"(tf32r(areg[i].y)),
                     "r"(tf32r(areg[i].z)), "r"(tf32r(areg[i].w)));
    }
    CP_WAIT0();
    __syncthreads();

    for (int kb = 0; kb < nk; kb++) {
        const int cur = kb & 1;
        const bool nxt = (kb + 1 < nk);
        if (nxt) {
            int k0g = (kb + 1) * 32;
#pragma unroll
            for (int i = 0; i < 2; i++) {
                int idx = tid + i * 256;
                int m = idx >> 3, kq = idx & 7;
                areg[i] = *reinterpret_cast<const float4*>(
                    &A[(size_t)(rowbase + m) * K + k0g + kq * 4]);
            }
            int sB = cur ^ 1;
#pragma unroll
            for (int i = 0; i < 8; i++) {
                int idx = tid + i * 256;
                int n = idx >> 3, kq = idx & 7;
                cp_async16(sb + (4608 + sB * 9216 + n * 36 + kq * 4) * 4,
                           &WT[(size_t)(colbase + n) * K + k0g + kq * 4]);
            }
            CP_COMMIT();
        }
        // ---- compute current stage ----
        {
            const float* As = smf + cur * 2304;
            const float* Bs = smf + 4608 + cur * 9216;
#pragma unroll
            for (int ks = 0; ks < 4; ks++) {
                const int k0 = ks * 8;
                uint32_t af[2][4], bf[8][2];
#pragma unroll
                for (int mt = 0; mt < 2; mt++) {
                    int r0 = wm + mt * 16 + g;
                    af[mt][0] = __float_as_uint(As[r0 * 36 + k0 + t]);
                    af[mt][1] = __float_as_uint(As[(r0 + 8) * 36 + k0 + t]);
                    af[mt][2] = __float_as_uint(As[r0 * 36 + k0 + t + 4]);
                    af[mt][3] = __float_as_uint(As[(r0 + 8) * 36 + k0 + t + 4]);
                }
#pragma unroll
                for (int nt = 0; nt < 8; nt++) {
                    int n0 = wn + nt * 8 + g;
                    bf[nt][0] = __float_as_uint(Bs[n0 * 36 + k0 + t]);
                    bf[nt][1] = __float_as_uint(Bs[n0 * 36 + k0 + t + 4]);
                }
#pragma unroll
                for (int mt = 0; mt < 2; mt++)
#pragma unroll
                    for (int nt = 0; nt < 8; nt++)
                        mma_tf32_16x8x8(acc[mt][nt], af[mt], bf[nt]);
            }
        }
        if (nxt) {
            int sB = cur ^ 1;
#pragma unroll
            for (int i = 0; i < 2; i++) {
                int idx = tid + i * 256;
                int m = idx >> 3, kq = idx & 7;
                uint32_t addr = sb + (sB * 2304 + m * 36 + kq * 4) * 4;
                asm volatile("st.shared.v4.b32 [%0], {%1,%2,%3,%4};" :: "r"(addr),
                             "r"(tf32r(areg[i].x)), "r"(tf32r(areg[i].y)),
                             "r"(tf32r(areg[i].z)), "r"(tf32r(areg[i].w)));
            }
            CP_WAIT0();
            __syncthreads();
        }
    }

    // ---- epilogue ----
#pragma unroll
    for (int mt = 0; mt < 2; mt++) {
        int r0 = rowbase + wm + mt * 16 + g;
#pragma unroll
        for (int nt = 0; nt < 8; nt++) {
            int col = colbase + wn + nt * 8 + 2 * t;
            float b0 = 0.0f, b1 = 0.0f;
            if (bias) { b0 = bias[col]; b1 = bias[col + 1]; }
            float v0 = acc[mt][nt][0] + b0, v1 = acc[mt][nt][1] + b1;
            float v2 = acc[mt][nt][2] + b0, v3 = acc[mt][nt][3] + b1;
            if (MODE == 0) {
                if (res) {
                    float2 r01 = *reinterpret_cast<const float2*>(&res[(size_t)r0 * 256 + col]);
                    float2 r23 = *reinterpret_cast<const float2*>(&res[(size_t)(r0 + 8) * 256 + col]);
                    v0 += r01.x; v1 += r01.y; v2 += r23.x; v3 += r23.y;
                }
            } else {
                v0 = gelu_exact(v0); v1 = gelu_exact(v1);
                v2 = gelu_exact(v2); v3 = gelu_exact(v3);
            }
            *reinterpret_cast<float2*>(&Out[(size_t)r0 * Ntot + col]) = make_float2(v0, v1);
            *reinterpret_cast<float2*>(&Out[(size_t)(r0 + 8) * Ntot + col]) = make_float2(v2, v3);
        }
    }
}

// ---------------- LayerNorm: out = LN(a)*g+b (+add2) ; row = 256 ----------------
__global__ void __launch_bounds__(256) ln_kernel(const float* __restrict__ a,
                                                 const float* __restrict__ lng,
                                                 const float* __restrict__ lnb,
                                                 const float* __restrict__ add2,
                                                 float* __restrict__ out) {
    int row = blockIdx.x * 8 + (threadIdx.x >> 5);
    int lane = threadIdx.x & 31;
    const float* ar = a + (size_t)row * 256 + lane * 8;
    float4 v0 = *reinterpret_cast<const float4*>(ar);
    float4 v1 = *reinterpret_cast<const float4*>(ar + 4);
    float s1 = v0.x + v0.y + v0.z + v0.w + v1.x + v1.y + v1.z + v1.w;
    float s2 = v0.x * v0.x + v0.y * v0.y + v0.z * v0.z + v0.w * v0.w
             + v1.x * v1.x + v1.y * v1.y + v1.z * v1.z + v1.w * v1.w;
#pragma unroll
    for (int off = 16; off > 0; off >>= 1) {
        s1 += __shfl_xor_sync(0xffffffffu, s1, off);
        s2 += __shfl_xor_sync(0xffffffffu, s2, off);
    }
    float mean = s1 * (1.0f / 256.0f);
    float var = s2 * (1.0f / 256.0f) - mean * mean;
    float rstd = rsqrtf(var + 1e-5f);
    float4 g0 = *reinterpret_cast<const float4*>(&lng[lane * 8]);
    float4 g1 = *reinterpret_cast<const float4*>(&lng[lane * 8 + 4]);
    float4 b0 = *reinterpret_cast<const float4*>(&lnb[lane * 8]);
    float4 b1 = *reinterpret_cast<const float4*>(&lnb[lane * 8 + 4]);
    float4 o0, o1;
    o0.x = (v0.x - mean) * rstd * g0.x + b0.x;
    o0.y = (v0.y - mean) * rstd * g0.y + b0.y;
    o0.z = (v0.z - mean) * rstd * g0.z + b0.z;
    o0.w = (v0.w - mean) * rstd * g0.w + b0.w;
    o1.x = (v1.x - mean) * rstd * g1.x + b1.x;
    o1.y = (v1.y - mean) * rstd * g1.y + b1.y;
    o1.z = (v1.z - mean) * rstd * g1.z + b1.z;
    o1.w = (v1.w - mean) * rstd * g1.w + b1.w;
    if (add2) {
        const float* a2 = add2 + (size_t)row * 256 + lane * 8;
        float4 x0 = *reinterpret_cast<const float4*>(a2);
        float4 x1 = *reinterpret_cast<const float4*>(a2 + 4);
        o0.x += x0.x; o0.y += x0.y; o0.z += x0.z; o0.w += x0.w;
        o1.x += x1.x; o1.y += x1.y; o1.z += x1.z; o1.w += x1.w;
    }
    float* orow = out + (size_t)row * 256 + lane * 8;
    *reinterpret_cast<float4*>(orow) = o0;
    *reinterpret_cast<float4*>(orow + 4) = o1;
}

// ---------------- node embedding ----------------
__global__ void node_embed_kernel(const float* __restrict__ x,
                                  const float* __restrict__ w,
                                  const float* __restrict__ b) {
    __shared__ float lx[11];
    int row = blockIdx.x;
    int t = threadIdx.x;
    if (t < 11) lx[t] = log1pf(x[row * 11 + t]);
    __syncthreads();
    float s = b[t];
#pragma unroll
    for (int j = 0; j < 11; j++) s += lx[j] * w[j * C_ + t];
    g_atoms[row * C_ + t] = s;
}

// ---------------- CSR build ----------------
__global__ void count_deg_kernel(const int* __restrict__ dst) {
    int e = blockIdx.x * blockDim.x + threadIdx.x;
    if (e < E_) atomicAdd(&g_deg[dst[e]], 1);
}
__global__ void scan_deg_kernel() {
    __shared__ int sh[1024];
    __shared__ int carry;
    int t = threadIdx.x;
    if (t == 0) carry = 0;
    __syncthreads();
    for (int base = 0; base < TN; base += 1024) {
        int v = g_deg[base + t];
        sh[t] = v;
        __syncthreads();
        for (int off = 1; off < 1024; off <<= 1) {
            int add = (t >= off) ? sh[t - off] : 0;
            __syncthreads();
            sh[t] += add;
            __syncthreads();
        }
        int ip = carry + sh[t] - v;
        g_indptr[base + t] = ip;
        g_cursor[base + t] = ip;
        __syncthreads();
        if (t == 0) carry += sh[1023];
        __syncthreads();
    }
    if (t == 0) g_indptr[TN] = carry;
}
__global__ void fill_adj_kernel(const int* __restrict__ dst) {
    int e = blockIdx.x * blockDim.x + threadIdx.x;
    if (e < E_) {
        int p = atomicAdd(&g_cursor[dst[e]], 1);
        g_eadj[p] = e;
    }
}

// ---------------- GINE aggregation ----------------
__global__ void __launch_bounds__(256) gine_kernel(const int* __restrict__ src,
                                                   const float* __restrict__ eattr,
                                                   const float* __restrict__ ew,
                                                   const float* __restrict__ eb) {
    __shared__ float sew[4][C_];
    __shared__ float seb[C_];
    int tid = threadIdx.x;
    for (int i = tid; i < 4 * C_; i += 256) sew[i >> 8][i & 255] = ew[i];
    seb[tid] = eb[tid];
    __syncthreads();
    int warp = tid >> 5, lane = tid & 31;
    int v = blockIdx.x * 8 + warp;
    float acc[8];
#pragma unroll
    for (int k = 0; k < 8; k++) acc[k] = g_atoms[v * C_ + lane + 32 * k];
    int p0 = g_indptr[v], p1 = g_indptr[v + 1];
    for (int p = p0; p < p1; p++) {
        int e = g_eadj[p];
        int s = src[e];
        float4 ea4 = *reinterpret_cast<const float4*>(&eattr[e * 4]);
        const float* arow = &g_atoms[s * C_];
#pragma unroll
        for (int k = 0; k < 8; k++) {
            int c = lane + 32 * k;
            float eac = seb[c] + ea4.x * sew[0][c] + ea4.y * sew[1][c]
                               + ea4.z * sew[2][c] + ea4.w * sew[3][c];
            acc[k] += fmaxf(arow[c] + eac, 0.0f);
        }
    }
#pragma unroll
    for (int k = 0; k < 8; k++) g_h0[v * C_ + lane + 32 * k] = acc[k];
}

// ---------------- Performer attention: one CTA per (b,h) ----------------
#define PERF_SMEM_FLOATS (64 * MP_ + MP_ * 64 + 32 * MP_ + 2048 + 2048 + MP_ + 32)

__device__ __forceinline__ void phi_chunk(const float* __restrict__ ks,
                                          const float* __restrict__ projT,
                                          float* __restrict__ kp, int tid) {
    for (int t = tid; t < 32 * 68; t += 512) {
        int n = t / 68;
        int m0 = (t - n * 68) * 4;
        ull a01 = 0ull, a23 = 0ull;
        const float* krow = &ks[n * 64];
        const float* pT = &projT[m0];
#pragma unroll 8
        for (int d = 0; d < 64; d++) {
            float a = krow[d];
            ull a2 = f2pack(a, a);
            const ull* pp = reinterpret_cast<const ull*>(pT + d * MP_);
            a01 = ffma2(a2, pp[0], a01);
            a23 = ffma2(a2, pp[1], a23);
        }
        float r0, r1, r2, r3;
        f2unpack(a01, r0, r1);
        f2unpack(a23, r2, r3);
        float* kpr = &kp[n * MP_ + m0];
        kpr[0] = (m0 + 0 < M_) ? fmaxf(r0, 0.0f) + 1e-3f : 0.0f;
        kpr[1] = (m0 + 1 < M_) ? fmaxf(r1, 0.0f) + 1e-3f : 0.0f;
        kpr[2] = (m0 + 2 < M_) ? fmaxf(r2, 0.0f) + 1e-3f : 0.0f;
        kpr[3] = (m0 + 3 < M_) ? fmaxf(r3, 0.0f) + 1e-3f : 0.0f;
    }
}

__global__ void __launch_bounds__(512, 1) performer_kernel(const float* __restrict__ Q,
                                                           const float* __restrict__ Kb,
                                                           const float* __restrict__ V,
                                                           const float* __restrict__ proj_l,
                                                           float* __restrict__ Att) {
    extern __shared__ float sm[];
    float* projT = sm;
    float* ctx = projT + 64 * MP_;
    float* kp = ctx + MP_ * 64;
    float* ks = kp + 32 * MP_;
    float* vs = ks + 2048;
    float* ksum = vs + 2048;
    float* den = ksum + MP_;

    const int tid = threadIdx.x;
    const int bh = blockIdx.x;
    const int b = bh >> 2;
    const int h = bh & 3;
    const int coff = h * 64;

    for (int idx = tid; idx < M_ * 64; idx += 512) {
        int m = idx >> 6, d = idx & 63;
        projT[d * MP_ + m] = proj_l[idx];
    }
    for (int idx = tid; idx < 64 * (MP_ - M_); idx += 512) {
        int d = idx / (MP_ - M_);
        int m = M_ + idx % (MP_ - M_);
        projT[d * MP_ + m] = 0.0f;
    }
    for (int idx = tid; idx < MP_ * 64; idx += 512) ctx[idx] = 0.0f;
    if (tid < MP_) ksum[tid] = 0.0f;
    __syncthreads();

    for (int c = 0; c < 16; c++) {
        int n0 = c * 32;
        for (int idx = tid; idx < 2048; idx += 512) {
            int n = idx >> 6, d = idx & 63;
            int gr = b * N_ + n0 + n;
            ks[idx] = Kb[gr * 256 + coff + d];
            vs[idx] = V[gr * 256 + coff + d];
        }
        __syncthreads();
        phi_chunk(ks, projT, kp, tid);
        __syncthreads();
        for (int m = tid; m < MP_; m += 512) {
            float s = 0.0f;
#pragma unroll 8
            for (int n = 0; n < 32; n++) s += kp[n * MP_ + m];
            ksum[m] += s;
        }
        for (int t = tid; t < 68 * 16; t += 512) {
            int m0 = (t >> 4) << 2;
            int d0 = (t & 15) << 2;
            ull a[4][2];
#pragma unroll
            for (int q = 0; q < 4; q++) { a[q][0] = 0ull; a[q][1] = 0ull; }
#pragma unroll 4
            for (int n = 0; n < 32; n++) {
                float4 kv = *reinterpret_cast<const float4*>(&kp[n * MP_ + m0]);
                const ull* vvp = reinterpret_cast<const ull*>(&vs[n * 64 + d0]);
                ull v01 = vvp[0], v23 = vvp[1];
                a[0][0] = ffma2(f2pack(kv.x, kv.x), v01, a[0][0]);
                a[0][1] = ffma2(f2pack(kv.x, kv.x), v23, a[0][1]);
                a[1][0] = ffma2(f2pack(kv.y, kv.y), v01, a[1][0]);
                a[1][1] = ffma2(f2pack(kv.y, kv.y), v23, a[1][1]);
                a[2][0] = ffma2(f2pack(kv.z, kv.z), v01, a[2][0]);
                a[2][1] = ffma2(f2pack(kv.z, kv.z), v23, a[2][1]);
                a[3][0] = ffma2(f2pack(kv.w, kv.w), v01, a[3][0]);
                a[3][1] = ffma2(f2pack(kv.w, kv.w), v23, a[3][1]);
            }
#pragma unroll
            for (int q = 0; q < 4; q++) {
                float f0, f1, f2v, f3v;
                f2unpack(a[q][0], f0, f1);
                f2unpack(a[q][1], f2v, f3v);
                float* cp = &ctx[(m0 + q) * 64 + d0];
                cp[0] += f0; cp[1] += f1; cp[2] += f2v; cp[3] += f3v;
            }
        }
        __syncthreads();
    }

    for (int c = 0; c < 16; c++) {
        int n0 = c * 32;
        for (int idx = tid; idx < 2048; idx += 512) {
            int n = idx >> 6, d = idx & 63;
            int gr = b * N_ + n0 + n;
            ks[idx] = Q[gr * 256 + coff + d];
        }
        __syncthreads();
        phi_chunk(ks, projT, kp, tid);
        __syncthreads();
        if (tid < 32) {
            int n = tid;
            float s = 0.0f;
            const float* kpn = &kp[n * MP_];
#pragma unroll 8
            for (int m = 0; m < MP_; m++) s += kpn[m] * ksum[m];
            den[n] = 1.0f / s;
        }
        __syncthreads();
        {
            int n = tid >> 4;
            int d0 = (tid & 15) << 2;
            ull a01 = 0ull, a23 = 0ull;
            const float* kpn = &kp[n * MP_];
#pragma unroll 8
            for (int m = 0; m < MP_; m++) {
                float qv = kpn[m];
                ull q2 = f2pack(qv, qv);
                const ull* cp = reinterpret_cast<const ull*>(&ctx[m * 64 + d0]);
                a01 = ffma2(q2, cp[0], a01);
                a23 = ffma2(q2, cp[1], a23);
            }
            float f0, f1, f2v, f3v;
            f2unpack(a01, f0, f1);
            f2unpack(a23, f2v, f3v);
            float dn = den[n];
            int gr = b * N_ + n0 + n;
            *reinterpret_cast<float4*>(&Att[gr * 256 + coff + d0]) =
                make_float4(f0 * dn, f1 * dn, f2v * dn, f3v * dn);
        }
        __syncthreads();
    }
}

// ---------------- final mean pool ----------------
__global__ void pool_kernel(float* __restrict__ out) {
    int b = blockIdx.x;
    int cix = threadIdx.x;
    float s = 0.0f;
    for (int n = 0; n < N_; n++) s += g_atoms[(b * N_ + n) * C_ + cix];
    out[b * C_ + cix] = s * (1.0f / (float)N_);
}

// ---------------- host launcher ----------------
extern "C" void kernel_launch(void* const* d_in, const int* in_sizes, int n_in,
                              void* d_out, int out_size) {
    const float* x      = (const float*)d_in[0];
    const float* eattr  = (const float*)d_in[1];
    const int*   eidx   = (const int*)d_in[2];
    const float* node_w = (const float*)d_in[4];
    const float* node_b = (const float*)d_in[5];
    const float* edge_w = (const float*)d_in[6];
    const float* edge_b = (const float*)d_in[7];
    const float* gw1    = (const float*)d_in[8];
    const float* gb1    = (const float*)d_in[9];
    const float* gw2    = (const float*)d_in[10];
    const float* gb2    = (const float*)d_in[11];
    const float* qw     = (const float*)d_in[12];
    const float* kw     = (const float*)d_in[13];
    const float* vw     = (const float*)d_in[14];
    const float* ow     = (const float*)d_in[15];
    const float* ob     = (const float*)d_in[16];
    const float* proj   = (const float*)d_in[17];
    const float* n1g    = (const float*)d_in[18];
    const float* n1b    = (const float*)d_in[19];
    const float* n2g    = (const float*)d_in[20];
    const float* n2b    = (const float*)d_in[21];
    const float* n3g    = (const float*)d_in[22];
    const float* n3b    = (const float*)d_in[23];
    const float* mw1    = (const float*)d_in[24];
    const float* mb1    = (const float*)d_in[25];
    const float* mw2    = (const float*)d_in[26];
    const float* mb2    = (const float*)d_in[27];

    const int* src = eidx;
    const int* dst = eidx + E_;

    float *p_atoms, *p_h0, *p_t1, *p_t2, *p_hloc, *p_q, *p_k, *p_v, *p_att, *p_out, *p_wt;
    int *p_deg;
    cudaGetSymbolAddress((void**)&p_atoms, g_atoms);
    cudaGetSymbolAddress((void**)&p_h0,    g_h0);
    cudaGetSymbolAddress((void**)&p_t1,    g_t1);
    cudaGetSymbolAddress((void**)&p_t2,    g_t2);
    cudaGetSymbolAddress((void**)&p_hloc,  g_hloc);
    cudaGetSymbolAddress((void**)&p_q,     g_q);
    cudaGetSymbolAddress((void**)&p_k,     g_k);
    cudaGetSymbolAddress((void**)&p_v,     g_v);
    cudaGetSymbolAddress((void**)&p_att,   g_att);
    cudaGetSymbolAddress((void**)&p_out,   g_out);
    cudaGetSymbolAddress((void**)&p_wt,    g_wt);
    cudaGetSymbolAddress((void**)&p_deg,   g_deg);

    cudaFuncSetAttribute(performer_kernel, cudaFuncAttributeMaxDynamicSharedMemorySize,
                         PERF_SMEM_FLOATS * 4);
    cudaFuncSetAttribute(mma_gemm<0>, cudaFuncAttributeMaxDynamicSharedMemorySize,
                         GEMM_SMEM_FLOATS * 4);
    cudaFuncSetAttribute(mma_gemm<1>, cudaFuncAttributeMaxDynamicSharedMemorySize,
                         GEMM_SMEM_FLOATS * 4);

    // weight transpose (+tf32 rounding), once
    WPtrs wp;
    wp.p[0] = gw1; wp.p[1] = gw2; wp.p[2] = qw; wp.p[3] = kw;
    wp.p[4] = vw;  wp.p[5] = ow;  wp.p[6] = mw1; wp.p[7] = mw2;
    transpose_kernel<<<dim3(16, 16, 40), dim3(32, 8)>>>(wp);

    // CSR build + node embedding
    cudaMemsetAsync(p_deg, 0, TN * sizeof(int));
    count_deg_kernel<<<E_ / 256, 256>>>(dst);
    scan_deg_kernel<<<1, 1024>>>();
    fill_adj_kernel<<<E_ / 256, 256>>>(dst);
    node_embed_kernel<<<TN, 256>>>(x, node_w, node_b);

    const int SMG = GEMM_SMEM_FLOATS * 4;
    dim3 g1(TN / 64, 1), g2(TN / 64, 2);
    for (int l = 0; l < L_; l++) {
        const float* wt_l = p_wt + l * 655360;
        // QKV
        mma_gemm<0><<<g1, 256, SMG>>>(p_atoms, wt_l + 131072, nullptr, nullptr, p_q, 256, 256);
        mma_gemm<0><<<g1, 256, SMG>>>(p_atoms, wt_l + 196608, nullptr, nullptr, p_k, 256, 256);
        mma_gemm<0><<<g1, 256, SMG>>>(p_atoms, wt_l + 262144, nullptr, nullptr, p_v, 256, 256);
        // GINE conv
        gine_kernel<<<TN / 8, 256>>>(src, eattr, edge_w, edge_b);
        mma_gemm<1><<<g1, 256, SMG>>>(p_h0, wt_l + 0, gb1 + l * C_, nullptr, p_t1, 256, 256);
        mma_gemm<0><<<g1, 256, SMG>>>(p_t1, wt_l + 65536, gb2 + l * C_, p_atoms, p_t2, 256, 256);
        ln_kernel<<<TN / 8, 256>>>(p_t2, n1g + l * C_, n1b + l * C_, nullptr, p_hloc);
        // Performer attention
        performer_kernel<<<B_ * H_, 512, PERF_SMEM_FLOATS * 4>>>(
            p_q, p_k, p_v, proj + l * M_ * DH_, p_att);
        // O-proj + LN + combine
        mma_gemm<0><<<g1, 256, SMG>>>(p_att, wt_l + 327680, ob + l * C_, p_atoms, p_t2, 256, 256);
        ln_kernel<<<TN / 8, 256>>>(p_t2, n2g + l * C_, n2b + l * C_, p_hloc, p_out);
        // FFN
        mma_gemm<1><<<g2, 256, SMG>>>(p_out, wt_l + 393216, mb1 + l * 2 * C_, nullptr, p_t1, 256, 512);
        mma_gemm<0><<<g1, 256, SMG>>>(p_t1, wt_l + 524288, mb2 + l * C_, p_out, p_t2, 512, 256);
        ln_kernel<<<TN / 8, 256>>>(p_t2, n3g + l * C_, n3b + l * C_, nullptr, p_atoms);
    }
    pool_kernel<<<B_, 256>>>((float*)d_out);
}

// round 7
// speedup vs baseline: 1.5810x; 1.0604x over previous
#include <cuda_runtime.h>
#include <cuda_fp16.h>
#include <math.h>
#include <stdint.h>

#define TN   32768
#define C_   256
#define B_   64
#define N_   512
#define H_   4
#define DH_  64
#define M_   266
#define MP_  272
#define E_   524288
#define L_   5

typedef unsigned long long ull;

// ---------------- scratch ----------------
__device__ float g_atoms[TN * C_];
__device__ float g_h0[TN * C_];
__device__ float g_t1[TN * 2 * C_];
__device__ float g_t2[TN * C_];
__device__ float g_hloc[TN * C_];
__device__ float g_qkv[TN * 3 * C_];
__device__ float g_att[TN * C_];
__device__ float g_out[TN * C_];
__device__ __half g_wt[L_ * 655360];     // transposed fp16 weights, [n][k] K-major
__device__ int   g_deg[TN];
__device__ int   g_indptr[TN + 1];
__device__ int   g_cursor[TN];
__device__ int   g_eadj[E_];

// ---------------- helpers ----------------
__device__ __forceinline__ ull f2pack(float x, float y) {
    ull r; asm("mov.b64 %0, {%1, %2};" : "=l"(r) : "f"(x), "f"(y)); return r;
}
__device__ __forceinline__ void f2unpack(ull p, float &x, float &y) {
    asm("mov.b64 {%0, %1}, %2;" : "=f"(x), "=f"(y) : "l"(p));
}
__device__ __forceinline__ ull ffma2(ull a, ull b, ull c) {
    ull d; asm("fma.rn.f32x2 %0, %1, %2, %3;" : "=l"(d) : "l"(a), "l"(b), "l"(c)); return d;
}
__device__ __forceinline__ float gelu_exact(float x) {
    return 0.5f * x * (1.0f + erff(x * 0.70710678118654752f));
}
__device__ __forceinline__ uint32_t f2h2(float a, float b) {
    __half2 h = __floats2half2_rn(a, b);
    return *reinterpret_cast<uint32_t*>(&h);
}
__device__ __forceinline__ uint32_t smem_u32(const void* p) {
    uint32_t a;
    asm("{ .reg .u64 t; cvta.to.shared.u64 t, %1; cvt.u32.u64 %0, t; }" : "=r"(a) : "l"(p));
    return a;
}
__device__ __forceinline__ void mma_f16_16x8x16(float* d, const uint32_t* a, const uint32_t* b) {
    asm volatile(
        "mma.sync.aligned.m16n8k16.row.col.f32.f16.f16.f32 "
        "{%0,%1,%2,%3}, {%4,%5,%6,%7}, {%8,%9}, {%0,%1,%2,%3};"
        : "+f"(d[0]), "+f"(d[1]), "+f"(d[2]), "+f"(d[3])
        : "r"(a[0]), "r"(a[1]), "r"(a[2]), "r"(a[3]), "r"(b[0]), "r"(b[1]));
}
__device__ __forceinline__ void cp_async16(uint32_t saddr, const void* gptr) {
    asm volatile("cp.async.cg.shared.global [%0], [%1], 16;" :: "r"(saddr), "l"(gptr));
}
#define CP_COMMIT() asm volatile("cp.async.commit_group;" ::: "memory")
#define CP_WAIT0()  asm volatile("cp.async.wait_group 0;" ::: "memory")

// ---------------- weight transpose (once): WT[n*K+k] = half(W[k*N+n]) ----------------
struct WPtrs { const float* p[8]; };

__global__ void transpose_kernel(WPtrs wp) {
    int z = blockIdx.z;
    int t = z & 7, l = z >> 3;
    int K = (t == 7) ? 512 : 256;
    int N = (t == 6) ? 512 : 256;
    int n0 = blockIdx.x * 32, k0 = blockIdx.y * 32;
    if (n0 >= N || k0 >= K) return;
    const float* src = wp.p[t] + ((t >= 6) ? l * 131072 : l * 65536);
    int doff = (t < 6) ? t * 65536 : (t == 6 ? 393216 : 524288);
    __half* dst = g_wt + l * 655360 + doff;
    __shared__ float s[32][33];
    int tx = threadIdx.x, ty = threadIdx.y;
#pragma unroll
    for (int i = 0; i < 4; i++)
        s[ty + 8 * i][tx] = src[(k0 + ty + 8 * i) * N + n0 + tx];
    __syncthreads();
#pragma unroll
    for (int i = 0; i < 4; i++)
        dst[(n0 + ty + 8 * i) * K + k0 + tx] = __float2half_rn(s[tx][ty + 8 * i]);
}

// ---------------- fp16 mma GEMM ----------------
// Out[64,256-tile] = A[64,K]@WT^T (+bias) (+res MODE0 / gelu MODE1)
// smem words: As[2][64*36] | Bs[2][256*36]  (row stride 36 words; 8 halves/word-pair)
#define GEMM_SMEM_WORDS (2 * 2304 + 2 * 9216)

template <int MODE>
__global__ void __launch_bounds__(256, 2) mma_gemm(const float* __restrict__ A,
                                                   const __half* __restrict__ WT,
                                                   const float* __restrict__ bias,
                                                   const float* __restrict__ res,
                                                   float* __restrict__ Out,
                                                   int K, int Ntot) {
    extern __shared__ uint32_t smw[];
    const int tid = threadIdx.x;
    const int lane = tid & 31, wid = tid >> 5;
    const int g = lane >> 2, t = lane & 3;
    const int wm = (wid & 1) * 32;
    const int wn = (wid >> 1) * 64;
    const int rowbase = blockIdx.x * 64;
    const int colbase = blockIdx.y * 256;
    const uint32_t sb = smem_u32(smw);

    float acc[2][8][4];
#pragma unroll
    for (int mt = 0; mt < 2; mt++)
#pragma unroll
        for (int nt = 0; nt < 8; nt++)
#pragma unroll
            for (int j = 0; j < 4; j++) acc[mt][nt][j] = 0.0f;

    float4 areg[4];
    const int nk = K >> 6;

    // ---- prologue: stage 0 ----
#pragma unroll
    for (int i = 0; i < 4; i++) {
        int idx = tid + i * 256;
        int m = idx >> 4, q = idx & 15;
        areg[i] = *reinterpret_cast<const float4*>(&A[(size_t)(rowbase + m) * K + q * 4]);
    }
#pragma unroll
    for (int i = 0; i < 8; i++) {
        int idx = tid + i * 256;
        int n = idx >> 3, c = idx & 7;
        cp_async16(sb + (4608 + n * 36 + c * 4) * 4,
                   &WT[(size_t)(colbase + n) * K + c * 8]);
    }
    CP_COMMIT();
#pragma unroll
    for (int i = 0; i < 4; i++) {
        int idx = tid + i * 256;
        int m = idx >> 4, q = idx & 15;
        uint32_t h01 = f2h2(areg[i].x, areg[i].y);
        uint32_t h23 = f2h2(areg[i].z, areg[i].w);
        uint32_t addr = sb + (m * 36 + q * 2) * 4;
        asm volatile("st.shared.v2.b32 [%0], {%1,%2};" :: "r"(addr), "r"(h01), "r"(h23));
    }
    CP_WAIT0();
    __syncthreads();

    for (int kb = 0; kb < nk; kb++) {
        const int cur = kb & 1;
        const bool nxt = (kb + 1 < nk);
        if (nxt) {
            int k0g = (kb + 1) * 64;
#pragma unroll
            for (int i = 0; i < 4; i++) {
                int idx = tid + i * 256;
                int m = idx >> 4, q = idx & 15;
                areg[i] = *reinterpret_cast<const float4*>(
                    &A[(size_t)(rowbase + m) * K + k0g + q * 4]);
            }
            int sB = cur ^ 1;
#pragma unroll
            for (int i = 0; i < 8; i++) {
                int idx = tid + i * 256;
                int n = idx >> 3, c = idx & 7;
                cp_async16(sb + (4608 + sB * 9216 + n * 36 + c * 4) * 4,
                           &WT[(size_t)(colbase + n) * K + k0g + c * 8]);
            }
            CP_COMMIT();
        }
        // ---- compute current stage (4 x k16) ----
        {
            const uint32_t* As = smw + cur * 2304;
            const uint32_t* Bs = smw + 4608 + cur * 9216;
#pragma unroll
            for (int ks = 0; ks < 4; ks++) {
                const int k0 = ks * 8;
                uint32_t af[2][4], bf[8][2];
#pragma unroll
                for (int mt = 0; mt < 2; mt++) {
                    int r0 = wm + mt * 16 + g;
                    af[mt][0] = As[r0 * 36 + k0 + t];
                    af[mt][1] = As[(r0 + 8) * 36 + k0 + t];
                    af[mt][2] = As[r0 * 36 + k0 + t + 4];
                    af[mt][3] = As[(r0 + 8) * 36 + k0 + t + 4];
                }
#pragma unroll
                for (int nt = 0; nt < 8; nt++) {
                    int n0 = wn + nt * 8 + g;
                    bf[nt][0] = Bs[n0 * 36 + k0 + t];
                    bf[nt][1] = Bs[n0 * 36 + k0 + t + 4];
                }
#pragma unroll
                for (int mt = 0; mt < 2; mt++)
#pragma unroll
                    for (int nt = 0; nt < 8; nt++)
                        mma_f16_16x8x16(acc[mt][nt], af[mt], bf[nt]);
            }
        }
        if (nxt) {
            int sB = cur ^ 1;
#pragma unroll
            for (int i = 0; i < 4; i++) {
                int idx = tid + i * 256;
                int m = idx >> 4, q = idx & 15;
                uint32_t h01 = f2h2(areg[i].x, areg[i].y);
                uint32_t h23 = f2h2(areg[i].z, areg[i].w);
                uint32_t addr = sb + (sB * 2304 + m * 36 + q * 2) * 4;
                asm volatile("st.shared.v2.b32 [%0], {%1,%2};" :: "r"(addr), "r"(h01), "r"(h23));
            }
            CP_WAIT0();
            __syncthreads();
        }
    }

    // ---- epilogue ----
#pragma unroll
    for (int mt = 0; mt < 2; mt++) {
        int r0 = rowbase + wm + mt * 16 + g;
#pragma unroll
        for (int nt = 0; nt < 8; nt++) {
            int col = colbase + wn + nt * 8 + 2 * t;
            float b0 = 0.0f, b1 = 0.0f;
            if (bias) { b0 = bias[col]; b1 = bias[col + 1]; }
            float v0 = acc[mt][nt][0] + b0, v1 = acc[mt][nt][1] + b1;
            float v2 = acc[mt][nt][2] + b0, v3 = acc[mt][nt][3] + b1;
            if (MODE == 0) {
                if (res) {
                    float2 r01 = *reinterpret_cast<const float2*>(&res[(size_t)r0 * 256 + col]);
                    float2 r23 = *reinterpret_cast<const float2*>(&res[(size_t)(r0 + 8) * 256 + col]);
                    v0 += r01.x; v1 += r01.y; v2 += r23.x; v3 += r23.y;
                }
            } else {
                v0 = gelu_exact(v0); v1 = gelu_exact(v1);
                v2 = gelu_exact(v2); v3 = gelu_exact(v3);
            }
            *reinterpret_cast<float2*>(&Out[(size_t)r0 * Ntot + col]) = make_float2(v0, v1);
            *reinterpret_cast<float2*>(&Out[(size_t)(r0 + 8) * Ntot + col]) = make_float2(v2, v3);
        }
    }
}

// ---------------- LayerNorm ----------------
__global__ void __launch_bounds__(256) ln_kernel(const float* __restrict__ a,
                                                 const float* __restrict__ lng,
                                                 const float* __restrict__ lnb,
                                                 const float* __restrict__ add2,
                                                 float* __restrict__ out) {
    int row = blockIdx.x * 8 + (threadIdx.x >> 5);
    int lane = threadIdx.x & 31;
    const float* ar = a + (size_t)row * 256 + lane * 8;
    float4 v0 = *reinterpret_cast<const float4*>(ar);
    float4 v1 = *reinterpret_cast<const float4*>(ar + 4);
    float s1 = v0.x + v0.y + v0.z + v0.w + v1.x + v1.y + v1.z + v1.w;
    float s2 = v0.x * v0.x + v0.y * v0.y + v0.z * v0.z + v0.w * v0.w
             + v1.x * v1.x + v1.y * v1.y + v1.z * v1.z + v1.w * v1.w;
#pragma unroll
    for (int off = 16; off > 0; off >>= 1) {
        s1 += __shfl_xor_sync(0xffffffffu, s1, off);
        s2 += __shfl_xor_sync(0xffffffffu, s2, off);
    }
    float mean = s1 * (1.0f / 256.0f);
    float var = s2 * (1.0f / 256.0f) - mean * mean;
    float rstd = rsqrtf(var + 1e-5f);
    float4 g0 = *reinterpret_cast<const float4*>(&lng[lane * 8]);
    float4 g1 = *reinterpret_cast<const float4*>(&lng[lane * 8 + 4]);
    float4 b0 = *reinterpret_cast<const float4*>(&lnb[lane * 8]);
    float4 b1 = *reinterpret_cast<const float4*>(&lnb[lane * 8 + 4]);
    float4 o0, o1;
    o0.x = (v0.x - mean) * rstd * g0.x + b0.x;
    o0.y = (v0.y - mean) * rstd * g0.y + b0.y;
    o0.z = (v0.z - mean) * rstd * g0.z + b0.z;
    o0.w = (v0.w - mean) * rstd * g0.w + b0.w;
    o1.x = (v1.x - mean) * rstd * g1.x + b1.x;
    o1.y = (v1.y - mean) * rstd * g1.y + b1.y;
    o1.z = (v1.z - mean) * rstd * g1.z + b1.z;
    o1.w = (v1.w - mean) * rstd * g1.w + b1.w;
    if (add2) {
        const float* a2 = add2 + (size_t)row * 256 + lane * 8;
        float4 x0 = *reinterpret_cast<const float4*>(a2);
        float4 x1 = *reinterpret_cast<const float4*>(a2 + 4);
        o0.x += x0.x; o0.y += x0.y; o0.z += x0.z; o0.w += x0.w;
        o1.x += x1.x; o1.y += x1.y; o1.z += x1.z; o1.w += x1.w;
    }
    float* orow = out + (size_t)row * 256 + lane * 8;
    *reinterpret_cast<float4*>(orow) = o0;
    *reinterpret_cast<float4*>(orow + 4) = o1;
}

// ---------------- node embedding ----------------
__global__ void node_embed_kernel(const float* __restrict__ x,
                                  const float* __restrict__ w,
                                  const float* __restrict__ b) {
    __shared__ float lx[11];
    int row = blockIdx.x;
    int t = threadIdx.x;
    if (t < 11) lx[t] = log1pf(x[row * 11 + t]);
    __syncthreads();
    float s = b[t];
#pragma unroll
    for (int j = 0; j < 11; j++) s += lx[j] * w[j * C_ + t];
    g_atoms[row * C_ + t] = s;
}

// ---------------- CSR build ----------------
__global__ void count_deg_kernel(const int* __restrict__ dst) {
    int e = blockIdx.x * blockDim.x + threadIdx.x;
    if (e < E_) atomicAdd(&g_deg[dst[e]], 1);
}
__global__ void scan_deg_kernel() {
    __shared__ int sh[1024];
    __shared__ int carry;
    int t = threadIdx.x;
    if (t == 0) carry = 0;
    __syncthreads();
    for (int base = 0; base < TN; base += 1024) {
        int v = g_deg[base + t];
        sh[t] = v;
        __syncthreads();
        for (int off = 1; off < 1024; off <<= 1) {
            int add = (t >= off) ? sh[t - off] : 0;
            __syncthreads();
            sh[t] += add;
            __syncthreads();
        }
        int ip = carry + sh[t] - v;
        g_indptr[base + t] = ip;
        g_cursor[base + t] = ip;
        __syncthreads();
        if (t == 0) carry += sh[1023];
        __syncthreads();
    }
    if (t == 0) g_indptr[TN] = carry;
}
__global__ void fill_adj_kernel(const int* __restrict__ dst) {
    int e = blockIdx.x * blockDim.x + threadIdx.x;
    if (e < E_) {
        int p = atomicAdd(&g_cursor[dst[e]], 1);
        g_eadj[p] = e;
    }
}

// ---------------- GINE aggregation ----------------
__global__ void __launch_bounds__(256) gine_kernel(const int* __restrict__ src,
                                                   const float* __restrict__ eattr,
                                                   const float* __restrict__ ew,
                                                   const float* __restrict__ eb) {
    __shared__ float sew[4][C_];
    __shared__ float seb[C_];
    int tid = threadIdx.x;
    for (int i = tid; i < 4 * C_; i += 256) sew[i >> 8][i & 255] = ew[i];
    seb[tid] = eb[tid];
    __syncthreads();
    int warp = tid >> 5, lane = tid & 31;
    int v = blockIdx.x * 8 + warp;
    float acc[8];
#pragma unroll
    for (int k = 0; k < 8; k++) acc[k] = g_atoms[v * C_ + lane + 32 * k];
    int p0 = g_indptr[v], p1 = g_indptr[v + 1];
    for (int p = p0; p < p1; p++) {
        int e = g_eadj[p];
        int s = src[e];
        float4 ea4 = *reinterpret_cast<const float4*>(&eattr[e * 4]);
        const float* arow = &g_atoms[s * C_];
#pragma unroll
        for (int k = 0; k < 8; k++) {
            int c = lane + 32 * k;
            float eac = seb[c] + ea4.x * sew[0][c] + ea4.y * sew[1][c]
                               + ea4.z * sew[2][c] + ea4.w * sew[3][c];
            acc[k] += fmaxf(arow[c] + eac, 0.0f);
        }
    }
#pragma unroll
    for (int k = 0; k < 8; k++) g_h0[v * C_ + lane + 32 * k] = acc[k];
}

// ---------------- Performer attention: one CTA per (b,h); QKV packed stride 768 ----
#define PERF_SMEM_FLOATS (64 * MP_ + MP_ * 64 + 32 * MP_ + 2048 + 2048 + MP_ + 32)
#define QKV_STRIDE 768

__device__ __forceinline__ void phi_chunk(const float* __restrict__ ks,
                                          const float* __restrict__ projT,
                                          float* __restrict__ kp, int tid) {
    for (int t = tid; t < 32 * 68; t += 512) {
        int n = t / 68;
        int m0 = (t - n * 68) * 4;
        ull a01 = 0ull, a23 = 0ull;
        const float* krow = &ks[n * 64];
        const float* pT = &projT[m0];
#pragma unroll 8
        for (int d = 0; d < 64; d++) {
            float a = krow[d];
            ull a2 = f2pack(a, a);
            const ull* pp = reinterpret_cast<const ull*>(pT + d * MP_);
            a01 = ffma2(a2, pp[0], a01);
            a23 = ffma2(a2, pp[1], a23);
        }
        float r0, r1, r2, r3;
        f2unpack(a01, r0, r1);
        f2unpack(a23, r2, r3);
        float* kpr = &kp[n * MP_ + m0];
        kpr[0] = (m0 + 0 < M_) ? fmaxf(r0, 0.0f) + 1e-3f : 0.0f;
        kpr[1] = (m0 + 1 < M_) ? fmaxf(r1, 0.0f) + 1e-3f : 0.0f;
        kpr[2] = (m0 + 2 < M_) ? fmaxf(r2, 0.0f) + 1e-3f : 0.0f;
        kpr[3] = (m0 + 3 < M_) ? fmaxf(r3, 0.0f) + 1e-3f : 0.0f;
    }
}

__global__ void __launch_bounds__(512, 1) performer_kernel(const float* __restrict__ QKV,
                                                           const float* __restrict__ proj_l,
                                                           float* __restrict__ Att) {
    extern __shared__ float sm[];
    float* projT = sm;
    float* ctx = projT + 64 * MP_;
    float* kp = ctx + MP_ * 64;
    float* ks = kp + 32 * MP_;
    float* vs = ks + 2048;
    float* ksum = vs + 2048;
    float* den = ksum + MP_;

    const int tid = threadIdx.x;
    const int bh = blockIdx.x;
    const int b = bh >> 2;
    const int h = bh & 3;
    const int coff = h * 64;

    for (int idx = tid; idx < M_ * 64; idx += 512) {
        int m = idx >> 6, d = idx & 63;
        projT[d * MP_ + m] = proj_l[idx];
    }
    for (int idx = tid; idx < 64 * (MP_ - M_); idx += 512) {
        int d = idx / (MP_ - M_);
        int m = M_ + idx % (MP_ - M_);
        projT[d * MP_ + m] = 0.0f;
    }
    for (int idx = tid; idx < MP_ * 64; idx += 512) ctx[idx] = 0.0f;
    if (tid < MP_) ksum[tid] = 0.0f;
    __syncthreads();

    for (int c = 0; c < 16; c++) {
        int n0 = c * 32;
        for (int idx = tid; idx < 2048; idx += 512) {
            int n = idx >> 6, d = idx & 63;
            size_t gr = (size_t)(b * N_ + n0 + n) * QKV_STRIDE;
            ks[idx] = QKV[gr + 256 + coff + d];
            vs[idx] = QKV[gr + 512 + coff + d];
        }
        __syncthreads();
        phi_chunk(ks, projT, kp, tid);
        __syncthreads();
        for (int m = tid; m < MP_; m += 512) {
            float s = 0.0f;
#pragma unroll 8
            for (int n = 0; n < 32; n++) s += kp[n * MP_ + m];
            ksum[m] += s;
        }
        for (int t = tid; t < 68 * 16; t += 512) {
            int m0 = (t >> 4) << 2;
            int d0 = (t & 15) << 2;
            ull a[4][2];
#pragma unroll
            for (int q = 0; q < 4; q++) { a[q][0] = 0ull; a[q][1] = 0ull; }
#pragma unroll 4
            for (int n = 0; n < 32; n++) {
                float4 kv = *reinterpret_cast<const float4*>(&kp[n * MP_ + m0]);
                const ull* vvp = reinterpret_cast<const ull*>(&vs[n * 64 + d0]);
                ull v01 = vvp[0], v23 = vvp[1];
                a[0][0] = ffma2(f2pack(kv.x, kv.x), v01, a[0][0]);
                a[0][1] = ffma2(f2pack(kv.x, kv.x), v23, a[0][1]);
                a[1][0] = ffma2(f2pack(kv.y, kv.y), v01, a[1][0]);
                a[1][1] = ffma2(f2pack(kv.y, kv.y), v23, a[1][1]);
                a[2][0] = ffma2(f2pack(kv.z, kv.z), v01, a[2][0]);
                a[2][1] = ffma2(f2pack(kv.z, kv.z), v23, a[2][1]);
                a[3][0] = ffma2(f2pack(kv.w, kv.w), v01, a[3][0]);
                a[3][1] = ffma2(f2pack(kv.w, kv.w), v23, a[3][1]);
            }
#pragma unroll
            for (int q = 0; q < 4; q++) {
                float f0, f1, f2v, f3v;
                f2unpack(a[q][0], f0, f1);
                f2unpack(a[q][1], f2v, f3v);
                float* cp = &ctx[(m0 + q) * 64 + d0];
                cp[0] += f0; cp[1] += f1; cp[2] += f2v; cp[3] += f3v;
            }
        }
        __syncthreads();
    }

    for (int c = 0; c < 16; c++) {
        int n0 = c * 32;
        for (int idx = tid; idx < 2048; idx += 512) {
            int n = idx >> 6, d = idx & 63;
            size_t gr = (size_t)(b * N_ + n0 + n) * QKV_STRIDE;
            ks[idx] = QKV[gr + coff + d];
        }
        __syncthreads();
        phi_chunk(ks, projT, kp, tid);
        __syncthreads();
        if (tid < 32) {
            int n = tid;
            float s = 0.0f;
            const float* kpn = &kp[n * MP_];
#pragma unroll 8
            for (int m = 0; m < MP_; m++) s += kpn[m] * ksum[m];
            den[n] = 1.0f / s;
        }
        __syncthreads();
        {
            int n = tid >> 4;
            int d0 = (tid & 15) << 2;
            ull a01 = 0ull, a23 = 0ull;
            const float* kpn = &kp[n * MP_];
#pragma unroll 8
            for (int m = 0; m < MP_; m++) {
                float qv = kpn[m];
                ull q2 = f2pack(qv, qv);
                const ull* cp = reinterpret_cast<const ull*>(&ctx[m * 64 + d0]);
                a01 = ffma2(q2, cp[0], a01);
                a23 = ffma2(q2, cp[1], a23);
            }
            float f0, f1, f2v, f3v;
            f2unpack(a01, f0, f1);
            f2unpack(a23, f2v, f3v);
            float dn = den[n];
            int gr = b * N_ + n0 + n;
            *reinterpret_cast<float4*>(&Att[(size_t)gr * 256 + coff + d0]) =
                make_float4(f0 * dn, f1 * dn, f2v * dn, f3v * dn);
        }
        __syncthreads();
    }
}

// ---------------- final mean pool ----------------
__global__ void pool_kernel(float* __restrict__ out) {
    int b = blockIdx.x;
    int cix = threadIdx.x;
    float s = 0.0f;
    for (int n = 0; n < N_; n++) s += g_atoms[(b * N_ + n) * C_ + cix];
    out[b * C_ + cix] = s * (1.0f / (float)N_);
}

// ---------------- host launcher ----------------
extern "C" void kernel_launch(void* const* d_in, const int* in_sizes, int n_in,
                              void* d_out, int out_size) {
    const float* x      = (const float*)d_in[0];
    const float* eattr  = (const float*)d_in[1];
    const int*   eidx   = (const int*)d_in[2];
    const float* node_w = (const float*)d_in[4];
    const float* node_b = (const float*)d_in[5];
    const float* edge_w = (const float*)d_in[6];
    const float* edge_b = (const float*)d_in[7];
    const float* gw1    = (const float*)d_in[8];
    const float* gb1    = (const float*)d_in[9];
    const float* gw2    = (const float*)d_in[10];
    const float* gb2    = (const float*)d_in[11];
    const float* qw     = (const float*)d_in[12];
    const float* kw     = (const float*)d_in[13];
    const float* vw     = (const float*)d_in[14];
    const float* ow     = (const float*)d_in[15];
    const float* ob     = (const float*)d_in[16];
    const float* proj   = (const float*)d_in[17];
    const float* n1g    = (const float*)d_in[18];
    const float* n1b    = (const float*)d_in[19];
    const float* n2g    = (const float*)d_in[20];
    const float* n2b    = (const float*)d_in[21];
    const float* n3g    = (const float*)d_in[22];
    const float* n3b    = (const float*)d_in[23];
    const float* mw1    = (const float*)d_in[24];
    const float* mb1    = (const float*)d_in[25];
    const float* mw2    = (const float*)d_in[26];
    const float* mb2    = (const float*)d_in[27];

    const int* src = eidx;
    const int* dst = eidx + E_;

    float *p_atoms, *p_h0, *p_t1, *p_t2, *p_hloc, *p_qkv, *p_att, *p_out;
    __half* p_wt;
    int* p_deg;
    cudaGetSymbolAddress((void**)&p_atoms, g_atoms);
    cudaGetSymbolAddress((void**)&p_h0,    g_h0);
    cudaGetSymbolAddress((void**)&p_t1,    g_t1);
    cudaGetSymbolAddress((void**)&p_t2,    g_t2);
    cudaGetSymbolAddress((void**)&p_hloc,  g_hloc);
    cudaGetSymbolAddress((void**)&p_qkv,   g_qkv);
    cudaGetSymbolAddress((void**)&p_att,   g_att);
    cudaGetSymbolAddress((void**)&p_out,   g_out);
    cudaGetSymbolAddress((void**)&p_wt,    g_wt);
    cudaGetSymbolAddress((void**)&p_deg,   g_deg);

    cudaFuncSetAttribute(performer_kernel, cudaFuncAttributeMaxDynamicSharedMemorySize,
                         PERF_SMEM_FLOATS * 4);
    cudaFuncSetAttribute(mma_gemm<0>, cudaFuncAttributeMaxDynamicSharedMemorySize,
                         GEMM_SMEM_WORDS * 4);
    cudaFuncSetAttribute(mma_gemm<1>, cudaFuncAttributeMaxDynamicSharedMemorySize,
                         GEMM_SMEM_WORDS * 4);

    WPtrs wp;
    wp.p[0] = gw1; wp.p[1] = gw2; wp.p[2] = qw; wp.p[3] = kw;
    wp.p[4] = vw;  wp.p[5] = ow;  wp.p[6] = mw1; wp.p[7] = mw2;
    transpose_kernel<<<dim3(16, 16, 40), dim3(32, 8)>>>(wp);                 // launch 1

    node_embed_kernel<<<TN, 256>>>(x, node_w, node_b);                       // launch 2
    cudaMemsetAsync(p_deg, 0, TN * sizeof(int));
    count_deg_kernel<<<E_ / 256, 256>>>(dst);                                // launch 3

    const int SMG = GEMM_SMEM_WORDS * 4;
    dim3 g1(TN / 64, 1), g2(TN / 64, 2), g3(TN / 64, 3);

    // layer 0 QKV as 4th kernel launch (profiling target)
    mma_gemm<0><<<g3, 256, SMG>>>(p_atoms, p_wt + 131072, nullptr, nullptr, p_qkv, 256, 768);

    scan_deg_kernel<<<1, 1024>>>();
    fill_adj_kernel<<<E_ / 256, 256>>>(dst);

    for (int l = 0; l < L_; l++) {
        const __half* wt_l = p_wt + l * 655360;
        if (l > 0)
            mma_gemm<0><<<g3, 256, SMG>>>(p_atoms, wt_l + 131072, nullptr, nullptr, p_qkv, 256, 768);
        // GINE conv
        gine_kernel<<<TN / 8, 256>>>(src, eattr, edge_w, edge_b);
        mma_gemm<1><<<g1, 256, SMG>>>(p_h0, wt_l + 0, gb1 + l * C_, nullptr, p_t1, 256, 256);
        mma_gemm<0><<<g1, 256, SMG>>>(p_t1, wt_l + 65536, gb2 + l * C_, p_atoms, p_t2, 256, 256);
        ln_kernel<<<TN / 8, 256>>>(p_t2, n1g + l * C_, n1b + l * C_, nullptr, p_hloc);
        // Performer
        performer_kernel<<<B_ * H_, 512, PERF_SMEM_FLOATS * 4>>>(
            p_qkv, proj + l * M_ * DH_, p_att);
        // O-proj + LN + combine
        mma_gemm<0><<<g1, 256, SMG>>>(p_att, wt_l + 327680, ob + l * C_, p_atoms, p_t2, 256, 256);
        ln_kernel<<<TN / 8, 256>>>(p_t2, n2g + l * C_, n2b + l * C_, p_hloc, p_out);
        // FFN
        mma_gemm<1><<<g2, 256, SMG>>>(p_out, wt_l + 393216, mb1 + l * 2 * C_, nullptr, p_t1, 256, 512);
        mma_gemm<0><<<g1, 256, SMG>>>(p_t1, wt_l + 524288, mb2 + l * C_, p_out, p_t2, 512, 256);
        ln_kernel<<<TN / 8, 256>>>(p_t2, n3g + l * C_, n3b + l * C_, nullptr, p_atoms);
    }
    pool_kernel<<<B_, 256>>>((float*)d_out);
}

// round 8
// speedup vs baseline: 4.3981x; 2.7818x over previous
#include <cuda_runtime.h>
#include <cuda_fp16.h>
#include <math.h>
#include <stdint.h>

#define TN   32768
#define C_   256
#define B_   64
#define N_   512
#define H_   4
#define DH_  64
#define M_   266
#define E_   524288
#define L_   5

// ---------------- scratch ----------------
__device__ float g_atoms[TN * C_];
__device__ float g_h0[TN * C_];
__device__ float g_t1[TN * 2 * C_];
__device__ float g_t2[TN * C_];
__device__ float g_hloc[TN * C_];
__device__ float g_qkv[TN * 3 * C_];
__device__ float g_att[TN * C_];
__device__ float g_out[TN * C_];
__device__ __half g_wt[L_ * 655360];          // transposed fp16 weights, [n][k]
__device__ __half g_projh[L_ * 288 * 64];     // fp16 proj, rows >=266 zero
__device__ __half g_kp[(size_t)H_ * TN * 288];
__device__ __half g_qp[(size_t)H_ * TN * 288];
__device__ float g_ctx[256 * 80 * 320];       // [bh][d'][m]
__device__ int   g_deg[TN];
__device__ int   g_indptr[TN + 1];
__device__ int   g_cursor[TN];
__device__ int   g_eadj[E_];

// ---------------- helpers ----------------
__device__ __forceinline__ float gelu_exact(float x) {
    return 0.5f * x * (1.0f + erff(x * 0.70710678118654752f));
}
__device__ __forceinline__ uint32_t f2h2(float a, float b) {
    __half2 h = __floats2half2_rn(a, b);
    return *reinterpret_cast<uint32_t*>(&h);
}
__device__ __forceinline__ uint32_t smem_u32(const void* p) {
    uint32_t a;
    asm("{ .reg .u64 t; cvta.to.shared.u64 t, %1; cvt.u32.u64 %0, t; }" : "=r"(a) : "l"(p));
    return a;
}
__device__ __forceinline__ void mma_f16_16x8x16(float* d, const uint32_t* a, const uint32_t* b) {
    asm volatile(
        "mma.sync.aligned.m16n8k16.row.col.f32.f16.f16.f32 "
        "{%0,%1,%2,%3}, {%4,%5,%6,%7}, {%8,%9}, {%0,%1,%2,%3};"
        : "+f"(d[0]), "+f"(d[1]), "+f"(d[2]), "+f"(d[3])
        : "r"(a[0]), "r"(a[1]), "r"(a[2]), "r"(a[3]), "r"(b[0]), "r"(b[1]));
}
__device__ __forceinline__ void cp_async16(uint32_t saddr, const void* gptr) {
    asm volatile("cp.async.cg.shared.global [%0], [%1], 16;" :: "r"(saddr), "l"(gptr));
}
#define CP_COMMIT() asm volatile("cp.async.commit_group;" ::: "memory")
#define CP_WAIT0()  asm volatile("cp.async.wait_group 0;" ::: "memory")

// ---------------- weight transpose (once): WT[n*K+k] = half(W[k*N+n]) ----------------
struct WPtrs { const float* p[8]; };

__global__ void transpose_kernel(WPtrs wp) {
    int z = blockIdx.z;
    int t = z & 7, l = z >> 3;
    int K = (t == 7) ? 512 : 256;
    int N = (t == 6) ? 512 : 256;
    int n0 = blockIdx.x * 32, k0 = blockIdx.y * 32;
    if (n0 >= N || k0 >= K) return;
    const float* src = wp.p[t] + ((t >= 6) ? l * 131072 : l * 65536);
    int doff = (t < 6) ? t * 65536 : (t == 6 ? 393216 : 524288);
    __half* dst = g_wt + l * 655360 + doff;
    __shared__ float s[32][33];
    int tx = threadIdx.x, ty = threadIdx.y;
#pragma unroll
    for (int i = 0; i < 4; i++)
        s[ty + 8 * i][tx] = src[(k0 + ty + 8 * i) * N + n0 + tx];
    __syncthreads();
#pragma unroll
    for (int i = 0; i < 4; i++)
        dst[(n0 + ty + 8 * i) * K + k0 + tx] = __float2half_rn(s[tx][ty + 8 * i]);
}

// ---------------- proj -> fp16, padded to 288 rows ----------------
__global__ void proj_prep_kernel(const float* __restrict__ proj) {
    int idx = blockIdx.x * 256 + threadIdx.x;
    if (idx >= L_ * 288 * 64) return;
    int l = idx / (288 * 64);
    int r = idx - l * (288 * 64);
    int m = r >> 6, d = r & 63;
    g_projh[idx] = (m < M_) ? __float2half_rn(proj[(l * M_ + m) * 64 + d]) : __half(0.f);
}

// ---------------- fp16 mma GEMM (dense layers) ----------------
#define GEMM_SMEM_WORDS (2 * 2304 + 2 * 9216)

template <int MODE>
__global__ void __launch_bounds__(256, 2) mma_gemm(const float* __restrict__ A,
                                                   const __half* __restrict__ WT,
                                                   const float* __restrict__ bias,
                                                   const float* __restrict__ res,
                                                   float* __restrict__ Out,
                                                   int K, int Ntot) {
    extern __shared__ uint32_t smw[];
    const int tid = threadIdx.x;
    const int lane = tid & 31, wid = tid >> 5;
    const int g = lane >> 2, t = lane & 3;
    const int wm = (wid & 1) * 32;
    const int wn = (wid >> 1) * 64;
    const int rowbase = blockIdx.x * 64;
    const int colbase = blockIdx.y * 256;
    const uint32_t sb = smem_u32(smw);

    float acc[2][8][4];
#pragma unroll
    for (int mt = 0; mt < 2; mt++)
#pragma unroll
        for (int nt = 0; nt < 8; nt++)
#pragma unroll
            for (int j = 0; j < 4; j++) acc[mt][nt][j] = 0.0f;

    float4 areg[4];
    const int nk = K >> 6;

#pragma unroll
    for (int i = 0; i < 4; i++) {
        int idx = tid + i * 256;
        int m = idx >> 4, q = idx & 15;
        areg[i] = *reinterpret_cast<const float4*>(&A[(size_t)(rowbase + m) * K + q * 4]);
    }
#pragma unroll
    for (int i = 0; i < 8; i++) {
        int idx = tid + i * 256;
        int n = idx >> 3, c = idx & 7;
        cp_async16(sb + (4608 + n * 36 + c * 4) * 4,
                   &WT[(size_t)(colbase + n) * K + c * 8]);
    }
    CP_COMMIT();
#pragma unroll
    for (int i = 0; i < 4; i++) {
        int idx = tid + i * 256;
        int m = idx >> 4, q = idx & 15;
        uint32_t h01 = f2h2(areg[i].x, areg[i].y);
        uint32_t h23 = f2h2(areg[i].z, areg[i].w);
        uint32_t addr = sb + (m * 36 + q * 2) * 4;
        asm volatile("st.shared.v2.b32 [%0], {%1,%2};" :: "r"(addr), "r"(h01), "r"(h23));
    }
    CP_WAIT0();
    __syncthreads();

    for (int kb = 0; kb < nk; kb++) {
        const int cur = kb & 1;
        const bool nxt = (kb + 1 < nk);
        if (nxt) {
            int k0g = (kb + 1) * 64;
#pragma unroll
            for (int i = 0; i < 4; i++) {
                int idx = tid + i * 256;
                int m = idx >> 4, q = idx & 15;
                areg[i] = *reinterpret_cast<const float4*>(
                    &A[(size_t)(rowbase + m) * K + k0g + q * 4]);
            }
            int sB = cur ^ 1;
#pragma unroll
            for (int i = 0; i < 8; i++) {
                int idx = tid + i * 256;
                int n = idx >> 3, c = idx & 7;
                cp_async16(sb + (4608 + sB * 9216 + n * 36 + c * 4) * 4,
                           &WT[(size_t)(colbase + n) * K + k0g + c * 8]);
            }
            CP_COMMIT();
        }
        {
            const uint32_t* As = smw + cur * 2304;
            const uint32_t* Bs = smw + 4608 + cur * 9216;
#pragma unroll
            for (int ks = 0; ks < 4; ks++) {
                const int k0 = ks * 8;
                uint32_t af[2][4], bf[8][2];
#pragma unroll
                for (int mt = 0; mt < 2; mt++) {
                    int r0 = wm + mt * 16 + g;
                    af[mt][0] = As[r0 * 36 + k0 + t];
                    af[mt][1] = As[(r0 + 8) * 36 + k0 + t];
                    af[mt][2] = As[r0 * 36 + k0 + t + 4];
                    af[mt][3] = As[(r0 + 8) * 36 + k0 + t + 4];
                }
#pragma unroll
                for (int nt = 0; nt < 8; nt++) {
                    int n0 = wn + nt * 8 + g;
                    bf[nt][0] = Bs[n0 * 36 + k0 + t];
                    bf[nt][1] = Bs[n0 * 36 + k0 + t + 4];
                }
#pragma unroll
                for (int mt = 0; mt < 2; mt++)
#pragma unroll
                    for (int nt = 0; nt < 8; nt++)
                        mma_f16_16x8x16(acc[mt][nt], af[mt], bf[nt]);
            }
        }
        if (nxt) {
            int sB = cur ^ 1;
#pragma unroll
            for (int i = 0; i < 4; i++) {
                int idx = tid + i * 256;
                int m = idx >> 4, q = idx & 15;
                uint32_t h01 = f2h2(areg[i].x, areg[i].y);
                uint32_t h23 = f2h2(areg[i].z, areg[i].w);
                uint32_t addr = sb + (sB * 2304 + m * 36 + q * 2) * 4;
                asm volatile("st.shared.v2.b32 [%0], {%1,%2};" :: "r"(addr), "r"(h01), "r"(h23));
            }
            CP_WAIT0();
            __syncthreads();
        }
    }

#pragma unroll
    for (int mt = 0; mt < 2; mt++) {
        int r0 = rowbase + wm + mt * 16 + g;
#pragma unroll
        for (int nt = 0; nt < 8; nt++) {
            int col = colbase + wn + nt * 8 + 2 * t;
            float b0 = 0.0f, b1 = 0.0f;
            if (bias) { b0 = bias[col]; b1 = bias[col + 1]; }
            float v0 = acc[mt][nt][0] + b0, v1 = acc[mt][nt][1] + b1;
            float v2 = acc[mt][nt][2] + b0, v3 = acc[mt][nt][3] + b1;
            if (MODE == 0) {
                if (res) {
                    float2 r01 = *reinterpret_cast<const float2*>(&res[(size_t)r0 * 256 + col]);
                    float2 r23 = *reinterpret_cast<const float2*>(&res[(size_t)(r0 + 8) * 256 + col]);
                    v0 += r01.x; v1 += r01.y; v2 += r23.x; v3 += r23.y;
                }
            } else {
                v0 = gelu_exact(v0); v1 = gelu_exact(v1);
                v2 = gelu_exact(v2); v3 = gelu_exact(v3);
            }
            *reinterpret_cast<float2*>(&Out[(size_t)r0 * Ntot + col]) = make_float2(v0, v1);
            *reinterpret_cast<float2*>(&Out[(size_t)(r0 + 8) * Ntot + col]) = make_float2(v2, v3);
        }
    }
}

// ---------------- Performer stage 1: kp/qp = relu(X_h @ projT)+eps, fp16 ----------------
#define S1_SMEM_BYTES ((2304 + 10368) * 4)

__global__ void __launch_bounds__(256) phi_kernel(const float* __restrict__ QKV,
                                                  const __half* __restrict__ projh_l,
                                                  __half* __restrict__ KP,
                                                  __half* __restrict__ QP) {
    extern __shared__ uint32_t sw[];
    uint32_t* As = sw;           // 64 x 36 words
    uint32_t* Bs = sw + 2304;    // 288 x 36 words
    const int tid = threadIdx.x;
    const int lane = tid & 31, wid = tid >> 5;
    const int g = lane >> 2, t = lane & 3;
    const int wm = (wid & 1) * 32;
    const int wn = (wid >> 1) * 72;
    const int rowbase = blockIdx.x * 64;
    const int h = blockIdx.y & 3;
    const int isq = blockIdx.y >> 2;
    const float* A = QKV + (isq ? h * 64 : 256 + h * 64);
    __half* outp = (isq ? QP : KP) + (size_t)h * TN * 288;

    const uint32_t* pb = (const uint32_t*)projh_l;
#pragma unroll
    for (int i = 0; i < 36; i++) {
        int w = tid + i * 256;
        Bs[(w >> 5) * 36 + (w & 31)] = pb[w];
    }
#pragma unroll
    for (int i = 0; i < 4; i++) {
        int idx = tid + i * 256;
        int m = idx >> 4, q4 = idx & 15;
        float4 v = *reinterpret_cast<const float4*>(&A[(size_t)(rowbase + m) * 768 + q4 * 4]);
        As[m * 36 + q4 * 2] = f2h2(v.x, v.y);
        As[m * 36 + q4 * 2 + 1] = f2h2(v.z, v.w);
    }
    __syncthreads();

    float acc[2][9][4];
#pragma unroll
    for (int mt = 0; mt < 2; mt++)
#pragma unroll
        for (int nt = 0; nt < 9; nt++)
#pragma unroll
            for (int j = 0; j < 4; j++) acc[mt][nt][j] = 0.0f;

#pragma unroll
    for (int ks = 0; ks < 4; ks++) {
        int k0 = ks * 8;
        uint32_t af[2][4], bf[9][2];
#pragma unroll
        for (int mt = 0; mt < 2; mt++) {
            int r0 = wm + mt * 16 + g;
            af[mt][0] = As[r0 * 36 + k0 + t];
            af[mt][1] = As[(r0 + 8) * 36 + k0 + t];
            af[mt][2] = As[r0 * 36 + k0 + t + 4];
            af[mt][3] = As[(r0 + 8) * 36 + k0 + t + 4];
        }
#pragma unroll
        for (int nt = 0; nt < 9; nt++) {
            int n0 = wn + nt * 8 + g;
            bf[nt][0] = Bs[n0 * 36 + k0 + t];
            bf[nt][1] = Bs[n0 * 36 + k0 + t + 4];
        }
#pragma unroll
        for (int mt = 0; mt < 2; mt++)
#pragma unroll
            for (int nt = 0; nt < 9; nt++)
                mma_f16_16x8x16(acc[mt][nt], af[mt], bf[nt]);
    }

#pragma unroll
    for (int mt = 0; mt < 2; mt++) {
        int r = rowbase + wm + mt * 16 + g;
#pragma unroll
        for (int nt = 0; nt < 9; nt++) {
            int c0 = wn + nt * 8 + 2 * t;
            float v0 = fmaxf(acc[mt][nt][0], 0.0f) + 1e-3f;
            float v1 = fmaxf(acc[mt][nt][1], 0.0f) + 1e-3f;
            float v2 = fmaxf(acc[mt][nt][2], 0.0f) + 1e-3f;
            float v3 = fmaxf(acc[mt][nt][3], 0.0f) + 1e-3f;
            if (c0 >= M_) { v0 = 0.0f; v2 = 0.0f; }
            if (c0 + 1 >= M_) { v1 = 0.0f; v3 = 0.0f; }
            *reinterpret_cast<uint32_t*>(&outp[(size_t)r * 288 + c0]) = f2h2(v0, v1);
            *reinterpret_cast<uint32_t*>(&outp[(size_t)(r + 8) * 288 + c0]) = f2h2(v2, v3);
        }
    }
}

// ---------------- Performer stage 2: ctx[m,d'] = sum_n kp[n,m] * V'[n,d'] ----------------
// V' col 64 = 1 (gives ksum), cols 65..79 = 0. Output layout [bh][d'][320].
#define S2_SMEM_BYTES ((11520 + 2880) * 4)

__global__ void __launch_bounds__(256) ctx_kernel(const __half* __restrict__ KP,
                                                  const float* __restrict__ QKV,
                                                  float* __restrict__ CTX) {
    extern __shared__ uint32_t sw[];
    uint32_t* kpT = sw;                   // 320 x 36 words ([m][n], 72-half rows)
    uint32_t* vsb = sw + 11520;           // 80 x 36 words ([d'][n])
    __half* kpT_h = (__half*)kpT;
    __half* vs_h = (__half*)vsb;
    const int tid = threadIdx.x;
    const int lane = tid & 31, wid = tid >> 5;
    const int g = lane >> 2, t = lane & 3;
    const int wm = (wid & 3) * 80;
    const int wn = (wid >> 2) * 40;
    const int bh = blockIdx.x;
    const int b = bh >> 2, h = bh & 3;

    // one-time zeros: kpT rows 288..319; vs rows 64..79 (row 64 = ones)
    for (int i = tid; i < 32 * 72; i += 256)
        kpT_h[(288 + i / 72) * 72 + (i % 72)] = __float2half(0.0f);
    for (int i = tid; i < 16 * 72; i += 256) {
        int d = 64 + i / 72, n = i % 72;
        vs_h[d * 72 + n] = __float2half((d == 64 && n < 64) ? 1.0f : 0.0f);
    }

    float acc[5][5][4];
#pragma unroll
    for (int mt = 0; mt < 5; mt++)
#pragma unroll
        for (int nt = 0; nt < 5; nt++)
#pragma unroll
            for (int j = 0; j < 4; j++) acc[mt][nt][j] = 0.0f;

    const uint32_t* kp2 = (const uint32_t*)(KP + (size_t)h * TN * 288);

    for (int c = 0; c < 8; c++) {
        __syncthreads();
        int base = b * 512 + c * 64;
        // stage kpT (transpose [n][m] -> [m][n])
#pragma unroll
        for (int i = 0; i < 36; i++) {
            int idx = tid + i * 256;            // < 9216 = 64 x 144
            int n = idx / 144, m2 = idx - n * 144;
            uint32_t w = kp2[(size_t)(base + n) * 144 + m2];
            __half2 hh = *reinterpret_cast<const __half2*>(&w);
            kpT_h[(2 * m2) * 72 + n] = __low2half(hh);
            kpT_h[(2 * m2 + 1) * 72 + n] = __high2half(hh);
        }
        // stage vs (transpose V [n][d] -> [d][n])
#pragma unroll
        for (int i = 0; i < 16; i++) {
            int idx = tid + i * 256;            // < 4096
            int n = idx >> 6, d = idx & 63;
            float v = QKV[(size_t)(base + n) * 768 + 512 + h * 64 + d];
            vs_h[d * 72 + n] = __float2half_rn(v);
        }
        __syncthreads();
#pragma unroll
        for (int ks = 0; ks < 4; ks++) {
            int k0 = ks * 8;
            uint32_t af[5][4], bf[5][2];
#pragma unroll
            for (int mt = 0; mt < 5; mt++) {
                int r0 = wm + mt * 16 + g;
                af[mt][0] = kpT[r0 * 36 + k0 + t];
                af[mt][1] = kpT[(r0 + 8) * 36 + k0 + t];
                af[mt][2] = kpT[r0 * 36 + k0 + t + 4];
                af[mt][3] = kpT[(r0 + 8) * 36 + k0 + t + 4];
            }
#pragma unroll
            for (int nt = 0; nt < 5; nt++) {
                int n0 = wn + nt * 8 + g;
                bf[nt][0] = vsb[n0 * 36 + k0 + t];
                bf[nt][1] = vsb[n0 * 36 + k0 + t + 4];
            }
#pragma unroll
            for (int mt = 0; mt < 5; mt++)
#pragma unroll
                for (int nt = 0; nt < 5; nt++)
                    mma_f16_16x8x16(acc[mt][nt], af[mt], bf[nt]);
        }
    }

    float* outc = CTX + (size_t)bh * 80 * 320;
#pragma unroll
    for (int mt = 0; mt < 5; mt++) {
        int m0 = wm + mt * 16 + g;
#pragma unroll
        for (int nt = 0; nt < 5; nt++) {
            int c0 = wn + nt * 8 + 2 * t;
            outc[(size_t)c0 * 320 + m0] = acc[mt][nt][0];
            outc[(size_t)(c0 + 1) * 320 + m0] = acc[mt][nt][1];
            outc[(size_t)c0 * 320 + m0 + 8] = acc[mt][nt][2];
            outc[(size_t)(c0 + 1) * 320 + m0 + 8] = acc[mt][nt][3];
        }
    }
}

// ---------------- Performer stage 3: att' = qp @ ctx ; normalize by col 64 ----------------
#define S3_W_CTX (80 * 164)
#define S3_W_AS  (64 * 148)
#define S3_W_ATT (64 * 80)
#define S3_SMEM_BYTES ((S3_W_CTX + S3_W_AS + S3_W_ATT) * 4)

__global__ void __launch_bounds__(256) att_kernel(const __half* __restrict__ QP,
                                                  const float* __restrict__ CTX,
                                                  float* __restrict__ Att) {
    extern __shared__ uint32_t sw[];
    uint32_t* ctxT = sw;                            // 80 x 164 words ([d'][m] fp16)
    uint32_t* As = sw + S3_W_CTX;                   // 64 x 148 words (qp rows)
    float* att_s = (float*)(sw + S3_W_CTX + S3_W_AS); // 64 x 80
    const int tid = threadIdx.x;
    const int lane = tid & 31, wid = tid >> 5;
    const int g = lane >> 2, t = lane & 3;
    const int wm = (wid & 3) * 16;
    const int wn = (wid >> 2) * 40;
    const int cta = blockIdx.x;
    const int bh = cta >> 1, half = cta & 1;
    const int b = bh >> 2, h = bh & 3;

    const float* cg = CTX + (size_t)bh * 80 * 320;
#pragma unroll
    for (int i = 0; i < 50; i++) {
        int idx = tid + i * 256;                    // < 12800 = 80 x 160
        int d = idx / 160, m2 = idx - d * 160;
        float2 v = *reinterpret_cast<const float2*>(&cg[(size_t)d * 320 + m2 * 2]);
        ctxT[d * 164 + m2] = f2h2(v.x, v.y);
    }
    const uint32_t* qp2 = (const uint32_t*)(QP + (size_t)h * TN * 288);
    const int rowg0 = b * 512 + half * 256;

    for (int ch = 0; ch < 4; ch++) {
        __syncthreads();
        int rbase = rowg0 + ch * 64;
#pragma unroll
        for (int i = 0; i < 36; i++) {
            int idx = tid + i * 256;                // < 9216 = 64 x 144
            int n = idx / 144, m2 = idx - n * 144;
            As[n * 148 + m2] = qp2[(size_t)(rbase + n) * 144 + m2];
        }
        __syncthreads();
        float acc[5][4];
#pragma unroll
        for (int nt = 0; nt < 5; nt++)
#pragma unroll
            for (int j = 0; j < 4; j++) acc[nt][j] = 0.0f;
#pragma unroll
        for (int ks = 0; ks < 17; ks++) {
            int k0 = ks * 8;
            uint32_t af[4], bf[5][2];
            int r0 = wm + g;
            af[0] = As[r0 * 148 + k0 + t];
            af[1] = As[(r0 + 8) * 148 + k0 + t];
            af[2] = As[r0 * 148 + k0 + t + 4];
            af[3] = As[(r0 + 8) * 148 + k0 + t + 4];
#pragma unroll
            for (int nt = 0; nt < 5; nt++) {
                int n0 = wn + nt * 8 + g;
                bf[nt][0] = ctxT[n0 * 164 + k0 + t];
                bf[nt][1] = ctxT[n0 * 164 + k0 + t + 4];
            }
#pragma unroll
            for (int nt = 0; nt < 5; nt++)
                mma_f16_16x8x16(acc[nt], af, bf[nt]);
        }
#pragma unroll
        for (int nt = 0; nt < 5; nt++) {
            int c0 = wn + nt * 8 + 2 * t;
            att_s[(wm + g) * 80 + c0] = acc[nt][0];
            att_s[(wm + g) * 80 + c0 + 1] = acc[nt][1];
            att_s[(wm + g + 8) * 80 + c0] = acc[nt][2];
            att_s[(wm + g + 8) * 80 + c0 + 1] = acc[nt][3];
        }
        __syncthreads();
#pragma unroll
        for (int i = 0; i < 16; i++) {
            int idx = tid + i * 256;                // < 4096 = 64 x 64
            int n = idx >> 6, d = idx & 63;
            float den = att_s[n * 80 + 64];
            Att[(size_t)(rbase + n) * 256 + h * 64 + d] = att_s[n * 80 + d] / den;
        }
    }
}

// ---------------- LayerNorm ----------------
__global__ void __launch_bounds__(256) ln_kernel(const float* __restrict__ a,
                                                 const float* __restrict__ lng,
                                                 const float* __restrict__ lnb,
                                                 const float* __restrict__ add2,
                                                 float* __restrict__ out) {
    int row = blockIdx.x * 8 + (threadIdx.x >> 5);
    int lane = threadIdx.x & 31;
    const float* ar = a + (size_t)row * 256 + lane * 8;
    float4 v0 = *reinterpret_cast<const float4*>(ar);
    float4 v1 = *reinterpret_cast<const float4*>(ar + 4);
    float s1 = v0.x + v0.y + v0.z + v0.w + v1.x + v1.y + v1.z + v1.w;
    float s2 = v0.x * v0.x + v0.y * v0.y + v0.z * v0.z + v0.w * v0.w
             + v1.x * v1.x + v1.y * v1.y + v1.z * v1.z + v1.w * v1.w;
#pragma unroll
    for (int off = 16; off > 0; off >>= 1) {
        s1 += __shfl_xor_sync(0xffffffffu, s1, off);
        s2 += __shfl_xor_sync(0xffffffffu, s2, off);
    }
    float mean = s1 * (1.0f / 256.0f);
    float var = s2 * (1.0f / 256.0f) - mean * mean;
    float rstd = rsqrtf(var + 1e-5f);
    float4 g0 = *reinterpret_cast<const float4*>(&lng[lane * 8]);
    float4 g1 = *reinterpret_cast<const float4*>(&lng[lane * 8 + 4]);
    float4 b0 = *reinterpret_cast<const float4*>(&lnb[lane * 8]);
    float4 b1 = *reinterpret_cast<const float4*>(&lnb[lane * 8 + 4]);
    float4 o0, o1;
    o0.x = (v0.x - mean) * rstd * g0.x + b0.x;
    o0.y = (v0.y - mean) * rstd * g0.y + b0.y;
    o0.z = (v0.z - mean) * rstd * g0.z + b0.z;
    o0.w = (v0.w - mean) * rstd * g0.w + b0.w;
    o1.x = (v1.x - mean) * rstd * g1.x + b1.x;
    o1.y = (v1.y - mean) * rstd * g1.y + b1.y;
    o1.z = (v1.z - mean) * rstd * g1.z + b1.z;
    o1.w = (v1.w - mean) * rstd * g1.w + b1.w;
    if (add2) {
        const float* a2 = add2 + (size_t)row * 256 + lane * 8;
        float4 x0 = *reinterpret_cast<const float4*>(a2);
        float4 x1 = *reinterpret_cast<const float4*>(a2 + 4);
        o0.x += x0.x; o0.y += x0.y; o0.z += x0.z; o0.w += x0.w;
        o1.x += x1.x; o1.y += x1.y; o1.z += x1.z; o1.w += x1.w;
    }
    float* orow = out + (size_t)row * 256 + lane * 8;
    *reinterpret_cast<float4*>(orow) = o0;
    *reinterpret_cast<float4*>(orow + 4) = o1;
}

// ---------------- node embedding ----------------
__global__ void node_embed_kernel(const float* __restrict__ x,
                                  const float* __restrict__ w,
                                  const float* __restrict__ b) {
    __shared__ float lx[11];
    int row = blockIdx.x;
    int t = threadIdx.x;
    if (t < 11) lx[t] = log1pf(x[row * 11 + t]);
    __syncthreads();
    float s = b[t];
#pragma unroll
    for (int j = 0; j < 11; j++) s += lx[j] * w[j * C_ + t];
    g_atoms[row * C_ + t] = s;
}

// ---------------- CSR build ----------------
__global__ void count_deg_kernel(const int* __restrict__ dst) {
    int e = blockIdx.x * blockDim.x + threadIdx.x;
    if (e < E_) atomicAdd(&g_deg[dst[e]], 1);
}
__global__ void scan_deg_kernel() {
    __shared__ int sh[1024];
    __shared__ int carry;
    int t = threadIdx.x;
    if (t == 0) carry = 0;
    __syncthreads();
    for (int base = 0; base < TN; base += 1024) {
        int v = g_deg[base + t];
        sh[t] = v;
        __syncthreads();
        for (int off = 1; off < 1024; off <<= 1) {
            int add = (t >= off) ? sh[t - off] : 0;
            __syncthreads();
            sh[t] += add;
            __syncthreads();
        }
        int ip = carry + sh[t] - v;
        g_indptr[base + t] = ip;
        g_cursor[base + t] = ip;
        __syncthreads();
        if (t == 0) carry += sh[1023];
        __syncthreads();
    }
    if (t == 0) g_indptr[TN] = carry;
}
__global__ void fill_adj_kernel(const int* __restrict__ dst) {
    int e = blockIdx.x * blockDim.x + threadIdx.x;
    if (e < E_) {
        int p = atomicAdd(&g_cursor[dst[e]], 1);
        g_eadj[p] = e;
    }
}

// ---------------- GINE aggregation ----------------
__global__ void __launch_bounds__(256) gine_kernel(const int* __restrict__ src,
                                                   const float* __restrict__ eattr,
                                                   const float* __restrict__ ew,
                                                   const float* __restrict__ eb) {
    __shared__ float sew[4][C_];
    __shared__ float seb[C_];
    int tid = threadIdx.x;
    for (int i = tid; i < 4 * C_; i += 256) sew[i >> 8][i & 255] = ew[i];
    seb[tid] = eb[tid];
    __syncthreads();
    int warp = tid >> 5, lane = tid & 31;
    int v = blockIdx.x * 8 + warp;
    float acc[8];
#pragma unroll
    for (int k = 0; k < 8; k++) acc[k] = g_atoms[v * C_ + lane + 32 * k];
    int p0 = g_indptr[v], p1 = g_indptr[v + 1];
    for (int p = p0; p < p1; p++) {
        int e = g_eadj[p];
        int s = src[e];
        float4 ea4 = *reinterpret_cast<const float4*>(&eattr[e * 4]);
        const float* arow = &g_atoms[s * C_];
#pragma unroll
        for (int k = 0; k < 8; k++) {
            int c = lane + 32 * k;
            float eac = seb[c] + ea4.x * sew[0][c] + ea4.y * sew[1][c]
                               + ea4.z * sew[2][c] + ea4.w * sew[3][c];
            acc[k] += fmaxf(arow[c] + eac, 0.0f);
        }
    }
#pragma unroll
    for (int k = 0; k < 8; k++) g_h0[v * C_ + lane + 32 * k] = acc[k];
}

// ---------------- final mean pool ----------------
__global__ void pool_kernel(float* __restrict__ out) {
    int b = blockIdx.x;
    int cix = threadIdx.x;
    float s = 0.0f;
    for (int n = 0; n < N_; n++) s += g_atoms[(b * N_ + n) * C_ + cix];
    out[b * C_ + cix] = s * (1.0f / (float)N_);
}

// ---------------- host launcher ----------------
extern "C" void kernel_launch(void* const* d_in, const int* in_sizes, int n_in,
                              void* d_out, int out_size) {
    const float* x      = (const float*)d_in[0];
    const float* eattr  = (const float*)d_in[1];
    const int*   eidx   = (const int*)d_in[2];
    const float* node_w = (const float*)d_in[4];
    const float* node_b = (const float*)d_in[5];
    const float* edge_w = (const float*)d_in[6];
    const float* edge_b = (const float*)d_in[7];
    const float* gw1    = (const float*)d_in[8];
    const float* gb1    = (const float*)d_in[9];
    const float* gw2    = (const float*)d_in[10];
    const float* gb2    = (const float*)d_in[11];
    const float* qw     = (const float*)d_in[12];
    const float* kw     = (const float*)d_in[13];
    const float* vw     = (const float*)d_in[14];
    const float* ow     = (const float*)d_in[15];
    const float* ob     = (const float*)d_in[16];
    const float* proj   = (const float*)d_in[17];
    const float* n1g    = (const float*)d_in[18];
    const float* n1b    = (const float*)d_in[19];
    const float* n2g    = (const float*)d_in[20];
    const float* n2b    = (const float*)d_in[21];
    const float* n3g    = (const float*)d_in[22];
    const float* n3b    = (const float*)d_in[23];
    const float* mw1    = (const float*)d_in[24];
    const float* mb1    = (const float*)d_in[25];
    const float* mw2    = (const float*)d_in[26];
    const float* mb2    = (const float*)d_in[27];

    const int* src = eidx;
    const int* dst = eidx + E_;

    float *p_atoms, *p_h0, *p_t1, *p_t2, *p_hloc, *p_qkv, *p_att, *p_out, *p_ctx;
    __half *p_wt, *p_projh, *p_kp, *p_qp;
    int* p_deg;
    cudaGetSymbolAddress((void**)&p_atoms, g_atoms);
    cudaGetSymbolAddress((void**)&p_h0,    g_h0);
    cudaGetSymbolAddress((void**)&p_t1,    g_t1);
    cudaGetSymbolAddress((void**)&p_t2,    g_t2);
    cudaGetSymbolAddress((void**)&p_hloc,  g_hloc);
    cudaGetSymbolAddress((void**)&p_qkv,   g_qkv);
    cudaGetSymbolAddress((void**)&p_att,   g_att);
    cudaGetSymbolAddress((void**)&p_out,   g_out);
    cudaGetSymbolAddress((void**)&p_ctx,   g_ctx);
    cudaGetSymbolAddress((void**)&p_wt,    g_wt);
    cudaGetSymbolAddress((void**)&p_projh, g_projh);
    cudaGetSymbolAddress((void**)&p_kp,    g_kp);
    cudaGetSymbolAddress((void**)&p_qp,    g_qp);
    cudaGetSymbolAddress((void**)&p_deg,   g_deg);

    cudaFuncSetAttribute(mma_gemm<0>, cudaFuncAttributeMaxDynamicSharedMemorySize,
                         GEMM_SMEM_WORDS * 4);
    cudaFuncSetAttribute(mma_gemm<1>, cudaFuncAttributeMaxDynamicSharedMemorySize,
                         GEMM_SMEM_WORDS * 4);
    cudaFuncSetAttribute(phi_kernel, cudaFuncAttributeMaxDynamicSharedMemorySize, S1_SMEM_BYTES);
    cudaFuncSetAttribute(ctx_kernel, cudaFuncAttributeMaxDynamicSharedMemorySize, S2_SMEM_BYTES);
    cudaFuncSetAttribute(att_kernel, cudaFuncAttributeMaxDynamicSharedMemorySize, S3_SMEM_BYTES);

    WPtrs wp;
    wp.p[0] = gw1; wp.p[1] = gw2; wp.p[2] = qw; wp.p[3] = kw;
    wp.p[4] = vw;  wp.p[5] = ow;  wp.p[6] = mw1; wp.p[7] = mw2;
    transpose_kernel<<<dim3(16, 16, 40), dim3(32, 8)>>>(wp);                  // 1
    proj_prep_kernel<<<(L_ * 288 * 64 + 255) / 256, 256>>>(proj);             // 2
    node_embed_kernel<<<TN, 256>>>(x, node_w, node_b);                        // 3

    const int SMG = GEMM_SMEM_WORDS * 4;
    dim3 g1(TN / 64, 1), g2(TN / 64, 2), g3(TN / 64, 3);
    bool csr_built = false;

    for (int l = 0; l < L_; l++) {
        const __half* wt_l = p_wt + l * 655360;
        // QKV (one fused GEMM, N=768)
        mma_gemm<0><<<g3, 256, SMG>>>(p_atoms, wt_l + 131072, nullptr, nullptr, p_qkv, 256, 768);
        // Performer (3 mma stages)
        phi_kernel<<<dim3(512, 8), 256, S1_SMEM_BYTES>>>(p_qkv, p_projh + l * 288 * 64, p_kp, p_qp);
        ctx_kernel<<<256, 256, S2_SMEM_BYTES>>>(p_kp, p_qkv, p_ctx);
        att_kernel<<<512, 256, S3_SMEM_BYTES>>>(p_qp, p_ctx, p_att);
        // CSR build (once, before first gine)
        if (!csr_built) {
            cudaMemsetAsync(p_deg, 0, TN * sizeof(int));
            count_deg_kernel<<<E_ / 256, 256>>>(dst);
            scan_deg_kernel<<<1, 1024>>>();
            fill_adj_kernel<<<E_ / 256, 256>>>(dst);
            csr_built = true;
        }
        // GINE conv
        gine_kernel<<<TN / 8, 256>>>(src, eattr, edge_w, edge_b);
        mma_gemm<1><<<g1, 256, SMG>>>(p_h0, wt_l + 0, gb1 + l * C_, nullptr, p_t1, 256, 256);
        mma_gemm<0><<<g1, 256, SMG>>>(p_t1, wt_l + 65536, gb2 + l * C_, p_atoms, p_t2, 256, 256);
        ln_kernel<<<TN / 8, 256>>>(p_t2, n1g + l * C_, n1b + l * C_, nullptr, p_hloc);
        // O-proj + LN + combine
        mma_gemm<0><<<g1, 256, SMG>>>(p_att, wt_l + 327680, ob + l * C_, p_atoms, p_t2, 256, 256);
        ln_kernel<<<TN / 8, 256>>>(p_t2, n2g + l * C_, n2b + l * C_, p_hloc, p_out);
        // FFN
        mma_gemm<1><<<g2, 256, SMG>>>(p_out, wt_l + 393216, mb1 + l * 2 * C_, nullptr, p_t1, 256, 512);
        mma_gemm<0><<<g1, 256, SMG>>>(p_t1, wt_l + 524288, mb2 + l * C_, p_out, p_t2, 512, 256);
        ln_kernel<<<TN / 8, 256>>>(p_t2, n3g + l * C_, n3b + l * C_, nullptr, p_atoms);
    }
    pool_kernel<<<B_, 256>>>((float*)d_out);
}

// round 9
// speedup vs baseline: 4.6689x; 1.0616x over previous
#include <cuda_runtime.h>
#include <cuda_fp16.h>
#include <math.h>
#include <stdint.h>

#define TN   32768
#define C_   256
#define B_   64
#define N_   512
#define H_   4
#define DH_  64
#define M_   266
#define E_   524288
#define L_   5

// ---------------- scratch ----------------
__device__ float  g_atoms[TN * C_];
__device__ __half g_atoms16[TN * C_];
__device__ __half g_h016[TN * C_];
__device__ __half g_t116[TN * 2 * C_];
__device__ float  g_t2[TN * C_];
__device__ float  g_hloc[TN * C_];
__device__ float  g_out[TN * C_];
__device__ __half g_out16[TN * C_];
__device__ __half g_qkv16[(size_t)TN * 3 * C_];
__device__ __half g_att16[TN * C_];
__device__ __half g_wt[L_ * 655360];          // transposed fp16 weights, [n][k]
__device__ __half g_projh[L_ * 288 * 64];     // fp16 proj, rows >=266 zero
__device__ __half g_kp[(size_t)H_ * TN * 288];
__device__ __half g_qp[(size_t)H_ * TN * 288];
__device__ float  g_ctx[256 * 80 * 320];      // [bh][d'][m]
__device__ int    g_deg[TN];
__device__ int    g_indptr[TN + 1];
__device__ int    g_cursor[TN];
__device__ int    g_eadj[E_];

// ---------------- helpers ----------------
__device__ __forceinline__ float gelu_exact(float x) {
    return 0.5f * x * (1.0f + erff(x * 0.70710678118654752f));
}
__device__ __forceinline__ uint32_t f2h2(float a, float b) {
    __half2 h = __floats2half2_rn(a, b);
    return *reinterpret_cast<uint32_t*>(&h);
}
__device__ __forceinline__ uint32_t smem_u32(const void* p) {
    uint32_t a;
    asm("{ .reg .u64 t; cvta.to.shared.u64 t, %1; cvt.u32.u64 %0, t; }" : "=r"(a) : "l"(p));
    return a;
}
__device__ __forceinline__ void mma_f16_16x8x16(float* d, const uint32_t* a, const uint32_t* b) {
    asm volatile(
        "mma.sync.aligned.m16n8k16.row.col.f32.f16.f16.f32 "
        "{%0,%1,%2,%3}, {%4,%5,%6,%7}, {%8,%9}, {%0,%1,%2,%3};"
        : "+f"(d[0]), "+f"(d[1]), "+f"(d[2]), "+f"(d[3])
        : "r"(a[0]), "r"(a[1]), "r"(a[2]), "r"(a[3]), "r"(b[0]), "r"(b[1]));
}
__device__ __forceinline__ void ldsm_x4(uint32_t* r, uint32_t saddr) {
    asm volatile("ldmatrix.sync.aligned.m8n8.x4.shared.b16 {%0,%1,%2,%3}, [%4];"
                 : "=r"(r[0]), "=r"(r[1]), "=r"(r[2]), "=r"(r[3]) : "r"(saddr));
}
__device__ __forceinline__ void cp_async16(uint32_t saddr, const void* gptr) {
    asm volatile("cp.async.cg.shared.global [%0], [%1], 16;" :: "r"(saddr), "l"(gptr));
}
#define CP_COMMIT() asm volatile("cp.async.commit_group;" ::: "memory")
#define CP_WAIT0()  asm volatile("cp.async.wait_group 0;" ::: "memory")

// ---------------- weight transpose (once): WT[n*K+k] = half(W[k*N+n]) ----------------
struct WPtrs { const float* p[8]; };

__global__ void transpose_kernel(WPtrs wp) {
    int z = blockIdx.z;
    int t = z & 7, l = z >> 3;
    int K = (t == 7) ? 512 : 256;
    int N = (t == 6) ? 512 : 256;
    int n0 = blockIdx.x * 32, k0 = blockIdx.y * 32;
    if (n0 >= N || k0 >= K) return;
    const float* src = wp.p[t] + ((t >= 6) ? l * 131072 : l * 65536);
    int doff = (t < 6) ? t * 65536 : (t == 6 ? 393216 : 524288);
    __half* dst = g_wt + l * 655360 + doff;
    __shared__ float s[32][33];
    int tx = threadIdx.x, ty = threadIdx.y;
#pragma unroll
    for (int i = 0; i < 4; i++)
        s[ty + 8 * i][tx] = src[(k0 + ty + 8 * i) * N + n0 + tx];
    __syncthreads();
#pragma unroll
    for (int i = 0; i < 4; i++)
        dst[(n0 + ty + 8 * i) * K + k0 + tx] = __float2half_rn(s[tx][ty + 8 * i]);
}

// ---------------- proj -> fp16, padded to 288 rows ----------------
__global__ void proj_prep_kernel(const float* __restrict__ proj) {
    int idx = blockIdx.x * 256 + threadIdx.x;
    if (idx >= L_ * 288 * 64) return;
    int l = idx / (288 * 64);
    int r = idx - l * (288 * 64);
    int m = r >> 6, d = r & 63;
    g_projh[idx] = (m < M_) ? __float2half_rn(proj[(l * M_ + m) * 64 + d]) : __half(0.f);
}

// ---------------- fp16 mma GEMM with ldmatrix + full cp.async ----------------
// A fp16 [row][K], B fp16 [n][K]. Tile 64x256, BK=64 halves, 2-stage.
// smem bytes: A stages @0,9216 ; B stages @18432, 18432+36864.
#define GEMM_SMEM_BYTES (2 * 9216 + 2 * 36864)

template <int GELU>
__global__ void __launch_bounds__(256, 2) mma_gemm(const __half* __restrict__ A,
                                                   const __half* __restrict__ WT,
                                                   const float* __restrict__ bias,
                                                   const float* __restrict__ res,
                                                   float* __restrict__ Out32,
                                                   __half* __restrict__ Out16,
                                                   int K, int Ntot) {
    extern __shared__ uint32_t smw[];
    const int tid = threadIdx.x;
    const int lane = tid & 31, wid = tid >> 5;
    const int g = lane >> 2, t = lane & 3;
    const int wm = (wid & 1) * 32;
    const int wn = (wid >> 1) * 64;
    const int rowbase = blockIdx.x * 64;
    const int colbase = blockIdx.y * 256;
    const uint32_t sb = smem_u32(smw);

    // ldmatrix per-lane base addresses
    const int l7 = lane & 7, l8 = (lane >> 3) & 1, l16 = (lane >> 4) & 1;
    uint32_t aAddr[2], bAddr[4];
#pragma unroll
    for (int mt = 0; mt < 2; mt++)
        aAddr[mt] = sb + (wm + mt * 16 + l7 + l8 * 8) * 144 + l16 * 16;
#pragma unroll
    for (int p = 0; p < 4; p++)
        bAddr[p] = sb + 18432 + (wn + p * 16 + l7 + l16 * 8) * 144 + l8 * 16;

    float acc[2][8][4];
#pragma unroll
    for (int mt = 0; mt < 2; mt++)
#pragma unroll
        for (int nt = 0; nt < 8; nt++)
#pragma unroll
            for (int j = 0; j < 4; j++) acc[mt][nt][j] = 0.0f;

    const int nk = K >> 6;
    // prologue: stage 0
#pragma unroll
    for (int i = 0; i < 2; i++) {
        int idx = tid + i * 256;
        int m = idx >> 3, c = idx & 7;
        cp_async16(sb + m * 144 + c * 16, A + (size_t)(rowbase + m) * K + c * 8);
    }
#pragma unroll
    for (int i = 0; i < 8; i++) {
        int idx = tid + i * 256;
        int n = idx >> 3, c = idx & 7;
        cp_async16(sb + 18432 + n * 144 + c * 16, WT + (size_t)(colbase + n) * K + c * 8);
    }
    CP_COMMIT();
    CP_WAIT0();
    __syncthreads();

    for (int kb = 0; kb < nk; kb++) {
        const int cur = kb & 1;
        const bool nxt = (kb + 1 < nk);
        if (nxt) {
            int k0g = (kb + 1) * 64;
            int sB = cur ^ 1;
#pragma unroll
            for (int i = 0; i < 2; i++) {
                int idx = tid + i * 256;
                int m = idx >> 3, c = idx & 7;
                cp_async16(sb + sB * 9216 + m * 144 + c * 16,
                           A + (size_t)(rowbase + m) * K + k0g + c * 8);
            }
#pragma unroll
            for (int i = 0; i < 8; i++) {
                int idx = tid + i * 256;
                int n = idx >> 3, c = idx & 7;
                cp_async16(sb + 18432 + sB * 36864 + n * 144 + c * 16,
                           WT + (size_t)(colbase + n) * K + k0g + c * 8);
            }
            CP_COMMIT();
        }
        const uint32_t aoff = cur * 9216, boff = cur * 36864;
#pragma unroll
        for (int ks = 0; ks < 4; ks++) {
            uint32_t ar[2][4], br[4][4];
            ldsm_x4(ar[0], aAddr[0] + aoff + ks * 32);
            ldsm_x4(ar[1], aAddr[1] + aoff + ks * 32);
#pragma unroll
            for (int p = 0; p < 4; p++) ldsm_x4(br[p], bAddr[p] + boff + ks * 32);
#pragma unroll
            for (int mt = 0; mt < 2; mt++)
#pragma unroll
                for (int p = 0; p < 4; p++) {
                    mma_f16_16x8x16(acc[mt][2 * p],     ar[mt], &br[p][0]);
                    mma_f16_16x8x16(acc[mt][2 * p + 1], ar[mt], &br[p][2]);
                }
        }
        if (nxt) {
            CP_WAIT0();
            __syncthreads();
        }
    }

    // ---- epilogue ----
#pragma unroll
    for (int mt = 0; mt < 2; mt++) {
        int r0 = rowbase + wm + mt * 16 + g;
#pragma unroll
        for (int nt = 0; nt < 8; nt++) {
            int col = colbase + wn + nt * 8 + 2 * t;
            float b0 = 0.0f, b1 = 0.0f;
            if (bias) { b0 = bias[col]; b1 = bias[col + 1]; }
            float v0 = acc[mt][nt][0] + b0, v1 = acc[mt][nt][1] + b1;
            float v2 = acc[mt][nt][2] + b0, v3 = acc[mt][nt][3] + b1;
            if (GELU) {
                v0 = gelu_exact(v0); v1 = gelu_exact(v1);
                v2 = gelu_exact(v2); v3 = gelu_exact(v3);
            } else if (res) {
                float2 r01 = *reinterpret_cast<const float2*>(&res[(size_t)r0 * 256 + col]);
                float2 r23 = *reinterpret_cast<const float2*>(&res[(size_t)(r0 + 8) * 256 + col]);
                v0 += r01.x; v1 += r01.y; v2 += r23.x; v3 += r23.y;
            }
            if (Out16) {
                *reinterpret_cast<uint32_t*>(&Out16[(size_t)r0 * Ntot + col]) = f2h2(v0, v1);
                *reinterpret_cast<uint32_t*>(&Out16[(size_t)(r0 + 8) * Ntot + col]) = f2h2(v2, v3);
            }
            if (Out32) {
                *reinterpret_cast<float2*>(&Out32[(size_t)r0 * Ntot + col]) = make_float2(v0, v1);
                *reinterpret_cast<float2*>(&Out32[(size_t)(r0 + 8) * Ntot + col]) = make_float2(v2, v3);
            }
        }
    }
}

// ---------------- Performer stage 1: kp/qp = relu(X_h @ projT)+eps, fp16 ----------------
#define S1_SMEM_BYTES ((2304 + 10368) * 4)

__global__ void __launch_bounds__(256) phi_kernel(const __half* __restrict__ QKV,
                                                  const __half* __restrict__ projh_l,
                                                  __half* __restrict__ KP,
                                                  __half* __restrict__ QP) {
    extern __shared__ uint32_t sw[];
    uint32_t* As = sw;           // 64 x 36 words
    uint32_t* Bs = sw + 2304;    // 288 x 36 words
    const int tid = threadIdx.x;
    const int lane = tid & 31, wid = tid >> 5;
    const int g = lane >> 2, t = lane & 3;
    const int wm = (wid & 1) * 32;
    const int wn = (wid >> 1) * 72;
    const int rowbase = blockIdx.x * 64;
    const int h = blockIdx.y & 3;
    const int isq = blockIdx.y >> 2;
    const __half* Ah = QKV + (isq ? h * 64 : 256 + h * 64);
    __half* outp = (isq ? QP : KP) + (size_t)h * TN * 288;
    const uint32_t sbA = smem_u32(As);

#pragma unroll
    for (int i = 0; i < 2; i++) {
        int idx = tid + i * 256;
        int m = idx >> 3, c = idx & 7;
        cp_async16(sbA + m * 144 + c * 16, Ah + (size_t)(rowbase + m) * 768 + c * 8);
    }
    CP_COMMIT();
    const uint32_t* pb = (const uint32_t*)projh_l;
#pragma unroll
    for (int i = 0; i < 36; i++) {
        int w = tid + i * 256;
        Bs[(w >> 5) * 36 + (w & 31)] = pb[w];
    }
    CP_WAIT0();
    __syncthreads();

    float acc[2][9][4];
#pragma unroll
    for (int mt = 0; mt < 2; mt++)
#pragma unroll
        for (int nt = 0; nt < 9; nt++)
#pragma unroll
            for (int j = 0; j < 4; j++) acc[mt][nt][j] = 0.0f;

#pragma unroll
    for (int ks = 0; ks < 4; ks++) {
        int k0 = ks * 8;
        uint32_t af[2][4], bf[9][2];
#pragma unroll
        for (int mt = 0; mt < 2; mt++) {
            int r0 = wm + mt * 16 + g;
            af[mt][0] = As[r0 * 36 + k0 + t];
            af[mt][1] = As[(r0 + 8) * 36 + k0 + t];
            af[mt][2] = As[r0 * 36 + k0 + t + 4];
            af[mt][3] = As[(r0 + 8) * 36 + k0 + t + 4];
        }
#pragma unroll
        for (int nt = 0; nt < 9; nt++) {
            int n0 = wn + nt * 8 + g;
            bf[nt][0] = Bs[n0 * 36 + k0 + t];
            bf[nt][1] = Bs[n0 * 36 + k0 + t + 4];
        }
#pragma unroll
        for (int mt = 0; mt < 2; mt++)
#pragma unroll
            for (int nt = 0; nt < 9; nt++)
                mma_f16_16x8x16(acc[mt][nt], af[mt], bf[nt]);
    }

#pragma unroll
    for (int mt = 0; mt < 2; mt++) {
        int r = rowbase + wm + mt * 16 + g;
#pragma unroll
        for (int nt = 0; nt < 9; nt++) {
            int c0 = wn + nt * 8 + 2 * t;
            float v0 = fmaxf(acc[mt][nt][0], 0.0f) + 1e-3f;
            float v1 = fmaxf(acc[mt][nt][1], 0.0f) + 1e-3f;
            float v2 = fmaxf(acc[mt][nt][2], 0.0f) + 1e-3f;
            float v3 = fmaxf(acc[mt][nt][3], 0.0f) + 1e-3f;
            if (c0 >= M_) { v0 = 0.0f; v2 = 0.0f; }
            if (c0 + 1 >= M_) { v1 = 0.0f; v3 = 0.0f; }
            *reinterpret_cast<uint32_t*>(&outp[(size_t)r * 288 + c0]) = f2h2(v0, v1);
            *reinterpret_cast<uint32_t*>(&outp[(size_t)(r + 8) * 288 + c0]) = f2h2(v2, v3);
        }
    }
}

// ---------------- Performer stage 2: ctx[m,d'] = sum_n kp[n,m] * V'[n,d'] ----------------
#define S2_SMEM_BYTES ((11520 + 2880) * 4)

__global__ void __launch_bounds__(256) ctx_kernel(const __half* __restrict__ KP,
                                                  const __half* __restrict__ QKV,
                                                  float* __restrict__ CTX) {
    extern __shared__ uint32_t sw[];
    uint32_t* kpT = sw;                   // 320 x 36 words ([m][n])
    uint32_t* vsb = sw + 11520;           // 80 x 36 words ([d'][n])
    __half* kpT_h = (__half*)kpT;
    __half* vs_h = (__half*)vsb;
    const int tid = threadIdx.x;
    const int lane = tid & 31, wid = tid >> 5;
    const int g = lane >> 2, t = lane & 3;
    const int wm = (wid & 3) * 80;
    const int wn = (wid >> 2) * 40;
    const int bh = blockIdx.x;
    const int b = bh >> 2, h = bh & 3;

    for (int i = tid; i < 32 * 72; i += 256)
        kpT_h[(288 + i / 72) * 72 + (i % 72)] = __float2half(0.0f);
    for (int i = tid; i < 16 * 72; i += 256) {
        int d = 64 + i / 72, n = i % 72;
        vs_h[d * 72 + n] = __float2half((d == 64 && n < 64) ? 1.0f : 0.0f);
    }

    float acc[5][5][4];
#pragma unroll
    for (int mt = 0; mt < 5; mt++)
#pragma unroll
        for (int nt = 0; nt < 5; nt++)
#pragma unroll
            for (int j = 0; j < 4; j++) acc[mt][nt][j] = 0.0f;

    const uint32_t* kp2 = (const uint32_t*)(KP + (size_t)h * TN * 288);

    for (int c = 0; c < 8; c++) {
        __syncthreads();
        int base = b * 512 + c * 64;
#pragma unroll
        for (int i = 0; i < 36; i++) {
            int idx = tid + i * 256;
            int n = idx / 144, m2 = idx - n * 144;
            uint32_t w = kp2[(size_t)(base + n) * 144 + m2];
            __half2 hh = *reinterpret_cast<const __half2*>(&w);
            kpT_h[(2 * m2) * 72 + n] = __low2half(hh);
            kpT_h[(2 * m2 + 1) * 72 + n] = __high2half(hh);
        }
#pragma unroll
        for (int i = 0; i < 16; i++) {
            int idx = tid + i * 256;
            int n = idx >> 6, d = idx & 63;
            vs_h[d * 72 + n] = QKV[(size_t)(base + n) * 768 + 512 + h * 64 + d];
        }
        __syncthreads();
#pragma unroll
        for (int ks = 0; ks < 4; ks++) {
            int k0 = ks * 8;
            uint32_t af[5][4], bf[5][2];
#pragma unroll
            for (int mt = 0; mt < 5; mt++) {
                int r0 = wm + mt * 16 + g;
                af[mt][0] = kpT[r0 * 36 + k0 + t];
                af[mt][1] = kpT[(r0 + 8) * 36 + k0 + t];
                af[mt][2] = kpT[r0 * 36 + k0 + t + 4];
                af[mt][3] = kpT[(r0 + 8) * 36 + k0 + t + 4];
            }
#pragma unroll
            for (int nt = 0; nt < 5; nt++) {
                int n0 = wn + nt * 8 + g;
                bf[nt][0] = vsb[n0 * 36 + k0 + t];
                bf[nt][1] = vsb[n0 * 36 + k0 + t + 4];
            }
#pragma unroll
            for (int mt = 0; mt < 5; mt++)
#pragma unroll
                for (int nt = 0; nt < 5; nt++)
                    mma_f16_16x8x16(acc[mt][nt], af[mt], bf[nt]);
        }
    }

    float* outc = CTX + (size_t)bh * 80 * 320;
#pragma unroll
    for (int mt = 0; mt < 5; mt++) {
        int m0 = wm + mt * 16 + g;
#pragma unroll
        for (int nt = 0; nt < 5; nt++) {
            int c0 = wn + nt * 8 + 2 * t;
            outc[(size_t)c0 * 320 + m0] = acc[mt][nt][0];
            outc[(size_t)(c0 + 1) * 320 + m0] = acc[mt][nt][1];
            outc[(size_t)c0 * 320 + m0 + 8] = acc[mt][nt][2];
            outc[(size_t)(c0 + 1) * 320 + m0 + 8] = acc[mt][nt][3];
        }
    }
}

// ---------------- Performer stage 3: att' = qp @ ctx ; normalize; write fp16 ----------------
#define S3_W_CTX (80 * 164)
#define S3_W_AS  (64 * 148)
#define S3_W_ATT (64 * 80)
#define S3_SMEM_BYTES ((S3_W_CTX + S3_W_AS + S3_W_ATT) * 4)

__global__ void __launch_bounds__(256) att_kernel(const __half* __restrict__ QP,
                                                  const float* __restrict__ CTX,
                                                  __half* __restrict__ Att) {
    extern __shared__ uint32_t sw[];
    uint32_t* ctxT = sw;                              // 80 x 164 words
    uint32_t* As = sw + S3_W_CTX;                     // 64 x 148 words
    float* att_s = (float*)(sw + S3_W_CTX + S3_W_AS); // 64 x 80
    const int tid = threadIdx.x;
    const int lane = tid & 31, wid = tid >> 5;
    const int g = lane >> 2, t = lane & 3;
    const int wm = (wid & 3) * 16;
    const int wn = (wid >> 2) * 40;
    const int cta = blockIdx.x;
    const int bh = cta >> 1, half = cta & 1;
    const int b = bh >> 2, h = bh & 3;

    const float* cg = CTX + (size_t)bh * 80 * 320;
#pragma unroll
    for (int i = 0; i < 50; i++) {
        int idx = tid + i * 256;
        int d = idx / 160, m2 = idx - d * 160;
        float2 v = *reinterpret_cast<const float2*>(&cg[(size_t)d * 320 + m2 * 2]);
        ctxT[d * 164 + m2] = f2h2(v.x, v.y);
    }
    const uint32_t* qp2 = (const uint32_t*)(QP + (size_t)h * TN * 288);
    const int rowg0 = b * 512 + half * 256;

    for (int ch = 0; ch < 4; ch++) {
        __syncthreads();
        int rbase = rowg0 + ch * 64;
#pragma unroll
        for (int i = 0; i < 36; i++) {
            int idx = tid + i * 256;
            int n = idx / 144, m2 = idx - n * 144;
            As[n * 148 + m2] = qp2[(size_t)(rbase + n) * 144 + m2];
        }
        __syncthreads();
        float acc[5][4];
#pragma unroll
        for (int nt = 0; nt < 5; nt++)
#pragma unroll
            for (int j = 0; j < 4; j++) acc[nt][j] = 0.0f;
#pragma unroll
        for (int ks = 0; ks < 17; ks++) {
            int k0 = ks * 8;
            uint32_t af[4], bf[5][2];
            int r0 = wm + g;
            af[0] = As[r0 * 148 + k0 + t];
            af[1] = As[(r0 + 8) * 148 + k0 + t];
            af[2] = As[r0 * 148 + k0 + t + 4];
            af[3] = As[(r0 + 8) * 148 + k0 + t + 4];
#pragma unroll
            for (int nt = 0; nt < 5; nt++) {
                int n0 = wn + nt * 8 + g;
                bf[nt][0] = ctxT[n0 * 164 + k0 + t];
                bf[nt][1] = ctxT[n0 * 164 + k0 + t + 4];
            }
#pragma unroll
            for (int nt = 0; nt < 5; nt++)
                mma_f16_16x8x16(acc[nt], af, bf[nt]);
        }
#pragma unroll
        for (int nt = 0; nt < 5; nt++) {
            int c0 = wn + nt * 8 + 2 * t;
            att_s[(wm + g) * 80 + c0] = acc[nt][0];
            att_s[(wm + g) * 80 + c0 + 1] = acc[nt][1];
            att_s[(wm + g + 8) * 80 + c0] = acc[nt][2];
            att_s[(wm + g + 8) * 80 + c0 + 1] = acc[nt][3];
        }
        __syncthreads();
#pragma unroll
        for (int i = 0; i < 16; i++) {
            int idx = tid + i * 256;
            int n = idx >> 6, d = idx & 63;
            float den = att_s[n * 80 + 64];
            Att[(size_t)(rbase + n) * 256 + h * 64 + d] = __float2half_rn(att_s[n * 80 + d] / den);
        }
    }
}

// ---------------- LayerNorm (dual fp32/fp16 out) ----------------
__global__ void __launch_bounds__(256) ln_kernel(const float* __restrict__ a,
                                                 const float* __restrict__ lng,
                                                 const float* __restrict__ lnb,
                                                 const float* __restrict__ add2,
                                                 float* __restrict__ out,
                                                 __half* __restrict__ out16) {
    int row = blockIdx.x * 8 + (threadIdx.x >> 5);
    int lane = threadIdx.x & 31;
    const float* ar = a + (size_t)row * 256 + lane * 8;
    float4 v0 = *reinterpret_cast<const float4*>(ar);
    float4 v1 = *reinterpret_cast<const float4*>(ar + 4);
    float s1 = v0.x + v0.y + v0.z + v0.w + v1.x + v1.y + v1.z + v1.w;
    float s2 = v0.x * v0.x + v0.y * v0.y + v0.z * v0.z + v0.w * v0.w
             + v1.x * v1.x + v1.y * v1.y + v1.z * v1.z + v1.w * v1.w;
#pragma unroll
    for (int off = 16; off > 0; off >>= 1) {
        s1 += __shfl_xor_sync(0xffffffffu, s1, off);
        s2 += __shfl_xor_sync(0xffffffffu, s2, off);
    }
    float mean = s1 * (1.0f / 256.0f);
    float var = s2 * (1.0f / 256.0f) - mean * mean;
    float rstd = rsqrtf(var + 1e-5f);
    float4 g0 = *reinterpret_cast<const float4*>(&lng[lane * 8]);
    float4 g1 = *reinterpret_cast<const float4*>(&lng[lane * 8 + 4]);
    float4 b0 = *reinterpret_cast<const float4*>(&lnb[lane * 8]);
    float4 b1 = *reinterpret_cast<const float4*>(&lnb[lane * 8 + 4]);
    float4 o0, o1;
    o0.x = (v0.x - mean) * rstd * g0.x + b0.x;
    o0.y = (v0.y - mean) * rstd * g0.y + b0.y;
    o0.z = (v0.z - mean) * rstd * g0.z + b0.z;
    o0.w = (v0.w - mean) * rstd * g0.w + b0.w;
    o1.x = (v1.x - mean) * rstd * g1.x + b1.x;
    o1.y = (v1.y - mean) * rstd * g1.y + b1.y;
    o1.z = (v1.z - mean) * rstd * g1.z + b1.z;
    o1.w = (v1.w - mean) * rstd * g1.w + b1.w;
    if (add2) {
        const float* a2 = add2 + (size_t)row * 256 + lane * 8;
        float4 x0 = *reinterpret_cast<const float4*>(a2);
        float4 x1 = *reinterpret_cast<const float4*>(a2 + 4);
        o0.x += x0.x; o0.y += x0.y; o0.z += x0.z; o0.w += x0.w;
        o1.x += x1.x; o1.y += x1.y; o1.z += x1.z; o1.w += x1.w;
    }
    float* orow = out + (size_t)row * 256 + lane * 8;
    *reinterpret_cast<float4*>(orow) = o0;
    *reinterpret_cast<float4*>(orow + 4) = o1;
    if (out16) {
        uint4 h;
        h.x = f2h2(o0.x, o0.y); h.y = f2h2(o0.z, o0.w);
        h.z = f2h2(o1.x, o1.y); h.w = f2h2(o1.z, o1.w);
        *reinterpret_cast<uint4*>(&out16[(size_t)row * 256 + lane * 8]) = h;
    }
}

// ---------------- node embedding ----------------
__global__ void node_embed_kernel(const float* __restrict__ x,
                                  const float* __restrict__ w,
                                  const float* __restrict__ b) {
    __shared__ float lx[11];
    int row = blockIdx.x;
    int t = threadIdx.x;
    if (t < 11) lx[t] = log1pf(x[row * 11 + t]);
    __syncthreads();
    float s = b[t];
#pragma unroll
    for (int j = 0; j < 11; j++) s += lx[j] * w[j * C_ + t];
    g_atoms[row * C_ + t] = s;
    g_atoms16[row * C_ + t] = __float2half_rn(s);
}

// ---------------- CSR build ----------------
__global__ void count_deg_kernel(const int* __restrict__ dst) {
    int e = blockIdx.x * blockDim.x + threadIdx.x;
    if (e < E_) atomicAdd(&g_deg[dst[e]], 1);
}
__global__ void scan_deg_kernel() {
    __shared__ int sh[1024];
    __shared__ int carry;
    int t = threadIdx.x;
    if (t == 0) carry = 0;
    __syncthreads();
    for (int base = 0; base < TN; base += 1024) {
        int v = g_deg[base + t];
        sh[t] = v;
        __syncthreads();
        for (int off = 1; off < 1024; off <<= 1) {
            int add = (t >= off) ? sh[t - off] : 0;
            __syncthreads();
            sh[t] += add;
            __syncthreads();
        }
        int ip = carry + sh[t] - v;
        g_indptr[base + t] = ip;
        g_cursor[base + t] = ip;
        __syncthreads();
        if (t == 0) carry += sh[1023];
        __syncthreads();
    }
    if (t == 0) g_indptr[TN] = carry;
}
__global__ void fill_adj_kernel(const int* __restrict__ dst) {
    int e = blockIdx.x * blockDim.x + threadIdx.x;
    if (e < E_) {
        int p = atomicAdd(&g_cursor[dst[e]], 1);
        g_eadj[p] = e;
    }
}

// ---------------- GINE aggregation (fp16 gather, fp16 out) ----------------
__global__ void __launch_bounds__(256) gine_kernel(const int* __restrict__ src,
                                                   const float* __restrict__ eattr,
                                                   const float* __restrict__ ew,
                                                   const float* __restrict__ eb) {
    __shared__ float sew[4][C_];
    __shared__ float seb[C_];
    int tid = threadIdx.x;
    for (int i = tid; i < 4 * C_; i += 256) sew[i >> 8][i & 255] = ew[i];
    seb[tid] = eb[tid];
    __syncthreads();
    int warp = tid >> 5, lane = tid & 31;
    int v = blockIdx.x * 8 + warp;
    float acc[8];
#pragma unroll
    for (int k = 0; k < 8; k++) acc[k] = g_atoms[v * C_ + lane + 32 * k];
    int p0 = g_indptr[v], p1 = g_indptr[v + 1];
    for (int p = p0; p < p1; p++) {
        int e = g_eadj[p];
        int s = src[e];
        float4 ea4 = *reinterpret_cast<const float4*>(&eattr[e * 4]);
        const __half* arow = &g_atoms16[s * C_];
#pragma unroll
        for (int k = 0; k < 8; k++) {
            int c = lane + 32 * k;
            float eac = seb[c] + ea4.x * sew[0][c] + ea4.y * sew[1][c]
                               + ea4.z * sew[2][c] + ea4.w * sew[3][c];
            acc[k] += fmaxf(__half2float(arow[c]) + eac, 0.0f);
        }
    }
#pragma unroll
    for (int k = 0; k < 8; k++)
        g_h016[v * C_ + lane + 32 * k] = __float2half_rn(acc[k]);
}

// ---------------- final mean pool ----------------
__global__ void pool_kernel(float* __restrict__ out) {
    int b = blockIdx.x;
    int cix = threadIdx.x;
    float s = 0.0f;
    for (int n = 0; n < N_; n++) s += g_atoms[(b * N_ + n) * C_ + cix];
    out[b * C_ + cix] = s * (1.0f / (float)N_);
}

// ---------------- host launcher ----------------
extern "C" void kernel_launch(void* const* d_in, const int* in_sizes, int n_in,
                              void* d_out, int out_size) {
    const float* x      = (const float*)d_in[0];
    const float* eattr  = (const float*)d_in[1];
    const int*   eidx   = (const int*)d_in[2];
    const float* node_w = (const float*)d_in[4];
    const float* node_b = (const float*)d_in[5];
    const float* edge_w = (const float*)d_in[6];
    const float* edge_b = (const float*)d_in[7];
    const float* gw1    = (const float*)d_in[8];
    const float* gb1    = (const float*)d_in[9];
    const float* gw2    = (const float*)d_in[10];
    const float* gb2    = (const float*)d_in[11];
    const float* qw     = (const float*)d_in[12];
    const float* kw     = (const float*)d_in[13];
    const float* vw     = (const float*)d_in[14];
    const float* ow     = (const float*)d_in[15];
    const float* ob     = (const float*)d_in[16];
    const float* proj   = (const float*)d_in[17];
    const float* n1g    = (const float*)d_in[18];
    const float* n1b    = (const float*)d_in[19];
    const float* n2g    = (const float*)d_in[20];
    const float* n2b    = (const float*)d_in[21];
    const float* n3g    = (const float*)d_in[22];
    const float* n3b    = (const float*)d_in[23];
    const float* mw1    = (const float*)d_in[24];
    const float* mb1    = (const float*)d_in[25];
    const float* mw2    = (const float*)d_in[26];
    const float* mb2    = (const float*)d_in[27];

    const int* src = eidx;
    const int* dst = eidx + E_;

    float *p_atoms, *p_t2, *p_hloc, *p_out, *p_ctx;
    __half *p_atoms16, *p_h016, *p_t116, *p_out16, *p_qkv16, *p_att16;
    __half *p_wt, *p_projh, *p_kp, *p_qp;
    int* p_deg;
    cudaGetSymbolAddress((void**)&p_atoms,   g_atoms);
    cudaGetSymbolAddress((void**)&p_atoms16, g_atoms16);
    cudaGetSymbolAddress((void**)&p_h016,    g_h016);
    cudaGetSymbolAddress((void**)&p_t116,    g_t116);
    cudaGetSymbolAddress((void**)&p_t2,      g_t2);
    cudaGetSymbolAddress((void**)&p_hloc,    g_hloc);
    cudaGetSymbolAddress((void**)&p_out,     g_out);
    cudaGetSymbolAddress((void**)&p_out16,   g_out16);
    cudaGetSymbolAddress((void**)&p_qkv16,   g_qkv16);
    cudaGetSymbolAddress((void**)&p_att16,   g_att16);
    cudaGetSymbolAddress((void**)&p_ctx,     g_ctx);
    cudaGetSymbolAddress((void**)&p_wt,      g_wt);
    cudaGetSymbolAddress((void**)&p_projh,   g_projh);
    cudaGetSymbolAddress((void**)&p_kp,      g_kp);
    cudaGetSymbolAddress((void**)&p_qp,      g_qp);
    cudaGetSymbolAddress((void**)&p_deg,     g_deg);

    cudaFuncSetAttribute(mma_gemm<0>, cudaFuncAttributeMaxDynamicSharedMemorySize, GEMM_SMEM_BYTES);
    cudaFuncSetAttribute(mma_gemm<1>, cudaFuncAttributeMaxDynamicSharedMemorySize, GEMM_SMEM_BYTES);
    cudaFuncSetAttribute(phi_kernel, cudaFuncAttributeMaxDynamicSharedMemorySize, S1_SMEM_BYTES);
    cudaFuncSetAttribute(ctx_kernel, cudaFuncAttributeMaxDynamicSharedMemorySize, S2_SMEM_BYTES);
    cudaFuncSetAttribute(att_kernel, cudaFuncAttributeMaxDynamicSharedMemorySize, S3_SMEM_BYTES);

    WPtrs wp;
    wp.p[0] = gw1; wp.p[1] = gw2; wp.p[2] = qw; wp.p[3] = kw;
    wp.p[4] = vw;  wp.p[5] = ow;  wp.p[6] = mw1; wp.p[7] = mw2;
    transpose_kernel<<<dim3(16, 16, 40), dim3(32, 8)>>>(wp);                  // 1
    proj_prep_kernel<<<(L_ * 288 * 64 + 255) / 256, 256>>>(proj);             // 2
    node_embed_kernel<<<TN, 256>>>(x, node_w, node_b);                        // 3

    dim3 g1(TN / 64, 1), g2(TN / 64, 2), g3(TN / 64, 3);
    bool csr_built = false;

    for (int l = 0; l < L_; l++) {
        const __half* wt_l = p_wt + l * 655360;
        // QKV (fused, N=768, fp16 out) — first mma_gemm is kernel #4 for ncu
        mma_gemm<0><<<g3, 256, GEMM_SMEM_BYTES>>>(p_atoms16, wt_l + 131072, nullptr, nullptr,
                                                  nullptr, p_qkv16, 256, 768);
        // Performer (3 mma stages)
        phi_kernel<<<dim3(512, 8), 256, S1_SMEM_BYTES>>>(p_qkv16, p_projh + l * 288 * 64, p_kp, p_qp);
        ctx_kernel<<<256, 256, S2_SMEM_BYTES>>>(p_kp, p_qkv16, p_ctx);
        att_kernel<<<512, 256, S3_SMEM_BYTES>>>(p_qp, p_ctx, p_att16);
        // CSR build (once)
        if (!csr_built) {
            cudaMemsetAsync(p_deg, 0, TN * sizeof(int));
            count_deg_kernel<<<E_ / 256, 256>>>(dst);
            scan_deg_kernel<<<1, 1024>>>();
            fill_adj_kernel<<<E_ / 256, 256>>>(dst);
            csr_built = true;
        }
        // GINE conv
        gine_kernel<<<TN / 8, 256>>>(src, eattr, edge_w, edge_b);
        mma_gemm<1><<<g1, 256, GEMM_SMEM_BYTES>>>(p_h016, wt_l + 0, gb1 + l * C_, nullptr,
                                                  nullptr, p_t116, 256, 256);
        mma_gemm<0><<<g1, 256, GEMM_SMEM_BYTES>>>(p_t116, wt_l + 65536, gb2 + l * C_, p_atoms,
                                                  p_t2, nullptr, 256, 256);
        ln_kernel<<<TN / 8, 256>>>(p_t2, n1g + l * C_, n1b + l * C_, nullptr, p_hloc, nullptr);
        // O-proj + LN + combine
        mma_gemm<0><<<g1, 256, GEMM_SMEM_BYTES>>>(p_att16, wt_l + 327680, ob + l * C_, p_atoms,
                                                  p_t2, nullptr, 256, 256);
        ln_kernel<<<TN / 8, 256>>>(p_t2, n2g + l * C_, n2b + l * C_, p_hloc, p_out, p_out16);
        // FFN
        mma_gemm<1><<<g2, 256, GEMM_SMEM_BYTES>>>(p_out16, wt_l + 393216, mb1 + l * 2 * C_, nullptr,
                                                  nullptr, p_t116, 256, 512);
        mma_gemm<0><<<g1, 256, GEMM_SMEM_BYTES>>>(p_t116, wt_l + 524288, mb2 + l * C_, p_out,
                                                  p_t2, nullptr, 512, 256);
        ln_kernel<<<TN / 8, 256>>>(p_t2, n3g + l * C_, n3b + l * C_, nullptr, p_atoms, p_atoms16);
    }
    pool_kernel<<<B_, 256>>>((float*)d_out);
}

// round 10
// speedup vs baseline: 4.9646x; 1.0633x over previous
#include <cuda_runtime.h>
#include <cuda_fp16.h>
#include <math.h>
#include <stdint.h>

#define TN   32768
#define C_   256
#define B_   64
#define N_   512
#define H_   4
#define DH_  64
#define M_   266
#define E_   524288
#define L_   5

// ---------------- scratch ----------------
__device__ float  g_atoms[TN * C_];
__device__ __half g_atoms16[TN * C_];
__device__ __half g_h016[TN * C_];
__device__ __half g_t116[TN * 2 * C_];
__device__ float  g_hloc[TN * C_];
__device__ float  g_out[TN * C_];
__device__ __half g_out16[TN * C_];
__device__ __half g_qkv16[(size_t)TN * 3 * C_];
__device__ __half g_att16[TN * C_];
__device__ __half g_wt[L_ * 655360];          // transposed fp16 weights, [n][k]
__device__ __half g_projh[L_ * 288 * 64];     // fp16 proj, rows >=266 zero
__device__ __half g_kp[(size_t)H_ * TN * 288];
__device__ __half g_qp[(size_t)H_ * TN * 288];
__device__ float  g_ctx[2 * 256 * 80 * 320];  // [part][bh][d'][m]
__device__ int    g_deg[TN];
__device__ int    g_indptr[TN + 1];
__device__ int    g_cursor[TN];
__device__ int    g_eadj[E_];

// ---------------- helpers ----------------
__device__ __forceinline__ float gelu_exact(float x) {
    return 0.5f * x * (1.0f + erff(x * 0.70710678118654752f));
}
__device__ __forceinline__ uint32_t f2h2(float a, float b) {
    __half2 h = __floats2half2_rn(a, b);
    return *reinterpret_cast<uint32_t*>(&h);
}
__device__ __forceinline__ uint32_t smem_u32(const void* p) {
    uint32_t a;
    asm("{ .reg .u64 t; cvta.to.shared.u64 t, %1; cvt.u32.u64 %0, t; }" : "=r"(a) : "l"(p));
    return a;
}
__device__ __forceinline__ void mma_f16_16x8x16(float* d, const uint32_t* a, const uint32_t* b) {
    asm volatile(
        "mma.sync.aligned.m16n8k16.row.col.f32.f16.f16.f32 "
        "{%0,%1,%2,%3}, {%4,%5,%6,%7}, {%8,%9}, {%0,%1,%2,%3};"
        : "+f"(d[0]), "+f"(d[1]), "+f"(d[2]), "+f"(d[3])
        : "r"(a[0]), "r"(a[1]), "r"(a[2]), "r"(a[3]), "r"(b[0]), "r"(b[1]));
}
__device__ __forceinline__ void ldsm_x4(uint32_t* r, uint32_t saddr) {
    asm volatile("ldmatrix.sync.aligned.m8n8.x4.shared.b16 {%0,%1,%2,%3}, [%4];"
                 : "=r"(r[0]), "=r"(r[1]), "=r"(r[2]), "=r"(r[3]) : "r"(saddr));
}
__device__ __forceinline__ void cp_async16(uint32_t saddr, const void* gptr) {
    asm volatile("cp.async.cg.shared.global [%0], [%1], 16;" :: "r"(saddr), "l"(gptr));
}
#define CP_COMMIT() asm volatile("cp.async.commit_group;" ::: "memory")
#define CP_WAIT0()  asm volatile("cp.async.wait_group 0;" ::: "memory")

// ---------------- weight transpose (once): WT[n*K+k] = half(W[k*N+n]) ----------------
struct WPtrs { const float* p[8]; };

__global__ void transpose_kernel(WPtrs wp) {
    int z = blockIdx.z;
    int t = z & 7, l = z >> 3;
    int K = (t == 7) ? 512 : 256;
    int N = (t == 6) ? 512 : 256;
    int n0 = blockIdx.x * 32, k0 = blockIdx.y * 32;
    if (n0 >= N || k0 >= K) return;
    const float* src = wp.p[t] + ((t >= 6) ? l * 131072 : l * 65536);
    int doff = (t < 6) ? t * 65536 : (t == 6 ? 393216 : 524288);
    __half* dst = g_wt + l * 655360 + doff;
    __shared__ float s[32][33];
    int tx = threadIdx.x, ty = threadIdx.y;
#pragma unroll
    for (int i = 0; i < 4; i++)
        s[ty + 8 * i][tx] = src[(k0 + ty + 8 * i) * N + n0 + tx];
    __syncthreads();
#pragma unroll
    for (int i = 0; i < 4; i++)
        dst[(n0 + ty + 8 * i) * K + k0 + tx] = __float2half_rn(s[tx][ty + 8 * i]);
}

// ---------------- proj -> fp16, padded to 288 rows ----------------
__global__ void proj_prep_kernel(const float* __restrict__ proj) {
    int idx = blockIdx.x * 256 + threadIdx.x;
    if (idx >= L_ * 288 * 64) return;
    int l = idx / (288 * 64);
    int r = idx - l * (288 * 64);
    int m = r >> 6, d = r & 63;
    g_projh[idx] = (m < M_) ? __float2half_rn(proj[(l * M_ + m) * 64 + d]) : __half(0.f);
}

// ---------------- fp16 mma GEMM, ldmatrix + cp.async, fused LN epilogue ----------------
// MODE 0: +bias -> out16            MODE 1: gelu(+bias) -> out16
// MODE 2: LN(+bias+res) (+add2) -> out32 (+out16)      [Ntot==256, grid.y==1]
#define GEMM_SMEM_MAIN  (2 * 9216 + 2 * 36864)
#define GEMM_SMEM_BYTES (GEMM_SMEM_MAIN + 512)

template <int MODE, int NK>
__global__ void __launch_bounds__(256, 2) mma_gemm(const __half* __restrict__ A,
                                                   const __half* __restrict__ WT,
                                                   const float* __restrict__ bias,
                                                   const float* __restrict__ res,
                                                   const float* __restrict__ add2,
                                                   const float* __restrict__ lng,
                                                   const float* __restrict__ lnb,
                                                   float* __restrict__ Out32,
                                                   __half* __restrict__ Out16,
                                                   int Ntot) {
    extern __shared__ uint32_t smw[];
    const int K = NK * 64;
    const int tid = threadIdx.x;
    const int lane = tid & 31, wid = tid >> 5;
    const int g = lane >> 2, t = lane & 3;
    const int wm = (wid & 1) * 32;
    const int wn = (wid >> 1) * 64;
    const int rowbase = blockIdx.x * 64;
    const int colbase = blockIdx.y * 256;
    const uint32_t sb = smem_u32(smw);

    const int l7 = lane & 7, l8 = (lane >> 3) & 1, l16 = (lane >> 4) & 1;
    uint32_t aAddr[2], bAddr[4];
#pragma unroll
    for (int mt = 0; mt < 2; mt++)
        aAddr[mt] = sb + (wm + mt * 16 + l7 + l8 * 8) * 144 + l16 * 16;
#pragma unroll
    for (int p = 0; p < 4; p++)
        bAddr[p] = sb + 18432 + (wn + p * 16 + l7 + l16 * 8) * 144 + l8 * 16;

    float acc[2][8][4];
#pragma unroll
    for (int mt = 0; mt < 2; mt++)
#pragma unroll
        for (int nt = 0; nt < 8; nt++)
#pragma unroll
            for (int j = 0; j < 4; j++) acc[mt][nt][j] = 0.0f;

    // prologue: stage 0
#pragma unroll
    for (int i = 0; i < 2; i++) {
        int idx = tid + i * 256;
        int m = idx >> 3, c = idx & 7;
        cp_async16(sb + m * 144 + c * 16, A + (size_t)(rowbase + m) * K + c * 8);
    }
#pragma unroll
    for (int i = 0; i < 8; i++) {
        int idx = tid + i * 256;
        int n = idx >> 3, c = idx & 7;
        cp_async16(sb + 18432 + n * 144 + c * 16, WT + (size_t)(colbase + n) * K + c * 8);
    }
    CP_COMMIT();
    CP_WAIT0();
    __syncthreads();

#pragma unroll
    for (int kb = 0; kb < NK; kb++) {
        const int cur = kb & 1;
        const bool nxt = (kb + 1 < NK);
        if (nxt) {
            int k0g = (kb + 1) * 64;
            int sB = cur ^ 1;
#pragma unroll
            for (int i = 0; i < 2; i++) {
                int idx = tid + i * 256;
                int m = idx >> 3, c = idx & 7;
                cp_async16(sb + sB * 9216 + m * 144 + c * 16,
                           A + (size_t)(rowbase + m) * K + k0g + c * 8);
            }
#pragma unroll
            for (int i = 0; i < 8; i++) {
                int idx = tid + i * 256;
                int n = idx >> 3, c = idx & 7;
                cp_async16(sb + 18432 + sB * 36864 + n * 144 + c * 16,
                           WT + (size_t)(colbase + n) * K + k0g + c * 8);
            }
            CP_COMMIT();
        }
        const uint32_t aoff = cur * 9216, boff = cur * 36864;
#pragma unroll
        for (int ks = 0; ks < 4; ks++) {
            uint32_t ar[2][4], br[4][4];
            ldsm_x4(ar[0], aAddr[0] + aoff + ks * 32);
            ldsm_x4(ar[1], aAddr[1] + aoff + ks * 32);
#pragma unroll
            for (int p = 0; p < 4; p++) ldsm_x4(br[p], bAddr[p] + boff + ks * 32);
#pragma unroll
            for (int mt = 0; mt < 2; mt++)
#pragma unroll
                for (int p = 0; p < 4; p++) {
                    mma_f16_16x8x16(acc[mt][2 * p],     ar[mt], &br[p][0]);
                    mma_f16_16x8x16(acc[mt][2 * p + 1], ar[mt], &br[p][2]);
                }
        }
        if (nxt) {
            CP_WAIT0();
            __syncthreads();
        }
    }

    if (MODE <= 1) {
#pragma unroll
        for (int mt = 0; mt < 2; mt++) {
            int r0 = rowbase + wm + mt * 16 + g;
#pragma unroll
            for (int nt = 0; nt < 8; nt++) {
                int col = colbase + wn + nt * 8 + 2 * t;
                float b0 = 0.0f, b1 = 0.0f;
                if (bias) { b0 = bias[col]; b1 = bias[col + 1]; }
                float v0 = acc[mt][nt][0] + b0, v1 = acc[mt][nt][1] + b1;
                float v2 = acc[mt][nt][2] + b0, v3 = acc[mt][nt][3] + b1;
                if (MODE == 1) {
                    v0 = gelu_exact(v0); v1 = gelu_exact(v1);
                    v2 = gelu_exact(v2); v3 = gelu_exact(v3);
                }
                *reinterpret_cast<uint32_t*>(&Out16[(size_t)r0 * Ntot + col]) = f2h2(v0, v1);
                *reinterpret_cast<uint32_t*>(&Out16[(size_t)(r0 + 8) * Ntot + col]) = f2h2(v2, v3);
            }
        }
    } else {
        // ---- fused LayerNorm epilogue (Ntot==256, colbase==0) ----
        float* sums = (float*)(smw + GEMM_SMEM_MAIN / 4);   // 64 rows x {s1,s2}
        if (tid < 128) sums[tid] = 0.0f;
        // bias + res into acc
        float gg[8][2], bb[8][2];
#pragma unroll
        for (int mt = 0; mt < 2; mt++) {
            int r0 = rowbase + wm + mt * 16 + g;
#pragma unroll
            for (int nt = 0; nt < 8; nt++) {
                int col = wn + nt * 8 + 2 * t;
                float b0 = bias[col], b1 = bias[col + 1];
                float2 r01 = *reinterpret_cast<const float2*>(&res[(size_t)r0 * 256 + col]);
                float2 r23 = *reinterpret_cast<const float2*>(&res[(size_t)(r0 + 8) * 256 + col]);
                acc[mt][nt][0] += b0 + r01.x; acc[mt][nt][1] += b1 + r01.y;
                acc[mt][nt][2] += b0 + r23.x; acc[mt][nt][3] += b1 + r23.y;
            }
        }
        __syncthreads();
#pragma unroll
        for (int mt = 0; mt < 2; mt++)
#pragma unroll
            for (int rh = 0; rh < 2; rh++) {
                float s1 = 0.0f, s2 = 0.0f;
#pragma unroll
                for (int nt = 0; nt < 8; nt++) {
                    float v0 = acc[mt][nt][2 * rh], v1 = acc[mt][nt][2 * rh + 1];
                    s1 += v0 + v1; s2 += v0 * v0 + v1 * v1;
                }
                s1 += __shfl_xor_sync(0xffffffffu, s1, 1);
                s1 += __shfl_xor_sync(0xffffffffu, s1, 2);
                s2 += __shfl_xor_sync(0xffffffffu, s2, 1);
                s2 += __shfl_xor_sync(0xffffffffu, s2, 2);
                if (t == 0) {
                    int rl = wm + mt * 16 + g + rh * 8;
                    atomicAdd(&sums[2 * rl], s1);
                    atomicAdd(&sums[2 * rl + 1], s2);
                }
            }
#pragma unroll
        for (int nt = 0; nt < 8; nt++) {
            int col = wn + nt * 8 + 2 * t;
            gg[nt][0] = lng[col]; gg[nt][1] = lng[col + 1];
            bb[nt][0] = lnb[col]; bb[nt][1] = lnb[col + 1];
        }
        __syncthreads();
#pragma unroll
        for (int mt = 0; mt < 2; mt++) {
#pragma unroll
            for (int rh = 0; rh < 2; rh++) {
                int rl = wm + mt * 16 + g + rh * 8;
                int grow = rowbase + rl;
                float mean = sums[2 * rl] * (1.0f / 256.0f);
                float var = sums[2 * rl + 1] * (1.0f / 256.0f) - mean * mean;
                float rstd = rsqrtf(var + 1e-5f);
#pragma unroll
                for (int nt = 0; nt < 8; nt++) {
                    int col = wn + nt * 8 + 2 * t;
                    float y0 = (acc[mt][nt][2 * rh] - mean) * rstd * gg[nt][0] + bb[nt][0];
                    float y1 = (acc[mt][nt][2 * rh + 1] - mean) * rstd * gg[nt][1] + bb[nt][1];
                    if (add2) {
                        float2 a2 = *reinterpret_cast<const float2*>(&add2[(size_t)grow * 256 + col]);
                        y0 += a2.x; y1 += a2.y;
                    }
                    *reinterpret_cast<float2*>(&Out32[(size_t)grow * 256 + col]) = make_float2(y0, y1);
                    if (Out16)
                        *reinterpret_cast<uint32_t*>(&Out16[(size_t)grow * 256 + col]) = f2h2(y0, y1);
                }
            }
        }
    }
}

// ---------------- Performer stage 1: kp/qp = relu(X_h @ projT)+eps, fp16 ----------------
#define S1_SMEM_BYTES ((2304 + 10368) * 4)

__global__ void __launch_bounds__(256) phi_kernel(const __half* __restrict__ QKV,
                                                  const __half* __restrict__ projh_l,
                                                  __half* __restrict__ KP,
                                                  __half* __restrict__ QP) {
    extern __shared__ uint32_t sw[];
    uint32_t* As = sw;           // 64 x 36 words
    uint32_t* Bs = sw + 2304;    // 288 x 36 words
    const int tid = threadIdx.x;
    const int lane = tid & 31, wid = tid >> 5;
    const int g = lane >> 2, t = lane & 3;
    const int wm = (wid & 1) * 32;
    const int wn = (wid >> 1) * 72;
    const int rowbase = blockIdx.x * 64;
    const int h = blockIdx.y & 3;
    const int isq = blockIdx.y >> 2;
    const __half* Ah = QKV + (isq ? h * 64 : 256 + h * 64);
    __half* outp = (isq ? QP : KP) + (size_t)h * TN * 288;
    const uint32_t sbA = smem_u32(As);

#pragma unroll
    for (int i = 0; i < 2; i++) {
        int idx = tid + i * 256;
        int m = idx >> 3, c = idx & 7;
        cp_async16(sbA + m * 144 + c * 16, Ah + (size_t)(rowbase + m) * 768 + c * 8);
    }
    CP_COMMIT();
    const uint32_t* pb = (const uint32_t*)projh_l;
#pragma unroll
    for (int i = 0; i < 36; i++) {
        int w = tid + i * 256;
        Bs[(w >> 5) * 36 + (w & 31)] = pb[w];
    }
    CP_WAIT0();
    __syncthreads();

    float acc[2][9][4];
#pragma unroll
    for (int mt = 0; mt < 2; mt++)
#pragma unroll
        for (int nt = 0; nt < 9; nt++)
#pragma unroll
            for (int j = 0; j < 4; j++) acc[mt][nt][j] = 0.0f;

#pragma unroll
    for (int ks = 0; ks < 4; ks++) {
        int k0 = ks * 8;
        uint32_t af[2][4], bf[9][2];
#pragma unroll
        for (int mt = 0; mt < 2; mt++) {
            int r0 = wm + mt * 16 + g;
            af[mt][0] = As[r0 * 36 + k0 + t];
            af[mt][1] = As[(r0 + 8) * 36 + k0 + t];
            af[mt][2] = As[r0 * 36 + k0 + t + 4];
            af[mt][3] = As[(r0 + 8) * 36 + k0 + t + 4];
        }
#pragma unroll
        for (int nt = 0; nt < 9; nt++) {
            int n0 = wn + nt * 8 + g;
            bf[nt][0] = Bs[n0 * 36 + k0 + t];
            bf[nt][1] = Bs[n0 * 36 + k0 + t + 4];
        }
#pragma unroll
        for (int mt = 0; mt < 2; mt++)
#pragma unroll
            for (int nt = 0; nt < 9; nt++)
                mma_f16_16x8x16(acc[mt][nt], af[mt], bf[nt]);
    }

#pragma unroll
    for (int mt = 0; mt < 2; mt++) {
        int r = rowbase + wm + mt * 16 + g;
#pragma unroll
        for (int nt = 0; nt < 9; nt++) {
            int c0 = wn + nt * 8 + 2 * t;
            float v0 = fmaxf(acc[mt][nt][0], 0.0f) + 1e-3f;
            float v1 = fmaxf(acc[mt][nt][1], 0.0f) + 1e-3f;
            float v2 = fmaxf(acc[mt][nt][2], 0.0f) + 1e-3f;
            float v3 = fmaxf(acc[mt][nt][3], 0.0f) + 1e-3f;
            if (c0 >= M_) { v0 = 0.0f; v2 = 0.0f; }
            if (c0 + 1 >= M_) { v1 = 0.0f; v3 = 0.0f; }
            *reinterpret_cast<uint32_t*>(&outp[(size_t)r * 288 + c0]) = f2h2(v0, v1);
            *reinterpret_cast<uint32_t*>(&outp[(size_t)(r + 8) * 288 + c0]) = f2h2(v2, v3);
        }
    }
}

// ---------------- Performer stage 2: ctx partials (2 CTAs per bh) ----------------
#define SK2W 37   // words per staged row (74 halves)
#define S2_SMEM_BYTES ((320 * SK2W + 80 * SK2W) * 4)

__global__ void __launch_bounds__(256) ctx_kernel(const __half* __restrict__ KP,
                                                  const __half* __restrict__ QKV,
                                                  float* __restrict__ CTX) {
    extern __shared__ uint32_t sw[];
    uint32_t* kpT = sw;                     // 320 x 37 words ([m][n])
    uint32_t* vsb = sw + 320 * SK2W;        // 80 x 37 words ([d'][n])
    __half* kpT_h = (__half*)kpT;
    __half* vs_h = (__half*)vsb;
    const int tid = threadIdx.x;
    const int lane = tid & 31, wid = tid >> 5;
    const int g = lane >> 2, t = lane & 3;
    const int wm = (wid & 3) * 80;
    const int wn = (wid >> 2) * 40;
    const int part = blockIdx.x >> 8;
    const int bh = blockIdx.x & 255;
    const int b = bh >> 2, h = bh & 3;

    for (int i = tid; i < 32 * 64; i += 256)
        kpT_h[(288 + i / 64) * 74 + (i % 64)] = __float2half(0.0f);
    for (int i = tid; i < 16 * 64; i += 256) {
        int d = 64 + i / 64, n = i % 64;
        vs_h[d * 74 + n] = __float2half((d == 64) ? 1.0f : 0.0f);
    }

    float acc[5][5][4];
#pragma unroll
    for (int mt = 0; mt < 5; mt++)
#pragma unroll
        for (int nt = 0; nt < 5; nt++)
#pragma unroll
            for (int j = 0; j < 4; j++) acc[mt][nt][j] = 0.0f;

    const uint32_t* kp2 = (const uint32_t*)(KP + (size_t)h * TN * 288);

    for (int c = 0; c < 4; c++) {
        __syncthreads();
        int base = b * 512 + (part * 4 + c) * 64;
#pragma unroll
        for (int i = 0; i < 36; i++) {
            int idx = tid + i * 256;
            int n = idx / 144, m2 = idx - n * 144;
            uint32_t w = kp2[(size_t)(base + n) * 144 + m2];
            __half2 hh = *reinterpret_cast<const __half2*>(&w);
            kpT_h[(2 * m2) * 74 + n] = __low2half(hh);
            kpT_h[(2 * m2 + 1) * 74 + n] = __high2half(hh);
        }
#pragma unroll
        for (int i = 0; i < 16; i++) {
            int idx = tid + i * 256;
            int n = idx >> 6, d = idx & 63;
            vs_h[d * 74 + n] = QKV[(size_t)(base + n) * 768 + 512 + h * 64 + d];
        }
        __syncthreads();
#pragma unroll
        for (int ks = 0; ks < 4; ks++) {
            int k0 = ks * 8;
            uint32_t af[5][4], bf[5][2];
#pragma unroll
            for (int mt = 0; mt < 5; mt++) {
                int r0 = wm + mt * 16 + g;
                af[mt][0] = kpT[r0 * SK2W + k0 + t];
                af[mt][1] = kpT[(r0 + 8) * SK2W + k0 + t];
                af[mt][2] = kpT[r0 * SK2W + k0 + t + 4];
                af[mt][3] = kpT[(r0 + 8) * SK2W + k0 + t + 4];
            }
#pragma unroll
            for (int nt = 0; nt < 5; nt++) {
                int n0 = wn + nt * 8 + g;
                bf[nt][0] = vsb[n0 * SK2W + k0 + t];
                bf[nt][1] = vsb[n0 * SK2W + k0 + t + 4];
            }
#pragma unroll
            for (int mt = 0; mt < 5; mt++)
#pragma unroll
                for (int nt = 0; nt < 5; nt++)
                    mma_f16_16x8x16(acc[mt][nt], af[mt], bf[nt]);
        }
    }

    float* outc = CTX + ((size_t)part * 256 + bh) * 80 * 320;
#pragma unroll
    for (int mt = 0; mt < 5; mt++) {
        int m0 = wm + mt * 16 + g;
#pragma unroll
        for (int nt = 0; nt < 5; nt++) {
            int c0 = wn + nt * 8 + 2 * t;
            outc[(size_t)c0 * 320 + m0] = acc[mt][nt][0];
            outc[(size_t)(c0 + 1) * 320 + m0] = acc[mt][nt][1];
            outc[(size_t)c0 * 320 + m0 + 8] = acc[mt][nt][2];
            outc[(size_t)(c0 + 1) * 320 + m0 + 8] = acc[mt][nt][3];
        }
    }
}

// ---------------- Performer stage 3: att' = qp @ (ctx0+ctx1); normalize; fp16 ----------------
#define S3_W_CTX (80 * 164)
#define S3_W_AS  (64 * 148)
#define S3_W_ATT (64 * 80)
#define S3_SMEM_BYTES ((S3_W_CTX + S3_W_AS + S3_W_ATT) * 4)

__global__ void __launch_bounds__(256) att_kernel(const __half* __restrict__ QP,
                                                  const float* __restrict__ CTX,
                                                  __half* __restrict__ Att) {
    extern __shared__ uint32_t sw[];
    uint32_t* ctxT = sw;                              // 80 x 164 words
    uint32_t* As = sw + S3_W_CTX;                     // 64 x 148 words
    float* att_s = (float*)(sw + S3_W_CTX + S3_W_AS); // 64 x 80
    const int tid = threadIdx.x;
    const int lane = tid & 31, wid = tid >> 5;
    const int g = lane >> 2, t = lane & 3;
    const int wm = (wid & 3) * 16;
    const int wn = (wid >> 2) * 40;
    const int cta = blockIdx.x;
    const int bh = cta >> 1, half = cta & 1;
    const int b = bh >> 2, h = bh & 3;

    const float* cg0 = CTX + (size_t)bh * 80 * 320;
    const float* cg1 = CTX + ((size_t)256 + bh) * 80 * 320;
#pragma unroll
    for (int i = 0; i < 50; i++) {
        int idx = tid + i * 256;
        int d = idx / 160, m2 = idx - d * 160;
        size_t o = (size_t)d * 320 + m2 * 2;
        float2 v0 = *reinterpret_cast<const float2*>(&cg0[o]);
        float2 v1 = *reinterpret_cast<const float2*>(&cg1[o]);
        ctxT[d * 164 + m2] = f2h2(v0.x + v1.x, v0.y + v1.y);
    }
    const uint32_t* qp2 = (const uint32_t*)(QP + (size_t)h * TN * 288);
    const int rowg0 = b * 512 + half * 256;

    for (int ch = 0; ch < 4; ch++) {
        __syncthreads();
        int rbase = rowg0 + ch * 64;
#pragma unroll
        for (int i = 0; i < 36; i++) {
            int idx = tid + i * 256;
            int n = idx / 144, m2 = idx - n * 144;
            As[n * 148 + m2] = qp2[(size_t)(rbase + n) * 144 + m2];
        }
        __syncthreads();
        float acc[5][4];
#pragma unroll
        for (int nt = 0; nt < 5; nt++)
#pragma unroll
            for (int j = 0; j < 4; j++) acc[nt][j] = 0.0f;
#pragma unroll
        for (int ks = 0; ks < 17; ks++) {
            int k0 = ks * 8;
            uint32_t af[4], bf[5][2];
            int r0 = wm + g;
            af[0] = As[r0 * 148 + k0 + t];
            af[1] = As[(r0 + 8) * 148 + k0 + t];
            af[2] = As[r0 * 148 + k0 + t + 4];
            af[3] = As[(r0 + 8) * 148 + k0 + t + 4];
#pragma unroll
            for (int nt = 0; nt < 5; nt++) {
                int n0 = wn + nt * 8 + g;
                bf[nt][0] = ctxT[n0 * 164 + k0 + t];
                bf[nt][1] = ctxT[n0 * 164 + k0 + t + 4];
            }
#pragma unroll
            for (int nt = 0; nt < 5; nt++)
                mma_f16_16x8x16(acc[nt], af, bf[nt]);
        }
#pragma unroll
        for (int nt = 0; nt < 5; nt++) {
            int c0 = wn + nt * 8 + 2 * t;
            att_s[(wm + g) * 80 + c0] = acc[nt][0];
            att_s[(wm + g) * 80 + c0 + 1] = acc[nt][1];
            att_s[(wm + g + 8) * 80 + c0] = acc[nt][2];
            att_s[(wm + g + 8) * 80 + c0 + 1] = acc[nt][3];
        }
        __syncthreads();
#pragma unroll
        for (int i = 0; i < 16; i++) {
            int idx = tid + i * 256;
            int n = idx >> 6, d = idx & 63;
            float den = att_s[n * 80 + 64];
            Att[(size_t)(rbase + n) * 256 + h * 64 + d] = __float2half_rn(att_s[n * 80 + d] / den);
        }
    }
}

// ---------------- node embedding ----------------
__global__ void node_embed_kernel(const float* __restrict__ x,
                                  const float* __restrict__ w,
                                  const float* __restrict__ b) {
    __shared__ float lx[11];
    int row = blockIdx.x;
    int t = threadIdx.x;
    if (t < 11) lx[t] = log1pf(x[row * 11 + t]);
    __syncthreads();
    float s = b[t];
#pragma unroll
    for (int j = 0; j < 11; j++) s += lx[j] * w[j * C_ + t];
    g_atoms[row * C_ + t] = s;
    g_atoms16[row * C_ + t] = __float2half_rn(s);
}

// ---------------- CSR build ----------------
__global__ void count_deg_kernel(const int* __restrict__ dst) {
    int e = blockIdx.x * blockDim.x + threadIdx.x;
    if (e < E_) atomicAdd(&g_deg[dst[e]], 1);
}
__global__ void scan_deg_kernel() {
    __shared__ int sh[1024];
    __shared__ int carry;
    int t = threadIdx.x;
    if (t == 0) carry = 0;
    __syncthreads();
    for (int base = 0; base < TN; base += 1024) {
        int v = g_deg[base + t];
        sh[t] = v;
        __syncthreads();
        for (int off = 1; off < 1024; off <<= 1) {
            int add = (t >= off) ? sh[t - off] : 0;
            __syncthreads();
            sh[t] += add;
            __syncthreads();
        }
        int ip = carry + sh[t] - v;
        g_indptr[base + t] = ip;
        g_cursor[base + t] = ip;
        __syncthreads();
        if (t == 0) carry += sh[1023];
        __syncthreads();
    }
    if (t == 0) g_indptr[TN] = carry;
}
__global__ void fill_adj_kernel(const int* __restrict__ dst) {
    int e = blockIdx.x * blockDim.x + threadIdx.x;
    if (e < E_) {
        int p = atomicAdd(&g_cursor[dst[e]], 1);
        g_eadj[p] = e;
    }
}

// ---------------- GINE aggregation (fp16 gather, fp16 out) ----------------
__global__ void __launch_bounds__(256) gine_kernel(const int* __restrict__ src,
                                                   const float* __restrict__ eattr,
                                                   const float* __restrict__ ew,
                                                   const float* __restrict__ eb) {
    __shared__ float sew[4][C_];
    __shared__ float seb[C_];
    int tid = threadIdx.x;
    for (int i = tid; i < 4 * C_; i += 256) sew[i >> 8][i & 255] = ew[i];
    seb[tid] = eb[tid];
    __syncthreads();
    int warp = tid >> 5, lane = tid & 31;
    int v = blockIdx.x * 8 + warp;
    float acc[8];
#pragma unroll
    for (int k = 0; k < 8; k++) acc[k] = g_atoms[v * C_ + lane + 32 * k];
    int p0 = g_indptr[v], p1 = g_indptr[v + 1];
    for (int p = p0; p < p1; p++) {
        int e = g_eadj[p];
        int s = src[e];
        float4 ea4 = *reinterpret_cast<const float4*>(&eattr[e * 4]);
        const __half* arow = &g_atoms16[s * C_];
#pragma unroll
        for (int k = 0; k < 8; k++) {
            int c = lane + 32 * k;
            float eac = seb[c] + ea4.x * sew[0][c] + ea4.y * sew[1][c]
                               + ea4.z * sew[2][c] + ea4.w * sew[3][c];
            acc[k] += fmaxf(__half2float(arow[c]) + eac, 0.0f);
        }
    }
#pragma unroll
    for (int k = 0; k < 8; k++)
        g_h016[v * C_ + lane + 32 * k] = __float2half_rn(acc[k]);
}

// ---------------- final mean pool ----------------
__global__ void pool_kernel(float* __restrict__ out) {
    int b = blockIdx.x;
    int cix = threadIdx.x;
    float s = 0.0f;
    for (int n = 0; n < N_; n++) s += g_atoms[(b * N_ + n) * C_ + cix];
    out[b * C_ + cix] = s * (1.0f / (float)N_);
}

// ---------------- host launcher ----------------
extern "C" void kernel_launch(void* const* d_in, const int* in_sizes, int n_in,
                              void* d_out, int out_size) {
    const float* x      = (const float*)d_in[0];
    const float* eattr  = (const float*)d_in[1];
    const int*   eidx   = (const int*)d_in[2];
    const float* node_w = (const float*)d_in[4];
    const float* node_b = (const float*)d_in[5];
    const float* edge_w = (const float*)d_in[6];
    const float* edge_b = (const float*)d_in[7];
    const float* gw1    = (const float*)d_in[8];
    const float* gb1    = (const float*)d_in[9];
    const float* gw2    = (const float*)d_in[10];
    const float* gb2    = (const float*)d_in[11];
    const float* qw     = (const float*)d_in[12];
    const float* kw     = (const float*)d_in[13];
    const float* vw     = (const float*)d_in[14];
    const float* ow     = (const float*)d_in[15];
    const float* ob     = (const float*)d_in[16];
    const float* proj   = (const float*)d_in[17];
    const float* n1g    = (const float*)d_in[18];
    const float* n1b    = (const float*)d_in[19];
    const float* n2g    = (const float*)d_in[20];
    const float* n2b    = (const float*)d_in[21];
    const float* n3g    = (const float*)d_in[22];
    const float* n3b    = (const float*)d_in[23];
    const float* mw1    = (const float*)d_in[24];
    const float* mb1    = (const float*)d_in[25];
    const float* mw2    = (const float*)d_in[26];
    const float* mb2    = (const float*)d_in[27];

    const int* src = eidx;
    const int* dst = eidx + E_;

    float *p_atoms, *p_hloc, *p_out, *p_ctx;
    __half *p_atoms16, *p_h016, *p_t116, *p_out16, *p_qkv16, *p_att16;
    __half *p_wt, *p_projh, *p_kp, *p_qp;
    int* p_deg;
    cudaGetSymbolAddress((void**)&p_atoms,   g_atoms);
    cudaGetSymbolAddress((void**)&p_atoms16, g_atoms16);
    cudaGetSymbolAddress((void**)&p_h016,    g_h016);
    cudaGetSymbolAddress((void**)&p_t116,    g_t116);
    cudaGetSymbolAddress((void**)&p_hloc,    g_hloc);
    cudaGetSymbolAddress((void**)&p_out,     g_out);
    cudaGetSymbolAddress((void**)&p_out16,   g_out16);
    cudaGetSymbolAddress((void**)&p_qkv16,   g_qkv16);
    cudaGetSymbolAddress((void**)&p_att16,   g_att16);
    cudaGetSymbolAddress((void**)&p_ctx,     g_ctx);
    cudaGetSymbolAddress((void**)&p_wt,      g_wt);
    cudaGetSymbolAddress((void**)&p_projh,   g_projh);
    cudaGetSymbolAddress((void**)&p_kp,      g_kp);
    cudaGetSymbolAddress((void**)&p_qp,      g_qp);
    cudaGetSymbolAddress((void**)&p_deg,     g_deg);

    cudaFuncSetAttribute((const void*)mma_gemm<0, 4>, cudaFuncAttributeMaxDynamicSharedMemorySize, GEMM_SMEM_BYTES);
    cudaFuncSetAttribute((const void*)mma_gemm<1, 4>, cudaFuncAttributeMaxDynamicSharedMemorySize, GEMM_SMEM_BYTES);
    cudaFuncSetAttribute((const void*)mma_gemm<2, 4>, cudaFuncAttributeMaxDynamicSharedMemorySize, GEMM_SMEM_BYTES);
    cudaFuncSetAttribute((const void*)mma_gemm<2, 8>, cudaFuncAttributeMaxDynamicSharedMemorySize, GEMM_SMEM_BYTES);
    cudaFuncSetAttribute(phi_kernel, cudaFuncAttributeMaxDynamicSharedMemorySize, S1_SMEM_BYTES);
    cudaFuncSetAttribute(ctx_kernel, cudaFuncAttributeMaxDynamicSharedMemorySize, S2_SMEM_BYTES);
    cudaFuncSetAttribute(att_kernel, cudaFuncAttributeMaxDynamicSharedMemorySize, S3_SMEM_BYTES);

    WPtrs wp;
    wp.p[0] = gw1; wp.p[1] = gw2; wp.p[2] = qw; wp.p[3] = kw;
    wp.p[4] = vw;  wp.p[5] = ow;  wp.p[6] = mw1; wp.p[7] = mw2;
    transpose_kernel<<<dim3(16, 16, 40), dim3(32, 8)>>>(wp);                  // 1
    proj_prep_kernel<<<(L_ * 288 * 64 + 255) / 256, 256>>>(proj);             // 2
    node_embed_kernel<<<TN, 256>>>(x, node_w, node_b);                        // 3

    dim3 g1(TN / 64, 1), g2(TN / 64, 2), g3(TN / 64, 3);
    bool csr_built = false;

    for (int l = 0; l < L_; l++) {
        const __half* wt_l = p_wt + l * 655360;
        // QKV (fused, N=768, fp16 out) — first mma_gemm is kernel #4 for ncu
        mma_gemm<0, 4><<<g3, 256, GEMM_SMEM_BYTES>>>(p_atoms16, wt_l + 131072, nullptr, nullptr,
                                                     nullptr, nullptr, nullptr, nullptr, p_qkv16, 768);
        // Performer (3 mma stages)
        phi_kernel<<<dim3(512, 8), 256, S1_SMEM_BYTES>>>(p_qkv16, p_projh + l * 288 * 64, p_kp, p_qp);
        ctx_kernel<<<512, 256, S2_SMEM_BYTES>>>(p_kp, p_qkv16, p_ctx);
        att_kernel<<<512, 256, S3_SMEM_BYTES>>>(p_qp, p_ctx, p_att16);
        // CSR build (once)
        if (!csr_built) {
            cudaMemsetAsync(p_deg, 0, TN * sizeof(int));
            count_deg_kernel<<<E_ / 256, 256>>>(dst);
            scan_deg_kernel<<<1, 1024>>>();
            fill_adj_kernel<<<E_ / 256, 256>>>(dst);
            csr_built = true;
        }
        // GINE conv
        gine_kernel<<<TN / 8, 256>>>(src, eattr, edge_w, edge_b);
        mma_gemm<1, 4><<<g1, 256, GEMM_SMEM_BYTES>>>(p_h016, wt_l + 0, gb1 + l * C_, nullptr,
                                                     nullptr, nullptr, nullptr, nullptr, p_t116, 256);
        mma_gemm<2, 4><<<g1, 256, GEMM_SMEM_BYTES>>>(p_t116, wt_l + 65536, gb2 + l * C_, p_atoms,
                                                     nullptr, n1g + l * C_, n1b + l * C_,
                                                     p_hloc, nullptr, 256);
        // O-proj + LN + combine: out = LN(att@ow+ob+atoms) + hloc
        mma_gemm<2, 4><<<g1, 256, GEMM_SMEM_BYTES>>>(p_att16, wt_l + 327680, ob + l * C_, p_atoms,
                                                     p_hloc, n2g + l * C_, n2b + l * C_,
                                                     p_out, p_out16, 256);
        // FFN
        mma_gemm<1, 4><<<g2, 256, GEMM_SMEM_BYTES>>>(p_out16, wt_l + 393216, mb1 + l * 2 * C_, nullptr,
                                                     nullptr, nullptr, nullptr, nullptr, p_t116, 512);
        mma_gemm<2, 8><<<g1, 256, GEMM_SMEM_BYTES>>>(p_t116, wt_l + 524288, mb2 + l * C_, p_out,
                                                     nullptr, n3g + l * C_, n3b + l * C_,
                                                     p_atoms, p_atoms16, 256);
    }
    pool_kernel<<<B_, 256>>>((float*)d_out);
}

// round 11
// speedup vs baseline: 5.0041x; 1.0080x over previous
#include <cuda_runtime.h>
#include <cuda_fp16.h>
#include <math.h>
#include <stdint.h>

#define TN   32768
#define C_   256
#define B_   64
#define N_   512
#define H_   4
#define DH_  64
#define M_   266
#define E_   524288
#define L_   5

// ---------------- scratch ----------------
__device__ float  g_atoms[TN * C_];
__device__ __half g_atoms16[TN * C_];
__device__ __half g_h016[TN * C_];
__device__ __half g_t116[TN * 2 * C_];
__device__ float  g_hloc[TN * C_];
__device__ float  g_out[TN * C_];
__device__ __half g_out16[TN * C_];
__device__ __half g_qkv16[(size_t)TN * 3 * C_];
__device__ __half g_att16[TN * C_];
__device__ __half g_wt[L_ * 655360];          // transposed fp16 weights, [n][k]
__device__ __half g_projh[L_ * 288 * 64];     // fp16 proj, rows >=266 zero
__device__ __half g_kp[(size_t)H_ * TN * 288];
__device__ __half g_qp[(size_t)H_ * TN * 288];
__device__ float  g_ctx[2 * 256 * 80 * 320];  // [part][bh][d'][m]
__device__ int    g_deg[TN];
__device__ int    g_indptr[TN + 1];
__device__ int    g_cursor[TN];
__device__ int    g_eadj[E_];

// ---------------- helpers ----------------
__device__ __forceinline__ float gelu_exact(float x) {
    return 0.5f * x * (1.0f + erff(x * 0.70710678118654752f));
}
__device__ __forceinline__ uint32_t f2h2(float a, float b) {
    __half2 h = __floats2half2_rn(a, b);
    return *reinterpret_cast<uint32_t*>(&h);
}
__device__ __forceinline__ uint32_t smem_u32(const void* p) {
    uint32_t a;
    asm("{ .reg .u64 t; cvta.to.shared.u64 t, %1; cvt.u32.u64 %0, t; }" : "=r"(a) : "l"(p));
    return a;
}
__device__ __forceinline__ void mma_f16_16x8x16(float* d, const uint32_t* a, const uint32_t* b) {
    asm volatile(
        "mma.sync.aligned.m16n8k16.row.col.f32.f16.f16.f32 "
        "{%0,%1,%2,%3}, {%4,%5,%6,%7}, {%8,%9}, {%0,%1,%2,%3};"
        : "+f"(d[0]), "+f"(d[1]), "+f"(d[2]), "+f"(d[3])
        : "r"(a[0]), "r"(a[1]), "r"(a[2]), "r"(a[3]), "r"(b[0]), "r"(b[1]));
}
__device__ __forceinline__ void ldsm_x4(uint32_t* r, uint32_t saddr) {
    asm volatile("ldmatrix.sync.aligned.m8n8.x4.shared.b16 {%0,%1,%2,%3}, [%4];"
                 : "=r"(r[0]), "=r"(r[1]), "=r"(r[2]), "=r"(r[3]) : "r"(saddr));
}
__device__ __forceinline__ void cp_async16(uint32_t saddr, const void* gptr) {
    asm volatile("cp.async.cg.shared.global [%0], [%1], 16;" :: "r"(saddr), "l"(gptr));
}
#define CP_COMMIT() asm volatile("cp.async.commit_group;" ::: "memory")
#define CP_WAIT0()  asm volatile("cp.async.wait_group 0;" ::: "memory")

// ---------------- weight transpose (once): WT[n*K+k] = half(W[k*N+n]) ----------------
struct WPtrs { const float* p[8]; };

__global__ void transpose_kernel(WPtrs wp) {
    int z = blockIdx.z;
    int t = z & 7, l = z >> 3;
    int K = (t == 7) ? 512 : 256;
    int N = (t == 6) ? 512 : 256;
    int n0 = blockIdx.x * 32, k0 = blockIdx.y * 32;
    if (n0 >= N || k0 >= K) return;
    const float* src = wp.p[t] + ((t >= 6) ? l * 131072 : l * 65536);
    int doff = (t < 6) ? t * 65536 : (t == 6 ? 393216 : 524288);
    __half* dst = g_wt + l * 655360 + doff;
    __shared__ float s[32][33];
    int tx = threadIdx.x, ty = threadIdx.y;
#pragma unroll
    for (int i = 0; i < 4; i++)
        s[ty + 8 * i][tx] = src[(k0 + ty + 8 * i) * N + n0 + tx];
    __syncthreads();
#pragma unroll
    for (int i = 0; i < 4; i++)
        dst[(n0 + ty + 8 * i) * K + k0 + tx] = __float2half_rn(s[tx][ty + 8 * i]);
}

// ---------------- proj -> fp16, padded to 288 rows ----------------
__global__ void proj_prep_kernel(const float* __restrict__ proj) {
    int idx = blockIdx.x * 256 + threadIdx.x;
    if (idx >= L_ * 288 * 64) return;
    int l = idx / (288 * 64);
    int r = idx - l * (288 * 64);
    int m = r >> 6, d = r & 63;
    g_projh[idx] = (m < M_) ? __float2half_rn(proj[(l * M_ + m) * 64 + d]) : __half(0.f);
}

// ---------------- fp16 mma GEMM, ldmatrix + cp.async, fused LN epilogue ----------------
// MODE 0: +bias -> out16            MODE 1: gelu(+bias) -> out16
// MODE 2: LN(+bias+res) (+add2) -> out32 (+out16)      [Ntot==256, grid.y==1]
#define GEMM_SMEM_MAIN  (2 * 9216 + 2 * 36864)
#define GEMM_SMEM_BYTES (GEMM_SMEM_MAIN + 512)

template <int MODE, int NK>
__global__ void __launch_bounds__(256, 2) mma_gemm(const __half* __restrict__ A,
                                                   const __half* __restrict__ WT,
                                                   const float* __restrict__ bias,
                                                   const float* __restrict__ res,
                                                   const float* __restrict__ add2,
                                                   const float* __restrict__ lng,
                                                   const float* __restrict__ lnb,
                                                   float* __restrict__ Out32,
                                                   __half* __restrict__ Out16,
                                                   int Ntot) {
    extern __shared__ uint32_t smw[];
    const int K = NK * 64;
    const int tid = threadIdx.x;
    const int lane = tid & 31, wid = tid >> 5;
    const int g = lane >> 2, t = lane & 3;
    const int wm = (wid & 1) * 32;
    const int wn = (wid >> 1) * 64;
    const int rowbase = blockIdx.x * 64;
    const int colbase = blockIdx.y * 256;
    const uint32_t sb = smem_u32(smw);

    const int l7 = lane & 7, l8 = (lane >> 3) & 1, l16 = (lane >> 4) & 1;
    uint32_t aAddr[2], bAddr[4];
#pragma unroll
    for (int mt = 0; mt < 2; mt++)
        aAddr[mt] = sb + (wm + mt * 16 + l7 + l8 * 8) * 144 + l16 * 16;
#pragma unroll
    for (int p = 0; p < 4; p++)
        bAddr[p] = sb + 18432 + (wn + p * 16 + l7 + l16 * 8) * 144 + l8 * 16;

    float acc[2][8][4];
#pragma unroll
    for (int mt = 0; mt < 2; mt++)
#pragma unroll
        for (int nt = 0; nt < 8; nt++)
#pragma unroll
            for (int j = 0; j < 4; j++) acc[mt][nt][j] = 0.0f;

    // prologue: stage 0
#pragma unroll
    for (int i = 0; i < 2; i++) {
        int idx = tid + i * 256;
        int m = idx >> 3, c = idx & 7;
        cp_async16(sb + m * 144 + c * 16, A + (size_t)(rowbase + m) * K + c * 8);
    }
#pragma unroll
    for (int i = 0; i < 8; i++) {
        int idx = tid + i * 256;
        int n = idx >> 3, c = idx & 7;
        cp_async16(sb + 18432 + n * 144 + c * 16, WT + (size_t)(colbase + n) * K + c * 8);
    }
    CP_COMMIT();
    CP_WAIT0();
    __syncthreads();

#pragma unroll
    for (int kb = 0; kb < NK; kb++) {
        const int cur = kb & 1;
        const bool nxt = (kb + 1 < NK);
        if (nxt) {
            int k0g = (kb + 1) * 64;
            int sB = cur ^ 1;
#pragma unroll
            for (int i = 0; i < 2; i++) {
                int idx = tid + i * 256;
                int m = idx >> 3, c = idx & 7;
                cp_async16(sb + sB * 9216 + m * 144 + c * 16,
                           A + (size_t)(rowbase + m) * K + k0g + c * 8);
            }
#pragma unroll
            for (int i = 0; i < 8; i++) {
                int idx = tid + i * 256;
                int n = idx >> 3, c = idx & 7;
                cp_async16(sb + 18432 + sB * 36864 + n * 144 + c * 16,
                           WT + (size_t)(colbase + n) * K + k0g + c * 8);
            }
            CP_COMMIT();
        }
        const uint32_t aoff = cur * 9216, boff = cur * 36864;
#pragma unroll
        for (int ks = 0; ks < 4; ks++) {
            uint32_t ar[2][4], br[4][4];
            ldsm_x4(ar[0], aAddr[0] + aoff + ks * 32);
            ldsm_x4(ar[1], aAddr[1] + aoff + ks * 32);
#pragma unroll
            for (int p = 0; p < 4; p++) ldsm_x4(br[p], bAddr[p] + boff + ks * 32);
#pragma unroll
            for (int mt = 0; mt < 2; mt++)
#pragma unroll
                for (int p = 0; p < 4; p++) {
                    mma_f16_16x8x16(acc[mt][2 * p],     ar[mt], &br[p][0]);
                    mma_f16_16x8x16(acc[mt][2 * p + 1], ar[mt], &br[p][2]);
                }
        }
        if (nxt) {
            CP_WAIT0();
            __syncthreads();
        }
    }

    if (MODE <= 1) {
#pragma unroll
        for (int mt = 0; mt < 2; mt++) {
            int r0 = rowbase + wm + mt * 16 + g;
#pragma unroll
            for (int nt = 0; nt < 8; nt++) {
                int col = colbase + wn + nt * 8 + 2 * t;
                float b0 = 0.0f, b1 = 0.0f;
                if (bias) { b0 = bias[col]; b1 = bias[col + 1]; }
                float v0 = acc[mt][nt][0] + b0, v1 = acc[mt][nt][1] + b1;
                float v2 = acc[mt][nt][2] + b0, v3 = acc[mt][nt][3] + b1;
                if (MODE == 1) {
                    v0 = gelu_exact(v0); v1 = gelu_exact(v1);
                    v2 = gelu_exact(v2); v3 = gelu_exact(v3);
                }
                *reinterpret_cast<uint32_t*>(&Out16[(size_t)r0 * Ntot + col]) = f2h2(v0, v1);
                *reinterpret_cast<uint32_t*>(&Out16[(size_t)(r0 + 8) * Ntot + col]) = f2h2(v2, v3);
            }
        }
    } else {
        // ---- fused LayerNorm epilogue (Ntot==256, colbase==0) ----
        float* sums = (float*)(smw + GEMM_SMEM_MAIN / 4);   // 64 rows x {s1,s2}
        if (tid < 128) sums[tid] = 0.0f;
        float gg[8][2], bb[8][2];
#pragma unroll
        for (int mt = 0; mt < 2; mt++) {
            int r0 = rowbase + wm + mt * 16 + g;
#pragma unroll
            for (int nt = 0; nt < 8; nt++) {
                int col = wn + nt * 8 + 2 * t;
                float b0 = bias[col], b1 = bias[col + 1];
                float2 r01 = *reinterpret_cast<const float2*>(&res[(size_t)r0 * 256 + col]);
                float2 r23 = *reinterpret_cast<const float2*>(&res[(size_t)(r0 + 8) * 256 + col]);
                acc[mt][nt][0] += b0 + r01.x; acc[mt][nt][1] += b1 + r01.y;
                acc[mt][nt][2] += b0 + r23.x; acc[mt][nt][3] += b1 + r23.y;
            }
        }
        __syncthreads();
#pragma unroll
        for (int mt = 0; mt < 2; mt++)
#pragma unroll
            for (int rh = 0; rh < 2; rh++) {
                float s1 = 0.0f, s2 = 0.0f;
#pragma unroll
                for (int nt = 0; nt < 8; nt++) {
                    float v0 = acc[mt][nt][2 * rh], v1 = acc[mt][nt][2 * rh + 1];
                    s1 += v0 + v1; s2 += v0 * v0 + v1 * v1;
                }
                s1 += __shfl_xor_sync(0xffffffffu, s1, 1);
                s1 += __shfl_xor_sync(0xffffffffu, s1, 2);
                s2 += __shfl_xor_sync(0xffffffffu, s2, 1);
                s2 += __shfl_xor_sync(0xffffffffu, s2, 2);
                if (t == 0) {
                    int rl = wm + mt * 16 + g + rh * 8;
                    atomicAdd(&sums[2 * rl], s1);
                    atomicAdd(&sums[2 * rl + 1], s2);
                }
            }
#pragma unroll
        for (int nt = 0; nt < 8; nt++) {
            int col = wn + nt * 8 + 2 * t;
            gg[nt][0] = lng[col]; gg[nt][1] = lng[col + 1];
            bb[nt][0] = lnb[col]; bb[nt][1] = lnb[col + 1];
        }
        __syncthreads();
#pragma unroll
        for (int mt = 0; mt < 2; mt++) {
#pragma unroll
            for (int rh = 0; rh < 2; rh++) {
                int rl = wm + mt * 16 + g + rh * 8;
                int grow = rowbase + rl;
                float mean = sums[2 * rl] * (1.0f / 256.0f);
                float var = sums[2 * rl + 1] * (1.0f / 256.0f) - mean * mean;
                float rstd = rsqrtf(var + 1e-5f);
#pragma unroll
                for (int nt = 0; nt < 8; nt++) {
                    int col = wn + nt * 8 + 2 * t;
                    float y0 = (acc[mt][nt][2 * rh] - mean) * rstd * gg[nt][0] + bb[nt][0];
                    float y1 = (acc[mt][nt][2 * rh + 1] - mean) * rstd * gg[nt][1] + bb[nt][1];
                    if (add2) {
                        float2 a2 = *reinterpret_cast<const float2*>(&add2[(size_t)grow * 256 + col]);
                        y0 += a2.x; y1 += a2.y;
                    }
                    *reinterpret_cast<float2*>(&Out32[(size_t)grow * 256 + col]) = make_float2(y0, y1);
                    if (Out16)
                        *reinterpret_cast<uint32_t*>(&Out16[(size_t)grow * 256 + col]) = f2h2(y0, y1);
                }
            }
        }
    }
}

// ---------------- Performer stage 1: kp/qp = relu(X_h @ projT)+eps, fp16 ----------------
#define S1_SMEM_BYTES ((2304 + 10368) * 4)

__global__ void __launch_bounds__(256) phi_kernel(const __half* __restrict__ QKV,
                                                  const __half* __restrict__ projh_l,
                                                  __half* __restrict__ KP,
                                                  __half* __restrict__ QP) {
    extern __shared__ uint32_t sw[];
    uint32_t* As = sw;           // 64 x 36 words
    uint32_t* Bs = sw + 2304;    // 288 x 36 words
    const int tid = threadIdx.x;
    const int lane = tid & 31, wid = tid >> 5;
    const int g = lane >> 2, t = lane & 3;
    const int wm = (wid & 1) * 32;
    const int wn = (wid >> 1) * 72;
    const int rowbase = blockIdx.x * 64;
    const int h = blockIdx.y & 3;
    const int isq = blockIdx.y >> 2;
    const __half* Ah = QKV + (isq ? h * 64 : 256 + h * 64);
    __half* outp = (isq ? QP : KP) + (size_t)h * TN * 288;
    const uint32_t sbA = smem_u32(As);

#pragma unroll
    for (int i = 0; i < 2; i++) {
        int idx = tid + i * 256;
        int m = idx >> 3, c = idx & 7;
        cp_async16(sbA + m * 144 + c * 16, Ah + (size_t)(rowbase + m) * 768 + c * 8);
    }
    CP_COMMIT();
    const uint32_t* pb = (const uint32_t*)projh_l;
#pragma unroll
    for (int i = 0; i < 36; i++) {
        int w = tid + i * 256;
        Bs[(w >> 5) * 36 + (w & 31)] = pb[w];
    }
    CP_WAIT0();
    __syncthreads();

    float acc[2][9][4];
#pragma unroll
    for (int mt = 0; mt < 2; mt++)
#pragma unroll
        for (int nt = 0; nt < 9; nt++)
#pragma unroll
            for (int j = 0; j < 4; j++) acc[mt][nt][j] = 0.0f;

#pragma unroll
    for (int ks = 0; ks < 4; ks++) {
        int k0 = ks * 8;
        uint32_t af[2][4], bf[9][2];
#pragma unroll
        for (int mt = 0; mt < 2; mt++) {
            int r0 = wm + mt * 16 + g;
            af[mt][0] = As[r0 * 36 + k0 + t];
            af[mt][1] = As[(r0 + 8) * 36 + k0 + t];
            af[mt][2] = As[r0 * 36 + k0 + t + 4];
            af[mt][3] = As[(r0 + 8) * 36 + k0 + t + 4];
        }
#pragma unroll
        for (int nt = 0; nt < 9; nt++) {
            int n0 = wn + nt * 8 + g;
            bf[nt][0] = Bs[n0 * 36 + k0 + t];
            bf[nt][1] = Bs[n0 * 36 + k0 + t + 4];
        }
#pragma unroll
        for (int mt = 0; mt < 2; mt++)
#pragma unroll
            for (int nt = 0; nt < 9; nt++)
                mma_f16_16x8x16(acc[mt][nt], af[mt], bf[nt]);
    }

#pragma unroll
    for (int mt = 0; mt < 2; mt++) {
        int r = rowbase + wm + mt * 16 + g;
#pragma unroll
        for (int nt = 0; nt < 9; nt++) {
            int c0 = wn + nt * 8 + 2 * t;
            float v0 = fmaxf(acc[mt][nt][0], 0.0f) + 1e-3f;
            float v1 = fmaxf(acc[mt][nt][1], 0.0f) + 1e-3f;
            float v2 = fmaxf(acc[mt][nt][2], 0.0f) + 1e-3f;
            float v3 = fmaxf(acc[mt][nt][3], 0.0f) + 1e-3f;
            if (c0 >= M_) { v0 = 0.0f; v2 = 0.0f; }
            if (c0 + 1 >= M_) { v1 = 0.0f; v3 = 0.0f; }
            *reinterpret_cast<uint32_t*>(&outp[(size_t)r * 288 + c0]) = f2h2(v0, v1);
            *reinterpret_cast<uint32_t*>(&outp[(size_t)(r + 8) * 288 + c0]) = f2h2(v2, v3);
        }
    }
}

// ---------------- Performer stage 2: ctx partials (2 CTAs per bh) ----------------
#define SK2W 37   // words per staged row (74 halves)
#define S2_SMEM_BYTES ((320 * SK2W + 80 * SK2W) * 4)

__global__ void __launch_bounds__(256) ctx_kernel(const __half* __restrict__ KP,
                                                  const __half* __restrict__ QKV,
                                                  float* __restrict__ CTX) {
    extern __shared__ uint32_t sw[];
    uint32_t* kpT = sw;                     // 320 x 37 words ([m][n])
    uint32_t* vsb = sw + 320 * SK2W;        // 80 x 37 words ([d'][n])
    __half* kpT_h = (__half*)kpT;
    __half* vs_h = (__half*)vsb;
    const int tid = threadIdx.x;
    const int lane = tid & 31, wid = tid >> 5;
    const int g = lane >> 2, t = lane & 3;
    const int wm = (wid & 3) * 80;
    const int wn = (wid >> 2) * 40;
    const int part = blockIdx.x >> 8;
    const int bh = blockIdx.x & 255;
    const int b = bh >> 2, h = bh & 3;

    for (int i = tid; i < 32 * 64; i += 256)
        kpT_h[(288 + i / 64) * 74 + (i % 64)] = __float2half(0.0f);
    for (int i = tid; i < 16 * 64; i += 256) {
        int d = 64 + i / 64, n = i % 64;
        vs_h[d * 74 + n] = __float2half((d == 64) ? 1.0f : 0.0f);
    }

    float acc[5][5][4];
#pragma unroll
    for (int mt = 0; mt < 5; mt++)
#pragma unroll
        for (int nt = 0; nt < 5; nt++)
#pragma unroll
            for (int j = 0; j < 4; j++) acc[mt][nt][j] = 0.0f;

    const uint32_t* kp2 = (const uint32_t*)(KP + (size_t)h * TN * 288);

    for (int c = 0; c < 4; c++) {
        __syncthreads();
        int base = b * 512 + (part * 4 + c) * 64;
#pragma unroll
        for (int i = 0; i < 36; i++) {
            int idx = tid + i * 256;
            int n = idx / 144, m2 = idx - n * 144;
            uint32_t w = kp2[(size_t)(base + n) * 144 + m2];
            __half2 hh = *reinterpret_cast<const __half2*>(&w);
            kpT_h[(2 * m2) * 74 + n] = __low2half(hh);
            kpT_h[(2 * m2 + 1) * 74 + n] = __high2half(hh);
        }
#pragma unroll
        for (int i = 0; i < 16; i++) {
            int idx = tid + i * 256;
            int n = idx >> 6, d = idx & 63;
            vs_h[d * 74 + n] = QKV[(size_t)(base + n) * 768 + 512 + h * 64 + d];
        }
        __syncthreads();
#pragma unroll
        for (int ks = 0; ks < 4; ks++) {
            int k0 = ks * 8;
            uint32_t af[5][4], bf[5][2];
#pragma unroll
            for (int mt = 0; mt < 5; mt++) {
                int r0 = wm + mt * 16 + g;
                af[mt][0] = kpT[r0 * SK2W + k0 + t];
                af[mt][1] = kpT[(r0 + 8) * SK2W + k0 + t];
                af[mt][2] = kpT[r0 * SK2W + k0 + t + 4];
                af[mt][3] = kpT[(r0 + 8) * SK2W + k0 + t + 4];
            }
#pragma unroll
            for (int nt = 0; nt < 5; nt++) {
                int n0 = wn + nt * 8 + g;
                bf[nt][0] = vsb[n0 * SK2W + k0 + t];
                bf[nt][1] = vsb[n0 * SK2W + k0 + t + 4];
            }
#pragma unroll
            for (int mt = 0; mt < 5; mt++)
#pragma unroll
                for (int nt = 0; nt < 5; nt++)
                    mma_f16_16x8x16(acc[mt][nt], af[mt], bf[nt]);
        }
    }

    float* outc = CTX + ((size_t)part * 256 + bh) * 80 * 320;
#pragma unroll
    for (int mt = 0; mt < 5; mt++) {
        int m0 = wm + mt * 16 + g;
#pragma unroll
        for (int nt = 0; nt < 5; nt++) {
            int c0 = wn + nt * 8 + 2 * t;
            outc[(size_t)c0 * 320 + m0] = acc[mt][nt][0];
            outc[(size_t)(c0 + 1) * 320 + m0] = acc[mt][nt][1];
            outc[(size_t)c0 * 320 + m0 + 8] = acc[mt][nt][2];
            outc[(size_t)(c0 + 1) * 320 + m0 + 8] = acc[mt][nt][3];
        }
    }
}

// ---------------- Performer stage 3: att' = qp @ (ctx0+ctx1); normalize; fp16 ----------------
#define S3_W_CTX (80 * 164)
#define S3_W_AS  (64 * 148)
#define S3_W_ATT (64 * 80)
#define S3_SMEM_BYTES ((S3_W_CTX + S3_W_AS + S3_W_ATT) * 4)

__global__ void __launch_bounds__(256) att_kernel(const __half* __restrict__ QP,
                                                  const float* __restrict__ CTX,
                                                  __half* __restrict__ Att) {
    extern __shared__ uint32_t sw[];
    uint32_t* ctxT = sw;                              // 80 x 164 words
    uint32_t* As = sw + S3_W_CTX;                     // 64 x 148 words
    float* att_s = (float*)(sw + S3_W_CTX + S3_W_AS); // 64 x 80
    const int tid = threadIdx.x;
    const int lane = tid & 31, wid = tid >> 5;
    const int g = lane >> 2, t = lane & 3;
    const int wm = (wid & 3) * 16;
    const int wn = (wid >> 2) * 40;
    const int cta = blockIdx.x;
    const int bh = cta >> 1, half = cta & 1;
    const int b = bh >> 2, h = bh & 3;

    const float* cg0 = CTX + (size_t)bh * 80 * 320;
    const float* cg1 = CTX + ((size_t)256 + bh) * 80 * 320;
#pragma unroll
    for (int i = 0; i < 50; i++) {
        int idx = tid + i * 256;
        int d = idx / 160, m2 = idx - d * 160;
        size_t o = (size_t)d * 320 + m2 * 2;
        float2 v0 = *reinterpret_cast<const float2*>(&cg0[o]);
        float2 v1 = *reinterpret_cast<const float2*>(&cg1[o]);
        ctxT[d * 164 + m2] = f2h2(v0.x + v1.x, v0.y + v1.y);
    }
    const uint32_t* qp2 = (const uint32_t*)(QP + (size_t)h * TN * 288);
    const int rowg0 = b * 512 + half * 256;

    for (int ch = 0; ch < 4; ch++) {
        __syncthreads();
        int rbase = rowg0 + ch * 64;
#pragma unroll
        for (int i = 0; i < 36; i++) {
            int idx = tid + i * 256;
            int n = idx / 144, m2 = idx - n * 144;
            As[n * 148 + m2] = qp2[(size_t)(rbase + n) * 144 + m2];
        }
        __syncthreads();
        float acc[5][4];
#pragma unroll
        for (int nt = 0; nt < 5; nt++)
#pragma unroll
            for (int j = 0; j < 4; j++) acc[nt][j] = 0.0f;
#pragma unroll
        for (int ks = 0; ks < 17; ks++) {
            int k0 = ks * 8;
            uint32_t af[4], bf[5][2];
            int r0 = wm + g;
            af[0] = As[r0 * 148 + k0 + t];
            af[1] = As[(r0 + 8) * 148 + k0 + t];
            af[2] = As[r0 * 148 + k0 + t + 4];
            af[3] = As[(r0 + 8) * 148 + k0 + t + 4];
#pragma unroll
            for (int nt = 0; nt < 5; nt++) {
                int n0 = wn + nt * 8 + g;
                bf[nt][0] = ctxT[n0 * 164 + k0 + t];
                bf[nt][1] = ctxT[n0 * 164 + k0 + t + 4];
            }
#pragma unroll
            for (int nt = 0; nt < 5; nt++)
                mma_f16_16x8x16(acc[nt], af, bf[nt]);
        }
#pragma unroll
        for (int nt = 0; nt < 5; nt++) {
            int c0 = wn + nt * 8 + 2 * t;
            att_s[(wm + g) * 80 + c0] = acc[nt][0];
            att_s[(wm + g) * 80 + c0 + 1] = acc[nt][1];
            att_s[(wm + g + 8) * 80 + c0] = acc[nt][2];
            att_s[(wm + g + 8) * 80 + c0 + 1] = acc[nt][3];
        }
        __syncthreads();
#pragma unroll
        for (int i = 0; i < 16; i++) {
            int idx = tid + i * 256;
            int n = idx >> 6, d = idx & 63;
            float den = att_s[n * 80 + 64];
            Att[(size_t)(rbase + n) * 256 + h * 64 + d] = __float2half_rn(att_s[n * 80 + d] / den);
        }
    }
}

// ---------------- node embedding ----------------
__global__ void node_embed_kernel(const float* __restrict__ x,
                                  const float* __restrict__ w,
                                  const float* __restrict__ b) {
    __shared__ float lx[11];
    int row = blockIdx.x;
    int t = threadIdx.x;
    if (t < 11) lx[t] = log1pf(x[row * 11 + t]);
    __syncthreads();
    float s = b[t];
#pragma unroll
    for (int j = 0; j < 11; j++) s += lx[j] * w[j * C_ + t];
    g_atoms[row * C_ + t] = s;
    g_atoms16[row * C_ + t] = __float2half_rn(s);
}

// ---------------- CSR build ----------------
__global__ void count_deg_kernel(const int* __restrict__ dst) {
    int e = blockIdx.x * blockDim.x + threadIdx.x;
    if (e < E_) atomicAdd(&g_deg[dst[e]], 1);
}
__global__ void scan_deg_kernel() {
    __shared__ int sh[1024];
    __shared__ int carry;
    int t = threadIdx.x;
    if (t == 0) carry = 0;
    __syncthreads();
    for (int base = 0; base < TN; base += 1024) {
        int v = g_deg[base + t];
        sh[t] = v;
        __syncthreads();
        for (int off = 1; off < 1024; off <<= 1) {
            int add = (t >= off) ? sh[t - off] : 0;
            __syncthreads();
            sh[t] += add;
            __syncthreads();
        }
        int ip = carry + sh[t] - v;
        g_indptr[base + t] = ip;
        g_cursor[base + t] = ip;
        __syncthreads();
        if (t == 0) carry += sh[1023];
        __syncthreads();
    }
    if (t == 0) g_indptr[TN] = carry;
}
__global__ void fill_adj_kernel(const int* __restrict__ dst) {
    int e = blockIdx.x * blockDim.x + threadIdx.x;
    if (e < E_) {
        int p = atomicAdd(&g_cursor[dst[e]], 1);
        g_eadj[p] = e;
    }
}

// ---------------- GINE aggregation: vectorized gather, per-thread ew registers ----------
// Thread owns columns [lane*8, lane*8+8): one LDG.128 per edge per lane.
__global__ void __launch_bounds__(256) gine_kernel(const int* __restrict__ src,
                                                   const float* __restrict__ eattr,
                                                   const float* __restrict__ ew,
                                                   const float* __restrict__ eb) {
    int tid = threadIdx.x;
    int warp = tid >> 5, lane = tid & 31;
    int v = blockIdx.x * 8 + warp;
    const int c0 = lane * 8;

    float ewr[4][8], ebr[8];
#pragma unroll
    for (int j = 0; j < 4; j++) {
        float4 w0 = *reinterpret_cast<const float4*>(&ew[j * C_ + c0]);
        float4 w1 = *reinterpret_cast<const float4*>(&ew[j * C_ + c0 + 4]);
        ewr[j][0] = w0.x; ewr[j][1] = w0.y; ewr[j][2] = w0.z; ewr[j][3] = w0.w;
        ewr[j][4] = w1.x; ewr[j][5] = w1.y; ewr[j][6] = w1.z; ewr[j][7] = w1.w;
    }
    {
        float4 b0 = *reinterpret_cast<const float4*>(&eb[c0]);
        float4 b1 = *reinterpret_cast<const float4*>(&eb[c0 + 4]);
        ebr[0] = b0.x; ebr[1] = b0.y; ebr[2] = b0.z; ebr[3] = b0.w;
        ebr[4] = b1.x; ebr[5] = b1.y; ebr[6] = b1.z; ebr[7] = b1.w;
    }

    float acc[8];
    {
        float4 a0 = *reinterpret_cast<const float4*>(&g_atoms[(size_t)v * C_ + c0]);
        float4 a1 = *reinterpret_cast<const float4*>(&g_atoms[(size_t)v * C_ + c0 + 4]);
        acc[0] = a0.x; acc[1] = a0.y; acc[2] = a0.z; acc[3] = a0.w;
        acc[4] = a1.x; acc[5] = a1.y; acc[6] = a1.z; acc[7] = a1.w;
    }

    int p0 = g_indptr[v], p1 = g_indptr[v + 1];
    for (int p = p0; p < p1; p++) {
        int e = g_eadj[p];
        int s = src[e];
        float4 ea4 = *reinterpret_cast<const float4*>(&eattr[e * 4]);
        uint4 hv = *reinterpret_cast<const uint4*>(&g_atoms16[(size_t)s * C_ + c0]);
        float2 f0 = __half22float2(*reinterpret_cast<__half2*>(&hv.x));
        float2 f1 = __half22float2(*reinterpret_cast<__half2*>(&hv.y));
        float2 f2 = __half22float2(*reinterpret_cast<__half2*>(&hv.z));
        float2 f3 = __half22float2(*reinterpret_cast<__half2*>(&hv.w));
        float av[8] = {f0.x, f0.y, f1.x, f1.y, f2.x, f2.y, f3.x, f3.y};
#pragma unroll
        for (int i = 0; i < 8; i++) {
            float eac = ebr[i] + ea4.x * ewr[0][i] + ea4.y * ewr[1][i]
                               + ea4.z * ewr[2][i] + ea4.w * ewr[3][i];
            acc[i] += fmaxf(av[i] + eac, 0.0f);
        }
    }
    uint4 hout;
    hout.x = f2h2(acc[0], acc[1]);
    hout.y = f2h2(acc[2], acc[3]);
    hout.z = f2h2(acc[4], acc[5]);
    hout.w = f2h2(acc[6], acc[7]);
    *reinterpret_cast<uint4*>(&g_h016[(size_t)v * C_ + c0]) = hout;
}

// ---------------- final mean pool ----------------
__global__ void pool_kernel(float* __restrict__ out) {
    int b = blockIdx.x;
    int cix = threadIdx.x;
    float s = 0.0f;
    for (int n = 0; n < N_; n++) s += g_atoms[(b * N_ + n) * C_ + cix];
    out[b * C_ + cix] = s * (1.0f / (float)N_);
}

// ---------------- host launcher ----------------
extern "C" void kernel_launch(void* const* d_in, const int* in_sizes, int n_in,
                              void* d_out, int out_size) {
    const float* x      = (const float*)d_in[0];
    const float* eattr  = (const float*)d_in[1];
    const int*   eidx   = (const int*)d_in[2];
    const float* node_w = (const float*)d_in[4];
    const float* node_b = (const float*)d_in[5];
    const float* edge_w = (const float*)d_in[6];
    const float* edge_b = (const float*)d_in[7];
    const float* gw1    = (const float*)d_in[8];
    const float* gb1    = (const float*)d_in[9];
    const float* gw2    = (const float*)d_in[10];
    const float* gb2    = (const float*)d_in[11];
    const float* qw     = (const float*)d_in[12];
    const float* kw     = (const float*)d_in[13];
    const float* vw     = (const float*)d_in[14];
    const float* ow     = (const float*)d_in[15];
    const float* ob     = (const float*)d_in[16];
    const float* proj   = (const float*)d_in[17];
    const float* n1g    = (const float*)d_in[18];
    const float* n1b    = (const float*)d_in[19];
    const float* n2g    = (const float*)d_in[20];
    const float* n2b    = (const float*)d_in[21];
    const float* n3g    = (const float*)d_in[22];
    const float* n3b    = (const float*)d_in[23];
    const float* mw1    = (const float*)d_in[24];
    const float* mb1    = (const float*)d_in[25];
    const float* mw2    = (const float*)d_in[26];
    const float* mb2    = (const float*)d_in[27];

    const int* src = eidx;
    const int* dst = eidx + E_;

    float *p_atoms, *p_hloc, *p_out, *p_ctx;
    __half *p_atoms16, *p_h016, *p_t116, *p_out16, *p_qkv16, *p_att16;
    __half *p_wt, *p_projh, *p_kp, *p_qp;
    int* p_deg;
    cudaGetSymbolAddress((void**)&p_atoms,   g_atoms);
    cudaGetSymbolAddress((void**)&p_atoms16, g_atoms16);
    cudaGetSymbolAddress((void**)&p_h016,    g_h016);
    cudaGetSymbolAddress((void**)&p_t116,    g_t116);
    cudaGetSymbolAddress((void**)&p_hloc,    g_hloc);
    cudaGetSymbolAddress((void**)&p_out,     g_out);
    cudaGetSymbolAddress((void**)&p_out16,   g_out16);
    cudaGetSymbolAddress((void**)&p_qkv16,   g_qkv16);
    cudaGetSymbolAddress((void**)&p_att16,   g_att16);
    cudaGetSymbolAddress((void**)&p_ctx,     g_ctx);
    cudaGetSymbolAddress((void**)&p_wt,      g_wt);
    cudaGetSymbolAddress((void**)&p_projh,   g_projh);
    cudaGetSymbolAddress((void**)&p_kp,      g_kp);
    cudaGetSymbolAddress((void**)&p_qp,      g_qp);
    cudaGetSymbolAddress((void**)&p_deg,     g_deg);

    cudaFuncSetAttribute((const void*)mma_gemm<0, 4>, cudaFuncAttributeMaxDynamicSharedMemorySize, GEMM_SMEM_BYTES);
    cudaFuncSetAttribute((const void*)mma_gemm<1, 4>, cudaFuncAttributeMaxDynamicSharedMemorySize, GEMM_SMEM_BYTES);
    cudaFuncSetAttribute((const void*)mma_gemm<2, 4>, cudaFuncAttributeMaxDynamicSharedMemorySize, GEMM_SMEM_BYTES);
    cudaFuncSetAttribute((const void*)mma_gemm<2, 8>, cudaFuncAttributeMaxDynamicSharedMemorySize, GEMM_SMEM_BYTES);
    cudaFuncSetAttribute(phi_kernel, cudaFuncAttributeMaxDynamicSharedMemorySize, S1_SMEM_BYTES);
    cudaFuncSetAttribute(ctx_kernel, cudaFuncAttributeMaxDynamicSharedMemorySize, S2_SMEM_BYTES);
    cudaFuncSetAttribute(att_kernel, cudaFuncAttributeMaxDynamicSharedMemorySize, S3_SMEM_BYTES);

    WPtrs wp;
    wp.p[0] = gw1; wp.p[1] = gw2; wp.p[2] = qw; wp.p[3] = kw;
    wp.p[4] = vw;  wp.p[5] = ow;  wp.p[6] = mw1; wp.p[7] = mw2;
    transpose_kernel<<<dim3(16, 16, 40), dim3(32, 8)>>>(wp);                  // 1
    proj_prep_kernel<<<(L_ * 288 * 64 + 255) / 256, 256>>>(proj);             // 2
    node_embed_kernel<<<TN, 256>>>(x, node_w, node_b);                        // 3

    dim3 g1(TN / 64, 1), g2(TN / 64, 2), g3(TN / 64, 3);
    bool csr_built = false;

    for (int l = 0; l < L_; l++) {
        const __half* wt_l = p_wt + l * 655360;
        // QKV (fused, N=768, fp16 out) — first mma_gemm is kernel #4 for ncu
        mma_gemm<0, 4><<<g3, 256, GEMM_SMEM_BYTES>>>(p_atoms16, wt_l + 131072, nullptr, nullptr,
                                                     nullptr, nullptr, nullptr, nullptr, p_qkv16, 768);
        // Performer (3 mma stages)
        phi_kernel<<<dim3(512, 8), 256, S1_SMEM_BYTES>>>(p_qkv16, p_projh + l * 288 * 64, p_kp, p_qp);
        ctx_kernel<<<512, 256, S2_SMEM_BYTES>>>(p_kp, p_qkv16, p_ctx);
        att_kernel<<<512, 256, S3_SMEM_BYTES>>>(p_qp, p_ctx, p_att16);
        // CSR build (once)
        if (!csr_built) {
            cudaMemsetAsync(p_deg, 0, TN * sizeof(int));
            count_deg_kernel<<<E_ / 256, 256>>>(dst);
            scan_deg_kernel<<<1, 1024>>>();
            fill_adj_kernel<<<E_ / 256, 256>>>(dst);
            csr_built = true;
        }
        // GINE conv
        gine_kernel<<<TN / 8, 256>>>(src, eattr, edge_w, edge_b);
        mma_gemm<1, 4><<<g1, 256, GEMM_SMEM_BYTES>>>(p_h016, wt_l + 0, gb1 + l * C_, nullptr,
                                                     nullptr, nullptr, nullptr, nullptr, p_t116, 256);
        mma_gemm<2, 4><<<g1, 256, GEMM_SMEM_BYTES>>>(p_t116, wt_l + 65536, gb2 + l * C_, p_atoms,
                                                     nullptr, n1g + l * C_, n1b + l * C_,
                                                     p_hloc, nullptr, 256);
        // O-proj + LN + combine: out = LN(att@ow+ob+atoms) + hloc
        mma_gemm<2, 4><<<g1, 256, GEMM_SMEM_BYTES>>>(p_att16, wt_l + 327680, ob + l * C_, p_atoms,
                                                     p_hloc, n2g + l * C_, n2b + l * C_,
                                                     p_out, p_out16, 256);
        // FFN
        mma_gemm<1, 4><<<g2, 256, GEMM_SMEM_BYTES>>>(p_out16, wt_l + 393216, mb1 + l * 2 * C_, nullptr,
                                                     nullptr, nullptr, nullptr, nullptr, p_t116, 512);
        mma_gemm<2, 8><<<g1, 256, GEMM_SMEM_BYTES>>>(p_t116, wt_l + 524288, mb2 + l * C_, p_out,
                                                     nullptr, n3g + l * C_, n3b + l * C_,
                                                     p_atoms, p_atoms16, 256);
    }
    pool_kernel<<<B_, 256>>>((float*)d_out);
}

// round 12
// speedup vs baseline: 5.4798x; 1.0951x over previous
#include <cuda_runtime.h>
#include <cuda_fp16.h>
#include <math.h>
#include <stdint.h>

#define TN   32768
#define C_   256
#define B_   64
#define N_   512
#define H_   4
#define DH_  64
#define M_   266
#define E_   524288
#define L_   5

// ---------------- scratch ----------------
__device__ float  g_atoms[TN * C_];
__device__ __half g_atoms16[TN * C_];
__device__ __half g_h016[TN * C_];
__device__ __half g_t116[TN * 2 * C_];
__device__ float  g_hloc[TN * C_];
__device__ float  g_out[TN * C_];
__device__ __half g_out16[TN * C_];
__device__ __half g_qkv16[(size_t)TN * 3 * C_];
__device__ __half g_att16[TN * C_];
__device__ __half g_wt[L_ * 655360];          // transposed fp16 weights, [n][k]
__device__ __half g_projh[L_ * 288 * 64];     // fp16 proj, rows >=266 zero
__device__ __half g_kp[(size_t)H_ * TN * 288];
__device__ __half g_qp[(size_t)H_ * TN * 288];
__device__ float  g_ctx[2 * 256 * 80 * 320];  // [part][bh][d'][m]
__device__ int    g_deg[TN];
__device__ int    g_indptr[TN + 1];
__device__ int    g_cursor[TN];
__device__ int    g_esrc[E_];                 // CSR-ordered edge source
__device__ float4 g_ea4[E_];                  // CSR-ordered edge attributes

// ---------------- helpers ----------------
__device__ __forceinline__ float gelu_exact(float x) {
    return 0.5f * x * (1.0f + erff(x * 0.70710678118654752f));
}
__device__ __forceinline__ uint32_t f2h2(float a, float b) {
    __half2 h = __floats2half2_rn(a, b);
    return *reinterpret_cast<uint32_t*>(&h);
}
__device__ __forceinline__ uint32_t smem_u32(const void* p) {
    uint32_t a;
    asm("{ .reg .u64 t; cvta.to.shared.u64 t, %1; cvt.u32.u64 %0, t; }" : "=r"(a) : "l"(p));
    return a;
}
__device__ __forceinline__ void mma_f16_16x8x16(float* d, const uint32_t* a, const uint32_t* b) {
    asm volatile(
        "mma.sync.aligned.m16n8k16.row.col.f32.f16.f16.f32 "
        "{%0,%1,%2,%3}, {%4,%5,%6,%7}, {%8,%9}, {%0,%1,%2,%3};"
        : "+f"(d[0]), "+f"(d[1]), "+f"(d[2]), "+f"(d[3])
        : "r"(a[0]), "r"(a[1]), "r"(a[2]), "r"(a[3]), "r"(b[0]), "r"(b[1]));
}
__device__ __forceinline__ void ldsm_x4(uint32_t* r, uint32_t saddr) {
    asm volatile("ldmatrix.sync.aligned.m8n8.x4.shared.b16 {%0,%1,%2,%3}, [%4];"
                 : "=r"(r[0]), "=r"(r[1]), "=r"(r[2]), "=r"(r[3]) : "r"(saddr));
}
__device__ __forceinline__ void ldsm_x4_t(uint32_t* r, uint32_t saddr) {
    asm volatile("ldmatrix.sync.aligned.m8n8.x4.trans.shared.b16 {%0,%1,%2,%3}, [%4];"
                 : "=r"(r[0]), "=r"(r[1]), "=r"(r[2]), "=r"(r[3]) : "r"(saddr));
}
__device__ __forceinline__ void ldsm_x2_t(uint32_t* r, uint32_t saddr) {
    asm volatile("ldmatrix.sync.aligned.m8n8.x2.trans.shared.b16 {%0,%1}, [%2];"
                 : "=r"(r[0]), "=r"(r[1]) : "r"(saddr));
}
__device__ __forceinline__ void cp_async16(uint32_t saddr, const void* gptr) {
    asm volatile("cp.async.cg.shared.global [%0], [%1], 16;" :: "r"(saddr), "l"(gptr));
}
#define CP_COMMIT() asm volatile("cp.async.commit_group;" ::: "memory")
#define CP_WAIT0()  asm volatile("cp.async.wait_group 0;" ::: "memory")

// ---------------- weight transpose (once): WT[n*K+k] = half(W[k*N+n]) ----------------
struct WPtrs { const float* p[8]; };

__global__ void transpose_kernel(WPtrs wp) {
    int z = blockIdx.z;
    int t = z & 7, l = z >> 3;
    int K = (t == 7) ? 512 : 256;
    int N = (t == 6) ? 512 : 256;
    int n0 = blockIdx.x * 32, k0 = blockIdx.y * 32;
    if (n0 >= N || k0 >= K) return;
    const float* src = wp.p[t] + ((t >= 6) ? l * 131072 : l * 65536);
    int doff = (t < 6) ? t * 65536 : (t == 6 ? 393216 : 524288);
    __half* dst = g_wt + l * 655360 + doff;
    __shared__ float s[32][33];
    int tx = threadIdx.x, ty = threadIdx.y;
#pragma unroll
    for (int i = 0; i < 4; i++)
        s[ty + 8 * i][tx] = src[(k0 + ty + 8 * i) * N + n0 + tx];
    __syncthreads();
#pragma unroll
    for (int i = 0; i < 4; i++)
        dst[(n0 + ty + 8 * i) * K + k0 + tx] = __float2half_rn(s[tx][ty + 8 * i]);
}

// ---------------- proj -> fp16, padded to 288 rows ----------------
__global__ void proj_prep_kernel(const float* __restrict__ proj) {
    int idx = blockIdx.x * 256 + threadIdx.x;
    if (idx >= L_ * 288 * 64) return;
    int l = idx / (288 * 64);
    int r = idx - l * (288 * 64);
    int m = r >> 6, d = r & 63;
    g_projh[idx] = (m < M_) ? __float2half_rn(proj[(l * M_ + m) * 64 + d]) : __half(0.f);
}

// ---------------- fp16 mma GEMM, ldmatrix + cp.async, fused LN epilogue ----------------
#define GEMM_SMEM_MAIN  (2 * 9216 + 2 * 36864)
#define GEMM_SMEM_BYTES (GEMM_SMEM_MAIN + 512)

template <int MODE, int NK>
__global__ void __launch_bounds__(256, 2) mma_gemm(const __half* __restrict__ A,
                                                   const __half* __restrict__ WT,
                                                   const float* __restrict__ bias,
                                                   const float* __restrict__ res,
                                                   const float* __restrict__ add2,
                                                   const float* __restrict__ lng,
                                                   const float* __restrict__ lnb,
                                                   float* __restrict__ Out32,
                                                   __half* __restrict__ Out16,
                                                   int Ntot) {
    extern __shared__ uint32_t smw[];
    const int K = NK * 64;
    const int tid = threadIdx.x;
    const int lane = tid & 31, wid = tid >> 5;
    const int g = lane >> 2, t = lane & 3;
    const int wm = (wid & 1) * 32;
    const int wn = (wid >> 1) * 64;
    const int rowbase = blockIdx.x * 64;
    const int colbase = blockIdx.y * 256;
    const uint32_t sb = smem_u32(smw);

    const int l7 = lane & 7, l8 = (lane >> 3) & 1, l16 = (lane >> 4) & 1;
    uint32_t aAddr[2], bAddr[4];
#pragma unroll
    for (int mt = 0; mt < 2; mt++)
        aAddr[mt] = sb + (wm + mt * 16 + l7 + l8 * 8) * 144 + l16 * 16;
#pragma unroll
    for (int p = 0; p < 4; p++)
        bAddr[p] = sb + 18432 + (wn + p * 16 + l7 + l16 * 8) * 144 + l8 * 16;

    float acc[2][8][4];
#pragma unroll
    for (int mt = 0; mt < 2; mt++)
#pragma unroll
        for (int nt = 0; nt < 8; nt++)
#pragma unroll
            for (int j = 0; j < 4; j++) acc[mt][nt][j] = 0.0f;

#pragma unroll
    for (int i = 0; i < 2; i++) {
        int idx = tid + i * 256;
        int m = idx >> 3, c = idx & 7;
        cp_async16(sb + m * 144 + c * 16, A + (size_t)(rowbase + m) * K + c * 8);
    }
#pragma unroll
    for (int i = 0; i < 8; i++) {
        int idx = tid + i * 256;
        int n = idx >> 3, c = idx & 7;
        cp_async16(sb + 18432 + n * 144 + c * 16, WT + (size_t)(colbase + n) * K + c * 8);
    }
    CP_COMMIT();
    CP_WAIT0();
    __syncthreads();

#pragma unroll
    for (int kb = 0; kb < NK; kb++) {
        const int cur = kb & 1;
        const bool nxt = (kb + 1 < NK);
        if (nxt) {
            int k0g = (kb + 1) * 64;
            int sB = cur ^ 1;
#pragma unroll
            for (int i = 0; i < 2; i++) {
                int idx = tid + i * 256;
                int m = idx >> 3, c = idx & 7;
                cp_async16(sb + sB * 9216 + m * 144 + c * 16,
                           A + (size_t)(rowbase + m) * K + k0g + c * 8);
            }
#pragma unroll
            for (int i = 0; i < 8; i++) {
                int idx = tid + i * 256;
                int n = idx >> 3, c = idx & 7;
                cp_async16(sb + 18432 + sB * 36864 + n * 144 + c * 16,
                           WT + (size_t)(colbase + n) * K + k0g + c * 8);
            }
            CP_COMMIT();
        }
        const uint32_t aoff = cur * 9216, boff = cur * 36864;
#pragma unroll
        for (int ks = 0; ks < 4; ks++) {
            uint32_t ar[2][4], br[4][4];
            ldsm_x4(ar[0], aAddr[0] + aoff + ks * 32);
            ldsm_x4(ar[1], aAddr[1] + aoff + ks * 32);
#pragma unroll
            for (int p = 0; p < 4; p++) ldsm_x4(br[p], bAddr[p] + boff + ks * 32);
#pragma unroll
            for (int mt = 0; mt < 2; mt++)
#pragma unroll
                for (int p = 0; p < 4; p++) {
                    mma_f16_16x8x16(acc[mt][2 * p],     ar[mt], &br[p][0]);
                    mma_f16_16x8x16(acc[mt][2 * p + 1], ar[mt], &br[p][2]);
                }
        }
        if (nxt) {
            CP_WAIT0();
            __syncthreads();
        }
    }

    if (MODE <= 1) {
#pragma unroll
        for (int mt = 0; mt < 2; mt++) {
            int r0 = rowbase + wm + mt * 16 + g;
#pragma unroll
            for (int nt = 0; nt < 8; nt++) {
                int col = colbase + wn + nt * 8 + 2 * t;
                float b0 = 0.0f, b1 = 0.0f;
                if (bias) { b0 = bias[col]; b1 = bias[col + 1]; }
                float v0 = acc[mt][nt][0] + b0, v1 = acc[mt][nt][1] + b1;
                float v2 = acc[mt][nt][2] + b0, v3 = acc[mt][nt][3] + b1;
                if (MODE == 1) {
                    v0 = gelu_exact(v0); v1 = gelu_exact(v1);
                    v2 = gelu_exact(v2); v3 = gelu_exact(v3);
                }
                *reinterpret_cast<uint32_t*>(&Out16[(size_t)r0 * Ntot + col]) = f2h2(v0, v1);
                *reinterpret_cast<uint32_t*>(&Out16[(size_t)(r0 + 8) * Ntot + col]) = f2h2(v2, v3);
            }
        }
    } else {
        float* sums = (float*)(smw + GEMM_SMEM_MAIN / 4);   // 64 rows x {s1,s2}
        if (tid < 128) sums[tid] = 0.0f;
        float gg[8][2], bb[8][2];
#pragma unroll
        for (int mt = 0; mt < 2; mt++) {
            int r0 = rowbase + wm + mt * 16 + g;
#pragma unroll
            for (int nt = 0; nt < 8; nt++) {
                int col = wn + nt * 8 + 2 * t;
                float b0 = bias[col], b1 = bias[col + 1];
                float2 r01 = *reinterpret_cast<const float2*>(&res[(size_t)r0 * 256 + col]);
                float2 r23 = *reinterpret_cast<const float2*>(&res[(size_t)(r0 + 8) * 256 + col]);
                acc[mt][nt][0] += b0 + r01.x; acc[mt][nt][1] += b1 + r01.y;
                acc[mt][nt][2] += b0 + r23.x; acc[mt][nt][3] += b1 + r23.y;
            }
        }
        __syncthreads();
#pragma unroll
        for (int mt = 0; mt < 2; mt++)
#pragma unroll
            for (int rh = 0; rh < 2; rh++) {
                float s1 = 0.0f, s2 = 0.0f;
#pragma unroll
                for (int nt = 0; nt < 8; nt++) {
                    float v0 = acc[mt][nt][2 * rh], v1 = acc[mt][nt][2 * rh + 1];
                    s1 += v0 + v1; s2 += v0 * v0 + v1 * v1;
                }
                s1 += __shfl_xor_sync(0xffffffffu, s1, 1);
                s1 += __shfl_xor_sync(0xffffffffu, s1, 2);
                s2 += __shfl_xor_sync(0xffffffffu, s2, 1);
                s2 += __shfl_xor_sync(0xffffffffu, s2, 2);
                if (t == 0) {
                    int rl = wm + mt * 16 + g + rh * 8;
                    atomicAdd(&sums[2 * rl], s1);
                    atomicAdd(&sums[2 * rl + 1], s2);
                }
            }
#pragma unroll
        for (int nt = 0; nt < 8; nt++) {
            int col = wn + nt * 8 + 2 * t;
            gg[nt][0] = lng[col]; gg[nt][1] = lng[col + 1];
            bb[nt][0] = lnb[col]; bb[nt][1] = lnb[col + 1];
        }
        __syncthreads();
#pragma unroll
        for (int mt = 0; mt < 2; mt++) {
#pragma unroll
            for (int rh = 0; rh < 2; rh++) {
                int rl = wm + mt * 16 + g + rh * 8;
                int grow = rowbase + rl;
                float mean = sums[2 * rl] * (1.0f / 256.0f);
                float var = sums[2 * rl + 1] * (1.0f / 256.0f) - mean * mean;
                float rstd = rsqrtf(var + 1e-5f);
#pragma unroll
                for (int nt = 0; nt < 8; nt++) {
                    int col = wn + nt * 8 + 2 * t;
                    float y0 = (acc[mt][nt][2 * rh] - mean) * rstd * gg[nt][0] + bb[nt][0];
                    float y1 = (acc[mt][nt][2 * rh + 1] - mean) * rstd * gg[nt][1] + bb[nt][1];
                    if (add2) {
                        float2 a2 = *reinterpret_cast<const float2*>(&add2[(size_t)grow * 256 + col]);
                        y0 += a2.x; y1 += a2.y;
                    }
                    *reinterpret_cast<float2*>(&Out32[(size_t)grow * 256 + col]) = make_float2(y0, y1);
                    if (Out16)
                        *reinterpret_cast<uint32_t*>(&Out16[(size_t)grow * 256 + col]) = f2h2(y0, y1);
                }
            }
        }
    }
}

// ---------------- Performer stage 1: kp/qp = relu(X_h @ projT)+eps, fp16 ----------------
#define S1_SMEM_BYTES ((2304 + 10368) * 4)

__global__ void __launch_bounds__(256) phi_kernel(const __half* __restrict__ QKV,
                                                  const __half* __restrict__ projh_l,
                                                  __half* __restrict__ KP,
                                                  __half* __restrict__ QP) {
    extern __shared__ uint32_t sw[];
    uint32_t* As = sw;           // 64 x 36 words
    uint32_t* Bs = sw + 2304;    // 288 x 36 words
    const int tid = threadIdx.x;
    const int lane = tid & 31, wid = tid >> 5;
    const int g = lane >> 2, t = lane & 3;
    const int wm = (wid & 1) * 32;
    const int wn = (wid >> 1) * 72;
    const int rowbase = blockIdx.x * 64;
    const int h = blockIdx.y & 3;
    const int isq = blockIdx.y >> 2;
    const __half* Ah = QKV + (isq ? h * 64 : 256 + h * 64);
    __half* outp = (isq ? QP : KP) + (size_t)h * TN * 288;
    const uint32_t sbA = smem_u32(As);

#pragma unroll
    for (int i = 0; i < 2; i++) {
        int idx = tid + i * 256;
        int m = idx >> 3, c = idx & 7;
        cp_async16(sbA + m * 144 + c * 16, Ah + (size_t)(rowbase + m) * 768 + c * 8);
    }
    CP_COMMIT();
    const uint32_t* pb = (const uint32_t*)projh_l;
#pragma unroll
    for (int i = 0; i < 36; i++) {
        int w = tid + i * 256;
        Bs[(w >> 5) * 36 + (w & 31)] = pb[w];
    }
    CP_WAIT0();
    __syncthreads();

    float acc[2][9][4];
#pragma unroll
    for (int mt = 0; mt < 2; mt++)
#pragma unroll
        for (int nt = 0; nt < 9; nt++)
#pragma unroll
            for (int j = 0; j < 4; j++) acc[mt][nt][j] = 0.0f;

#pragma unroll
    for (int ks = 0; ks < 4; ks++) {
        int k0 = ks * 8;
        uint32_t af[2][4], bf[9][2];
#pragma unroll
        for (int mt = 0; mt < 2; mt++) {
            int r0 = wm + mt * 16 + g;
            af[mt][0] = As[r0 * 36 + k0 + t];
            af[mt][1] = As[(r0 + 8) * 36 + k0 + t];
            af[mt][2] = As[r0 * 36 + k0 + t + 4];
            af[mt][3] = As[(r0 + 8) * 36 + k0 + t + 4];
        }
#pragma unroll
        for (int nt = 0; nt < 9; nt++) {
            int n0 = wn + nt * 8 + g;
            bf[nt][0] = Bs[n0 * 36 + k0 + t];
            bf[nt][1] = Bs[n0 * 36 + k0 + t + 4];
        }
#pragma unroll
        for (int mt = 0; mt < 2; mt++)
#pragma unroll
            for (int nt = 0; nt < 9; nt++)
                mma_f16_16x8x16(acc[mt][nt], af[mt], bf[nt]);
    }

#pragma unroll
    for (int mt = 0; mt < 2; mt++) {
        int r = rowbase + wm + mt * 16 + g;
#pragma unroll
        for (int nt = 0; nt < 9; nt++) {
            int c0 = wn + nt * 8 + 2 * t;
            float v0 = fmaxf(acc[mt][nt][0], 0.0f) + 1e-3f;
            float v1 = fmaxf(acc[mt][nt][1], 0.0f) + 1e-3f;
            float v2 = fmaxf(acc[mt][nt][2], 0.0f) + 1e-3f;
            float v3 = fmaxf(acc[mt][nt][3], 0.0f) + 1e-3f;
            if (c0 >= M_) { v0 = 0.0f; v2 = 0.0f; }
            if (c0 + 1 >= M_) { v1 = 0.0f; v3 = 0.0f; }
            *reinterpret_cast<uint32_t*>(&outp[(size_t)r * 288 + c0]) = f2h2(v0, v1);
            *reinterpret_cast<uint32_t*>(&outp[(size_t)(r + 8) * 288 + c0]) = f2h2(v2, v3);
        }
    }
}

// ---------------- Performer stage 2: ctx partials via ldmatrix.trans ----------------
// kp_s: 64 rows x 336 halves (cols 288..335 zero)  -> A^T source
// vs_s: 64 rows x 88 halves (col 64 = 1, 65..87 = 0) -> B source
#define S2_KP_STRIDE 336
#define S2_VS_STRIDE 88
#define S2_VS_OFF    (64 * S2_KP_STRIDE * 2)
#define S2_SMEM_BYTES (64 * S2_KP_STRIDE * 2 + 64 * S2_VS_STRIDE * 2)

__global__ void __launch_bounds__(256) ctx_kernel(const __half* __restrict__ KP,
                                                  const __half* __restrict__ QKV,
                                                  float* __restrict__ CTX) {
    extern __shared__ uint32_t sw[];
    __half* kp_h = (__half*)sw;
    __half* vs_h = (__half*)((char*)sw + S2_VS_OFF);
    const int tid = threadIdx.x;
    const int lane = tid & 31, wid = tid >> 5;
    const int g = lane >> 2, t = lane & 3;
    const int wm = (wid & 3) * 80;
    const int wn = (wid >> 2) * 40;
    const int part = blockIdx.x >> 8;
    const int bh = blockIdx.x & 255;
    const int b = bh >> 2, h = bh & 3;
    const uint32_t sb = smem_u32(sw);
    const int l7 = lane & 7, l8 = (lane >> 3) & 1, l16 = (lane >> 4) & 1;

    // one-time pads
    for (int i = tid; i < 64 * 48; i += 256) {           // kp cols 288..335
        int n = i / 48, c = 288 + i % 48;
        kp_h[n * S2_KP_STRIDE + c] = __float2half(0.0f);
    }
    for (int i = tid; i < 64 * 24; i += 256) {           // vs cols 64..87
        int n = i / 24, c = 64 + i % 24;
        vs_h[n * S2_VS_STRIDE + c] = __float2half(c == 64 ? 1.0f : 0.0f);
    }

    // fragment base addresses
    // A (trans): addr = (k_row)*336*2 + (m_col)*2 ; k_row = ks*16 + l16*8 + l7 ; m_col = wm+mt*16+l8*8
    uint32_t aBase = sb + ((l16 * 8 + l7) * S2_KP_STRIDE + wm + l8 * 8) * 2;
    // B (trans, x2): k_row = ks*16 + l8b*8 + l7b (lane&15) ; n_col = wn + nt*8
    int bl = lane & 15;
    uint32_t bBase = sb + S2_VS_OFF + (((bl >> 3) * 8 + (bl & 7)) * S2_VS_STRIDE + wn) * 2;

    float acc[5][5][4];
#pragma unroll
    for (int mt = 0; mt < 5; mt++)
#pragma unroll
        for (int nt = 0; nt < 5; nt++)
#pragma unroll
            for (int j = 0; j < 4; j++) acc[mt][nt][j] = 0.0f;

    const __half* kp_g = KP + (size_t)h * TN * 288;

    for (int c = 0; c < 4; c++) {
        __syncthreads();
        int base = b * 512 + (part * 4 + c) * 64;
        // stage kp rows [n][288] via cp.async
#pragma unroll
        for (int i = 0; i < 9; i++) {
            int idx = tid + i * 256;                     // < 2304 = 64*36
            int n = idx / 36, cc = idx - n * 36;
            cp_async16(sb + (n * S2_KP_STRIDE + cc * 8) * 2,
                       kp_g + (size_t)(base + n) * 288 + cc * 8);
        }
        // stage V rows [n][64]
#pragma unroll
        for (int i = 0; i < 2; i++) {
            int idx = tid + i * 256;                     // < 512 = 64*8
            int n = idx >> 3, cc = idx & 7;
            cp_async16(sb + S2_VS_OFF + (n * S2_VS_STRIDE + cc * 8) * 2,
                       QKV + (size_t)(base + n) * 768 + 512 + h * 64 + cc * 8);
        }
        CP_COMMIT();
        CP_WAIT0();
        __syncthreads();
#pragma unroll
        for (int ks = 0; ks < 4; ks++) {
            uint32_t af[5][4], bf[5][2];
            uint32_t aK = aBase + ks * 16 * S2_KP_STRIDE * 2;
            uint32_t bK = bBase + ks * 16 * S2_VS_STRIDE * 2;
#pragma unroll
            for (int mt = 0; mt < 5; mt++) ldsm_x4_t(af[mt], aK + mt * 32);
#pragma unroll
            for (int nt = 0; nt < 5; nt++) ldsm_x2_t(bf[nt], bK + nt * 16);
#pragma unroll
            for (int mt = 0; mt < 5; mt++)
#pragma unroll
                for (int nt = 0; nt < 5; nt++)
                    mma_f16_16x8x16(acc[mt][nt], af[mt], bf[nt]);
        }
    }

    float* outc = CTX + ((size_t)part * 256 + bh) * 80 * 320;
#pragma unroll
    for (int mt = 0; mt < 5; mt++) {
        int m0 = wm + mt * 16 + g;
#pragma unroll
        for (int nt = 0; nt < 5; nt++) {
            int c0 = wn + nt * 8 + 2 * t;
            outc[(size_t)c0 * 320 + m0] = acc[mt][nt][0];
            outc[(size_t)(c0 + 1) * 320 + m0] = acc[mt][nt][1];
            outc[(size_t)c0 * 320 + m0 + 8] = acc[mt][nt][2];
            outc[(size_t)(c0 + 1) * 320 + m0 + 8] = acc[mt][nt][3];
        }
    }
}

// ---------------- Performer stage 3: att' = qp @ (ctx0+ctx1); normalize; fp16 ----------------
#define S3_W_CTX (80 * 164)
#define S3_W_AS  (64 * 148)
#define S3_W_ATT (64 * 80)
#define S3_SMEM_BYTES ((S3_W_CTX + S3_W_AS + S3_W_ATT) * 4)

__global__ void __launch_bounds__(256) att_kernel(const __half* __restrict__ QP,
                                                  const float* __restrict__ CTX,
                                                  __half* __restrict__ Att) {
    extern __shared__ uint32_t sw[];
    uint32_t* ctxT = sw;                              // 80 x 164 words
    uint32_t* As = sw + S3_W_CTX;                     // 64 x 148 words
    float* att_s = (float*)(sw + S3_W_CTX + S3_W_AS); // 64 x 80
    const int tid = threadIdx.x;
    const int lane = tid & 31, wid = tid >> 5;
    const int g = lane >> 2, t = lane & 3;
    const int wm = (wid & 3) * 16;
    const int wn = (wid >> 2) * 40;
    const int cta = blockIdx.x;
    const int bh = cta >> 1, half = cta & 1;
    const int b = bh >> 2, h = bh & 3;

    const float* cg0 = CTX + (size_t)bh * 80 * 320;
    const float* cg1 = CTX + ((size_t)256 + bh) * 80 * 320;
#pragma unroll
    for (int i = 0; i < 50; i++) {
        int idx = tid + i * 256;
        int d = idx / 160, m2 = idx - d * 160;
        size_t o = (size_t)d * 320 + m2 * 2;
        float2 v0 = *reinterpret_cast<const float2*>(&cg0[o]);
        float2 v1 = *reinterpret_cast<const float2*>(&cg1[o]);
        ctxT[d * 164 + m2] = f2h2(v0.x + v1.x, v0.y + v1.y);
    }
    const uint32_t* qp2 = (const uint32_t*)(QP + (size_t)h * TN * 288);
    const int rowg0 = b * 512 + half * 256;

    for (int ch = 0; ch < 4; ch++) {
        __syncthreads();
        int rbase = rowg0 + ch * 64;
#pragma unroll
        for (int i = 0; i < 36; i++) {
            int idx = tid + i * 256;
            int n = idx / 144, m2 = idx - n * 144;
            As[n * 148 + m2] = qp2[(size_t)(rbase + n) * 144 + m2];
        }
        __syncthreads();
        float acc[5][4];
#pragma unroll
        for (int nt = 0; nt < 5; nt++)
#pragma unroll
            for (int j = 0; j < 4; j++) acc[nt][j] = 0.0f;
#pragma unroll
        for (int ks = 0; ks < 17; ks++) {
            int k0 = ks * 8;
            uint32_t af[4], bf[5][2];
            int r0 = wm + g;
            af[0] = As[r0 * 148 + k0 + t];
            af[1] = As[(r0 + 8) * 148 + k0 + t];
            af[2] = As[r0 * 148 + k0 + t + 4];
            af[3] = As[(r0 + 8) * 148 + k0 + t + 4];
#pragma unroll
            for (int nt = 0; nt < 5; nt++) {
                int n0 = wn + nt * 8 + g;
                bf[nt][0] = ctxT[n0 * 164 + k0 + t];
                bf[nt][1] = ctxT[n0 * 164 + k0 + t + 4];
            }
#pragma unroll
            for (int nt = 0; nt < 5; nt++)
                mma_f16_16x8x16(acc[nt], af, bf[nt]);
        }
#pragma unroll
        for (int nt = 0; nt < 5; nt++) {
            int c0 = wn + nt * 8 + 2 * t;
            att_s[(wm + g) * 80 + c0] = acc[nt][0];
            att_s[(wm + g) * 80 + c0 + 1] = acc[nt][1];
            att_s[(wm + g + 8) * 80 + c0] = acc[nt][2];
            att_s[(wm + g + 8) * 80 + c0 + 1] = acc[nt][3];
        }
        __syncthreads();
#pragma unroll
        for (int i = 0; i < 16; i++) {
            int idx = tid + i * 256;
            int n = idx >> 6, d = idx & 63;
            float den = att_s[n * 80 + 64];
            Att[(size_t)(rbase + n) * 256 + h * 64 + d] = __float2half_rn(att_s[n * 80 + d] / den);
        }
    }
}

// ---------------- node embedding ----------------
__global__ void node_embed_kernel(const float* __restrict__ x,
                                  const float* __restrict__ w,
                                  const float* __restrict__ b) {
    __shared__ float lx[11];
    int row = blockIdx.x;
    int t = threadIdx.x;
    if (t < 11) lx[t] = log1pf(x[row * 11 + t]);
    __syncthreads();
    float s = b[t];
#pragma unroll
    for (int j = 0; j < 11; j++) s += lx[j] * w[j * C_ + t];
    g_atoms[row * C_ + t] = s;
    g_atoms16[row * C_ + t] = __float2half_rn(s);
}

// ---------------- CSR build ----------------
__global__ void count_deg_kernel(const int* __restrict__ dst) {
    int e = blockIdx.x * blockDim.x + threadIdx.x;
    if (e < E_) atomicAdd(&g_deg[dst[e]], 1);
}
__global__ void scan_deg_kernel() {
    __shared__ int sh[1024];
    __shared__ int carry;
    int t = threadIdx.x;
    if (t == 0) carry = 0;
    __syncthreads();
    for (int base = 0; base < TN; base += 1024) {
        int v = g_deg[base + t];
        sh[t] = v;
        __syncthreads();
        for (int off = 1; off < 1024; off <<= 1) {
            int add = (t >= off) ? sh[t - off] : 0;
            __syncthreads();
            sh[t] += add;
            __syncthreads();
        }
        int ip = carry + sh[t] - v;
        g_indptr[base + t] = ip;
        g_cursor[base + t] = ip;
        __syncthreads();
        if (t == 0) carry += sh[1023];
        __syncthreads();
    }
    if (t == 0) g_indptr[TN] = carry;
}
__global__ void fill_adj_kernel(const int* __restrict__ src,
                                const int* __restrict__ dst,
                                const float* __restrict__ eattr) {
    int e = blockIdx.x * blockDim.x + threadIdx.x;
    if (e < E_) {
        int p = atomicAdd(&g_cursor[dst[e]], 1);
        g_esrc[p] = src[e];
        g_ea4[p] = *reinterpret_cast<const float4*>(&eattr[e * 4]);
    }
}

// ---------------- GINE aggregation: CSR payloads + 2-edge unroll ----------------
__global__ void __launch_bounds__(256) gine_kernel(const float* __restrict__ ew,
                                                   const float* __restrict__ eb) {
    int tid = threadIdx.x;
    int warp = tid >> 5, lane = tid & 31;
    int v = blockIdx.x * 8 + warp;
    const int c0 = lane * 8;

    float ewr[4][8], ebr[8];
#pragma unroll
    for (int j = 0; j < 4; j++) {
        float4 w0 = *reinterpret_cast<const float4*>(&ew[j * C_ + c0]);
        float4 w1 = *reinterpret_cast<const float4*>(&ew[j * C_ + c0 + 4]);
        ewr[j][0] = w0.x; ewr[j][1] = w0.y; ewr[j][2] = w0.z; ewr[j][3] = w0.w;
        ewr[j][4] = w1.x; ewr[j][5] = w1.y; ewr[j][6] = w1.z; ewr[j][7] = w1.w;
    }
    {
        float4 b0 = *reinterpret_cast<const float4*>(&eb[c0]);
        float4 b1 = *reinterpret_cast<const float4*>(&eb[c0 + 4]);
        ebr[0] = b0.x; ebr[1] = b0.y; ebr[2] = b0.z; ebr[3] = b0.w;
        ebr[4] = b1.x; ebr[5] = b1.y; ebr[6] = b1.z; ebr[7] = b1.w;
    }

    float acc[8];
    {
        float4 a0 = *reinterpret_cast<const float4*>(&g_atoms[(size_t)v * C_ + c0]);
        float4 a1 = *reinterpret_cast<const float4*>(&g_atoms[(size_t)v * C_ + c0 + 4]);
        acc[0] = a0.x; acc[1] = a0.y; acc[2] = a0.z; acc[3] = a0.w;
        acc[4] = a1.x; acc[5] = a1.y; acc[6] = a1.z; acc[7] = a1.w;
    }

    int p0 = g_indptr[v], p1 = g_indptr[v + 1];
    int p = p0;
    for (; p + 1 < p1; p += 2) {
        int sA = g_esrc[p], sB = g_esrc[p + 1];
        float4 eaA = g_ea4[p], eaB = g_ea4[p + 1];
        uint4 hA = *reinterpret_cast<const uint4*>(&g_atoms16[(size_t)sA * C_ + c0]);
        uint4 hB = *reinterpret_cast<const uint4*>(&g_atoms16[(size_t)sB * C_ + c0]);
        float2 fa[4] = {__half22float2(*reinterpret_cast<__half2*>(&hA.x)),
                        __half22float2(*reinterpret_cast<__half2*>(&hA.y)),
                        __half22float2(*reinterpret_cast<__half2*>(&hA.z)),
                        __half22float2(*reinterpret_cast<__half2*>(&hA.w))};
        float2 fb[4] = {__half22float2(*reinterpret_cast<__half2*>(&hB.x)),
                        __half22float2(*reinterpret_cast<__half2*>(&hB.y)),
                        __half22float2(*reinterpret_cast<__half2*>(&hB.z)),
                        __half22float2(*reinterpret_cast<__half2*>(&hB.w))};
        float avA[8] = {fa[0].x, fa[0].y, fa[1].x, fa[1].y, fa[2].x, fa[2].y, fa[3].x, fa[3].y};
        float avB[8] = {fb[0].x, fb[0].y, fb[1].x, fb[1].y, fb[2].x, fb[2].y, fb[3].x, fb[3].y};
#pragma unroll
        for (int i = 0; i < 8; i++) {
            float eacA = ebr[i] + eaA.x * ewr[0][i] + eaA.y * ewr[1][i]
                                + eaA.z * ewr[2][i] + eaA.w * ewr[3][i];
            acc[i] += fmaxf(avA[i] + eacA, 0.0f);
        }
#pragma unroll
        for (int i = 0; i < 8; i++) {
            float eacB = ebr[i] + eaB.x * ewr[0][i] + eaB.y * ewr[1][i]
                                + eaB.z * ewr[2][i] + eaB.w * ewr[3][i];
            acc[i] += fmaxf(avB[i] + eacB, 0.0f);
        }
    }
    if (p < p1) {
        int s = g_esrc[p];
        float4 ea4 = g_ea4[p];
        uint4 hv = *reinterpret_cast<const uint4*>(&g_atoms16[(size_t)s * C_ + c0]);
        float2 f0 = __half22float2(*reinterpret_cast<__half2*>(&hv.x));
        float2 f1 = __half22float2(*reinterpret_cast<__half2*>(&hv.y));
        float2 f2 = __half22float2(*reinterpret_cast<__half2*>(&hv.z));
        float2 f3 = __half22float2(*reinterpret_cast<__half2*>(&hv.w));
        float av[8] = {f0.x, f0.y, f1.x, f1.y, f2.x, f2.y, f3.x, f3.y};
#pragma unroll
        for (int i = 0; i < 8; i++) {
            float eac = ebr[i] + ea4.x * ewr[0][i] + ea4.y * ewr[1][i]
                               + ea4.z * ewr[2][i] + ea4.w * ewr[3][i];
            acc[i] += fmaxf(av[i] + eac, 0.0f);
        }
    }
    uint4 hout;
    hout.x = f2h2(acc[0], acc[1]);
    hout.y = f2h2(acc[2], acc[3]);
    hout.z = f2h2(acc[4], acc[5]);
    hout.w = f2h2(acc[6], acc[7]);
    *reinterpret_cast<uint4*>(&g_h016[(size_t)v * C_ + c0]) = hout;
}

// ---------------- final mean pool ----------------
__global__ void pool_kernel(float* __restrict__ out) {
    int b = blockIdx.x;
    int cix = threadIdx.x;
    float s = 0.0f;
    for (int n = 0; n < N_; n++) s += g_atoms[(b * N_ + n) * C_ + cix];
    out[b * C_ + cix] = s * (1.0f / (float)N_);
}

// ---------------- host launcher ----------------
extern "C" void kernel_launch(void* const* d_in, const int* in_sizes, int n_in,
                              void* d_out, int out_size) {
    const float* x      = (const float*)d_in[0];
    const float* eattr  = (const float*)d_in[1];
    const int*   eidx   = (const int*)d_in[2];
    const float* node_w = (const float*)d_in[4];
    const float* node_b = (const float*)d_in[5];
    const float* edge_w = (const float*)d_in[6];
    const float* edge_b = (const float*)d_in[7];
    const float* gw1    = (const float*)d_in[8];
    const float* gb1    = (const float*)d_in[9];
    const float* gw2    = (const float*)d_in[10];
    const float* gb2    = (const float*)d_in[11];
    const float* qw     = (const float*)d_in[12];
    const float* kw     = (const float*)d_in[13];
    const float* vw     = (const float*)d_in[14];
    const float* ow     = (const float*)d_in[15];
    const float* ob     = (const float*)d_in[16];
    const float* proj   = (const float*)d_in[17];
    const float* n1g    = (const float*)d_in[18];
    const float* n1b    = (const float*)d_in[19];
    const float* n2g    = (const float*)d_in[20];
    const float* n2b    = (const float*)d_in[21];
    const float* n3g    = (const float*)d_in[22];
    const float* n3b    = (const float*)d_in[23];
    const float* mw1    = (const float*)d_in[24];
    const float* mb1    = (const float*)d_in[25];
    const float* mw2    = (const float*)d_in[26];
    const float* mb2    = (const float*)d_in[27];

    const int* src = eidx;
    const int* dst = eidx + E_;

    float *p_atoms, *p_hloc, *p_out, *p_ctx;
    __half *p_atoms16, *p_h016, *p_t116, *p_out16, *p_qkv16, *p_att16;
    __half *p_wt, *p_projh, *p_kp, *p_qp;
    int* p_deg;
    cudaGetSymbolAddress((void**)&p_atoms,   g_atoms);
    cudaGetSymbolAddress((void**)&p_atoms16, g_atoms16);
    cudaGetSymbolAddress((void**)&p_h016,    g_h016);
    cudaGetSymbolAddress((void**)&p_t116,    g_t116);
    cudaGetSymbolAddress((void**)&p_hloc,    g_hloc);
    cudaGetSymbolAddress((void**)&p_out,     g_out);
    cudaGetSymbolAddress((void**)&p_out16,   g_out16);
    cudaGetSymbolAddress((void**)&p_qkv16,   g_qkv16);
    cudaGetSymbolAddress((void**)&p_att16,   g_att16);
    cudaGetSymbolAddress((void**)&p_ctx,     g_ctx);
    cudaGetSymbolAddress((void**)&p_wt,      g_wt);
    cudaGetSymbolAddress((void**)&p_projh,   g_projh);
    cudaGetSymbolAddress((void**)&p_kp,      g_kp);
    cudaGetSymbolAddress((void**)&p_qp,      g_qp);
    cudaGetSymbolAddress((void**)&p_deg,     g_deg);

    cudaFuncSetAttribute((const void*)mma_gemm<0, 4>, cudaFuncAttributeMaxDynamicSharedMemorySize, GEMM_SMEM_BYTES);
    cudaFuncSetAttribute((const void*)mma_gemm<1, 4>, cudaFuncAttributeMaxDynamicSharedMemorySize, GEMM_SMEM_BYTES);
    cudaFuncSetAttribute((const void*)mma_gemm<2, 4>, cudaFuncAttributeMaxDynamicSharedMemorySize, GEMM_SMEM_BYTES);
    cudaFuncSetAttribute((const void*)mma_gemm<2, 8>, cudaFuncAttributeMaxDynamicSharedMemorySize, GEMM_SMEM_BYTES);
    cudaFuncSetAttribute(phi_kernel, cudaFuncAttributeMaxDynamicSharedMemorySize, S1_SMEM_BYTES);
    cudaFuncSetAttribute(ctx_kernel, cudaFuncAttributeMaxDynamicSharedMemorySize, S2_SMEM_BYTES);
    cudaFuncSetAttribute(att_kernel, cudaFuncAttributeMaxDynamicSharedMemorySize, S3_SMEM_BYTES);

    WPtrs wp;
    wp.p[0] = gw1; wp.p[1] = gw2; wp.p[2] = qw; wp.p[3] = kw;
    wp.p[4] = vw;  wp.p[5] = ow;  wp.p[6] = mw1; wp.p[7] = mw2;
    transpose_kernel<<<dim3(16, 16, 40), dim3(32, 8)>>>(wp);                  // 1
    proj_prep_kernel<<<(L_ * 288 * 64 + 255) / 256, 256>>>(proj);             // 2
    node_embed_kernel<<<TN, 256>>>(x, node_w, node_b);                        // 3

    dim3 g1(TN / 64, 1), g2(TN / 64, 2), g3(TN / 64, 3);
    bool csr_built = false;

    for (int l = 0; l < L_; l++) {
        const __half* wt_l = p_wt + l * 655360;
        // QKV (fused, N=768, fp16 out) — first mma_gemm is kernel #4 for ncu
        mma_gemm<0, 4><<<g3, 256, GEMM_SMEM_BYTES>>>(p_atoms16, wt_l + 131072, nullptr, nullptr,
                                                     nullptr, nullptr, nullptr, nullptr, p_qkv16, 768);
        // Performer (3 mma stages)
        phi_kernel<<<dim3(512, 8), 256, S1_SMEM_BYTES>>>(p_qkv16, p_projh + l * 288 * 64, p_kp, p_qp);
        ctx_kernel<<<512, 256, S2_SMEM_BYTES>>>(p_kp, p_qkv16, p_ctx);
        att_kernel<<<512, 256, S3_SMEM_BYTES>>>(p_qp, p_ctx, p_att16);
        // CSR build (once)
        if (!csr_built) {
            cudaMemsetAsync(p_deg, 0, TN * sizeof(int));
            count_deg_kernel<<<E_ / 256, 256>>>(dst);
            scan_deg_kernel<<<1, 1024>>>();
            fill_adj_kernel<<<E_ / 256, 256>>>(src, dst, eattr);
            csr_built = true;
        }
        // GINE conv
        gine_kernel<<<TN / 8, 256>>>(edge_w, edge_b);
        mma_gemm<1, 4><<<g1, 256, GEMM_SMEM_BYTES>>>(p_h016, wt_l + 0, gb1 + l * C_, nullptr,
                                                     nullptr, nullptr, nullptr, nullptr, p_t116, 256);
        mma_gemm<2, 4><<<g1, 256, GEMM_SMEM_BYTES>>>(p_t116, wt_l + 65536, gb2 + l * C_, p_atoms,
                                                     nullptr, n1g + l * C_, n1b + l * C_,
                                                     p_hloc, nullptr, 256);
        // O-proj + LN + combine: out = LN(att@ow+ob+atoms) + hloc
        mma_gemm<2, 4><<<g1, 256, GEMM_SMEM_BYTES>>>(p_att16, wt_l + 327680, ob + l * C_, p_atoms,
                                                     p_hloc, n2g + l * C_, n2b + l * C_,
                                                     p_out, p_out16, 256);
        // FFN
        mma_gemm<1, 4><<<g2, 256, GEMM_SMEM_BYTES>>>(p_out16, wt_l + 393216, mb1 + l * 2 * C_, nullptr,
                                                     nullptr, nullptr, nullptr, nullptr, p_t116, 512);
        mma_gemm<2, 8><<<g1, 256, GEMM_SMEM_BYTES>>>(p_t116, wt_l + 524288, mb2 + l * C_, p_out,
                                                     nullptr, n3g + l * C_, n3b + l * C_,
                                                     p_atoms, p_atoms16, 256);
    }
    pool_kernel<<<B_, 256>>>((float*)d_out);
}

// round 14
// speedup vs baseline: 5.9299x; 1.0821x over previous
#include <cuda_runtime.h>
#include <cuda_fp16.h>
#include <math.h>
#include <stdint.h>

#define TN   32768
#define C_   256
#define B_   64
#define N_   512
#define H_   4
#define DH_  64
#define M_   266
#define E_   524288
#define L_   5

// ---------------- scratch ----------------
__device__ float  g_atoms[TN * C_];
__device__ __half g_atoms16[TN * C_];
__device__ __half g_h016[TN * C_];
__device__ __half g_t116[TN * 2 * C_];
__device__ float  g_hloc[TN * C_];
__device__ float  g_out[TN * C_];
__device__ __half g_out16[TN * C_];
__device__ __half g_qkv16[(size_t)TN * 3 * C_];
__device__ __half g_att16[TN * C_];
__device__ __half g_wt[L_ * 655360];          // transposed fp16 weights, [n][k]
__device__ __half g_projh[L_ * 288 * 64];     // fp16 proj, rows >=266 zero
__device__ __half g_kp[(size_t)H_ * TN * 288];
__device__ __half g_qp[(size_t)H_ * TN * 288];
__device__ float  g_ctx[2 * 256 * 80 * 320];  // [part][bh][d'][m]
__device__ int    g_deg[TN];
__device__ int    g_indptr[TN + 1];
__device__ int    g_cursor[TN];
__device__ int    g_esrc[E_];                 // CSR-ordered edge source
__device__ float4 g_ea4[E_];                  // CSR-ordered edge attributes

// ---------------- helpers ----------------
__device__ __forceinline__ float gelu_exact(float x) {
    return 0.5f * x * (1.0f + erff(x * 0.70710678118654752f));
}
__device__ __forceinline__ uint32_t f2h2(float a, float b) {
    __half2 h = __floats2half2_rn(a, b);
    return *reinterpret_cast<uint32_t*>(&h);
}
__device__ __forceinline__ uint32_t smem_u32(const void* p) {
    uint32_t a;
    asm("{ .reg .u64 t; cvta.to.shared.u64 t, %1; cvt.u32.u64 %0, t; }" : "=r"(a) : "l"(p));
    return a;
}
__device__ __forceinline__ void mma_f16_16x8x16(float* d, const uint32_t* a, const uint32_t* b) {
    asm volatile(
        "mma.sync.aligned.m16n8k16.row.col.f32.f16.f16.f32 "
        "{%0,%1,%2,%3}, {%4,%5,%6,%7}, {%8,%9}, {%0,%1,%2,%3};"
        : "+f"(d[0]), "+f"(d[1]), "+f"(d[2]), "+f"(d[3])
        : "r"(a[0]), "r"(a[1]), "r"(a[2]), "r"(a[3]), "r"(b[0]), "r"(b[1]));
}
__device__ __forceinline__ void ldsm_x4(uint32_t* r, uint32_t saddr) {
    asm volatile("ldmatrix.sync.aligned.m8n8.x4.shared.b16 {%0,%1,%2,%3}, [%4];"
                 : "=r"(r[0]), "=r"(r[1]), "=r"(r[2]), "=r"(r[3]) : "r"(saddr));
}
__device__ __forceinline__ void ldsm_x4_t(uint32_t* r, uint32_t saddr) {
    asm volatile("ldmatrix.sync.aligned.m8n8.x4.trans.shared.b16 {%0,%1,%2,%3}, [%4];"
                 : "=r"(r[0]), "=r"(r[1]), "=r"(r[2]), "=r"(r[3]) : "r"(saddr));
}
__device__ __forceinline__ void ldsm_x2_t(uint32_t* r, uint32_t saddr) {
    asm volatile("ldmatrix.sync.aligned.m8n8.x2.trans.shared.b16 {%0,%1}, [%2];"
                 : "=r"(r[0]), "=r"(r[1]) : "r"(saddr));
}
__device__ __forceinline__ void cp_async16(uint32_t saddr, const void* gptr) {
    asm volatile("cp.async.cg.shared.global [%0], [%1], 16;" :: "r"(saddr), "l"(gptr));
}
#define CP_COMMIT() asm volatile("cp.async.commit_group;" ::: "memory")
#define CP_WAIT0()  asm volatile("cp.async.wait_group 0;" ::: "memory")

// ---------------- weight transpose (once): WT[n*K+k] = half(W[k*N+n]) ----------------
struct WPtrs { const float* p[8]; };

__global__ void transpose_kernel(WPtrs wp) {
    int z = blockIdx.z;
    int t = z & 7, l = z >> 3;
    int K = (t == 7) ? 512 : 256;
    int N = (t == 6) ? 512 : 256;
    int n0 = blockIdx.x * 32, k0 = blockIdx.y * 32;
    if (n0 >= N || k0 >= K) return;
    const float* src = wp.p[t] + ((t >= 6) ? l * 131072 : l * 65536);
    int doff = (t < 6) ? t * 65536 : (t == 6 ? 393216 : 524288);
    __half* dst = g_wt + l * 655360 + doff;
    __shared__ float s[32][33];
    int tx = threadIdx.x, ty = threadIdx.y;
#pragma unroll
    for (int i = 0; i < 4; i++)
        s[ty + 8 * i][tx] = src[(k0 + ty + 8 * i) * N + n0 + tx];
    __syncthreads();
#pragma unroll
    for (int i = 0; i < 4; i++)
        dst[(n0 + ty + 8 * i) * K + k0 + tx] = __float2half_rn(s[tx][ty + 8 * i]);
}

// ---------------- proj -> fp16, padded to 288 rows ----------------
__global__ void proj_prep_kernel(const float* __restrict__ proj) {
    int idx = blockIdx.x * 256 + threadIdx.x;
    if (idx >= L_ * 288 * 64) return;
    int l = idx / (288 * 64);
    int r = idx - l * (288 * 64);
    int m = r >> 6, d = r & 63;
    g_projh[idx] = (m < M_) ? __float2half_rn(proj[(l * M_ + m) * 64 + d]) : __half(0.f);
}

// ---------------- fp16 mma GEMM, ldmatrix + cp.async, fused LN epilogue ----------------
#define GEMM_SMEM_MAIN  (2 * 9216 + 2 * 36864)
#define GEMM_SMEM_BYTES (GEMM_SMEM_MAIN + 512)

template <int MODE, int NK>
__global__ void __launch_bounds__(256, 2) mma_gemm(const __half* __restrict__ A,
                                                   const __half* __restrict__ WT,
                                                   const float* __restrict__ bias,
                                                   const float* __restrict__ res,
                                                   const float* __restrict__ add2,
                                                   const float* __restrict__ lng,
                                                   const float* __restrict__ lnb,
                                                   float* __restrict__ Out32,
                                                   __half* __restrict__ Out16,
                                                   int Ntot) {
    extern __shared__ uint32_t smw[];
    const int K = NK * 64;
    const int tid = threadIdx.x;
    const int lane = tid & 31, wid = tid >> 5;
    const int g = lane >> 2, t = lane & 3;
    const int wm = (wid & 1) * 32;
    const int wn = (wid >> 1) * 64;
    const int rowbase = blockIdx.x * 64;
    const int colbase = blockIdx.y * 256;
    const uint32_t sb = smem_u32(smw);

    const int l7 = lane & 7, l8 = (lane >> 3) & 1, l16 = (lane >> 4) & 1;
    uint32_t aAddr[2], bAddr[4];
#pragma unroll
    for (int mt = 0; mt < 2; mt++)
        aAddr[mt] = sb + (wm + mt * 16 + l7 + l8 * 8) * 144 + l16 * 16;
#pragma unroll
    for (int p = 0; p < 4; p++)
        bAddr[p] = sb + 18432 + (wn + p * 16 + l7 + l16 * 8) * 144 + l8 * 16;

    float acc[2][8][4];
#pragma unroll
    for (int mt = 0; mt < 2; mt++)
#pragma unroll
        for (int nt = 0; nt < 8; nt++)
#pragma unroll
            for (int j = 0; j < 4; j++) acc[mt][nt][j] = 0.0f;

#pragma unroll
    for (int i = 0; i < 2; i++) {
        int idx = tid + i * 256;
        int m = idx >> 3, c = idx & 7;
        cp_async16(sb + m * 144 + c * 16, A + (size_t)(rowbase + m) * K + c * 8);
    }
#pragma unroll
    for (int i = 0; i < 8; i++) {
        int idx = tid + i * 256;
        int n = idx >> 3, c = idx & 7;
        cp_async16(sb + 18432 + n * 144 + c * 16, WT + (size_t)(colbase + n) * K + c * 8);
    }
    CP_COMMIT();
    CP_WAIT0();
    __syncthreads();

#pragma unroll
    for (int kb = 0; kb < NK; kb++) {
        const int cur = kb & 1;
        const bool nxt = (kb + 1 < NK);
        if (nxt) {
            int k0g = (kb + 1) * 64;
            int sB = cur ^ 1;
#pragma unroll
            for (int i = 0; i < 2; i++) {
                int idx = tid + i * 256;
                int m = idx >> 3, c = idx & 7;
                cp_async16(sb + sB * 9216 + m * 144 + c * 16,
                           A + (size_t)(rowbase + m) * K + k0g + c * 8);
            }
#pragma unroll
            for (int i = 0; i < 8; i++) {
                int idx = tid + i * 256;
                int n = idx >> 3, c = idx & 7;
                cp_async16(sb + 18432 + sB * 36864 + n * 144 + c * 16,
                           WT + (size_t)(colbase + n) * K + k0g + c * 8);
            }
            CP_COMMIT();
        }
        const uint32_t aoff = cur * 9216, boff = cur * 36864;
#pragma unroll
        for (int ks = 0; ks < 4; ks++) {
            uint32_t ar[2][4], br[4][4];
            ldsm_x4(ar[0], aAddr[0] + aoff + ks * 32);
            ldsm_x4(ar[1], aAddr[1] + aoff + ks * 32);
#pragma unroll
            for (int p = 0; p < 4; p++) ldsm_x4(br[p], bAddr[p] + boff + ks * 32);
#pragma unroll
            for (int mt = 0; mt < 2; mt++)
#pragma unroll
                for (int p = 0; p < 4; p++) {
                    mma_f16_16x8x16(acc[mt][2 * p],     ar[mt], &br[p][0]);
                    mma_f16_16x8x16(acc[mt][2 * p + 1], ar[mt], &br[p][2]);
                }
        }
        if (nxt) {
            CP_WAIT0();
            __syncthreads();
        }
    }

    if (MODE <= 1) {
#pragma unroll
        for (int mt = 0; mt < 2; mt++) {
            int r0 = rowbase + wm + mt * 16 + g;
#pragma unroll
            for (int nt = 0; nt < 8; nt++) {
                int col = colbase + wn + nt * 8 + 2 * t;
                float b0 = 0.0f, b1 = 0.0f;
                if (bias) { b0 = bias[col]; b1 = bias[col + 1]; }
                float v0 = acc[mt][nt][0] + b0, v1 = acc[mt][nt][1] + b1;
                float v2 = acc[mt][nt][2] + b0, v3 = acc[mt][nt][3] + b1;
                if (MODE == 1) {
                    v0 = gelu_exact(v0); v1 = gelu_exact(v1);
                    v2 = gelu_exact(v2); v3 = gelu_exact(v3);
                }
                *reinterpret_cast<uint32_t*>(&Out16[(size_t)r0 * Ntot + col]) = f2h2(v0, v1);
                *reinterpret_cast<uint32_t*>(&Out16[(size_t)(r0 + 8) * Ntot + col]) = f2h2(v2, v3);
            }
        }
    } else {
        float* sums = (float*)(smw + GEMM_SMEM_MAIN / 4);   // 64 rows x {s1,s2}
        if (tid < 128) sums[tid] = 0.0f;
        float gg[8][2], bb[8][2];
#pragma unroll
        for (int mt = 0; mt < 2; mt++) {
            int r0 = rowbase + wm + mt * 16 + g;
#pragma unroll
            for (int nt = 0; nt < 8; nt++) {
                int col = wn + nt * 8 + 2 * t;
                float b0 = bias[col], b1 = bias[col + 1];
                float2 r01 = *reinterpret_cast<const float2*>(&res[(size_t)r0 * 256 + col]);
                float2 r23 = *reinterpret_cast<const float2*>(&res[(size_t)(r0 + 8) * 256 + col]);
                acc[mt][nt][0] += b0 + r01.x; acc[mt][nt][1] += b1 + r01.y;
                acc[mt][nt][2] += b0 + r23.x; acc[mt][nt][3] += b1 + r23.y;
            }
        }
        __syncthreads();
#pragma unroll
        for (int mt = 0; mt < 2; mt++)
#pragma unroll
            for (int rh = 0; rh < 2; rh++) {
                float s1 = 0.0f, s2 = 0.0f;
#pragma unroll
                for (int nt = 0; nt < 8; nt++) {
                    float v0 = acc[mt][nt][2 * rh], v1 = acc[mt][nt][2 * rh + 1];
                    s1 += v0 + v1; s2 += v0 * v0 + v1 * v1;
                }
                s1 += __shfl_xor_sync(0xffffffffu, s1, 1);
                s1 += __shfl_xor_sync(0xffffffffu, s1, 2);
                s2 += __shfl_xor_sync(0xffffffffu, s2, 1);
                s2 += __shfl_xor_sync(0xffffffffu, s2, 2);
                if (t == 0) {
                    int rl = wm + mt * 16 + g + rh * 8;
                    atomicAdd(&sums[2 * rl], s1);
                    atomicAdd(&sums[2 * rl + 1], s2);
                }
            }
#pragma unroll
        for (int nt = 0; nt < 8; nt++) {
            int col = wn + nt * 8 + 2 * t;
            gg[nt][0] = lng[col]; gg[nt][1] = lng[col + 1];
            bb[nt][0] = lnb[col]; bb[nt][1] = lnb[col + 1];
        }
        __syncthreads();
#pragma unroll
        for (int mt = 0; mt < 2; mt++) {
#pragma unroll
            for (int rh = 0; rh < 2; rh++) {
                int rl = wm + mt * 16 + g + rh * 8;
                int grow = rowbase + rl;
                float mean = sums[2 * rl] * (1.0f / 256.0f);
                float var = sums[2 * rl + 1] * (1.0f / 256.0f) - mean * mean;
                float rstd = rsqrtf(var + 1e-5f);
#pragma unroll
                for (int nt = 0; nt < 8; nt++) {
                    int col = wn + nt * 8 + 2 * t;
                    float y0 = (acc[mt][nt][2 * rh] - mean) * rstd * gg[nt][0] + bb[nt][0];
                    float y1 = (acc[mt][nt][2 * rh + 1] - mean) * rstd * gg[nt][1] + bb[nt][1];
                    if (add2) {
                        float2 a2 = *reinterpret_cast<const float2*>(&add2[(size_t)grow * 256 + col]);
                        y0 += a2.x; y1 += a2.y;
                    }
                    *reinterpret_cast<float2*>(&Out32[(size_t)grow * 256 + col]) = make_float2(y0, y1);
                    if (Out16)
                        *reinterpret_cast<uint32_t*>(&Out16[(size_t)grow * 256 + col]) = f2h2(y0, y1);
                }
            }
        }
    }
}

// ---------------- Performer stage 1 ----------------
#define S1_SMEM_BYTES ((2304 + 10368) * 4)

__global__ void __launch_bounds__(256) phi_kernel(const __half* __restrict__ QKV,
                                                  const __half* __restrict__ projh_l,
                                                  __half* __restrict__ KP,
                                                  __half* __restrict__ QP) {
    extern __shared__ uint32_t sw[];
    uint32_t* As = sw;
    uint32_t* Bs = sw + 2304;
    const int tid = threadIdx.x;
    const int lane = tid & 31, wid = tid >> 5;
    const int g = lane >> 2, t = lane & 3;
    const int wm = (wid & 1) * 32;
    const int wn = (wid >> 1) * 72;
    const int rowbase = blockIdx.x * 64;
    const int h = blockIdx.y & 3;
    const int isq = blockIdx.y >> 2;
    const __half* Ah = QKV + (isq ? h * 64 : 256 + h * 64);
    __half* outp = (isq ? QP : KP) + (size_t)h * TN * 288;
    const uint32_t sbA = smem_u32(As);

#pragma unroll
    for (int i = 0; i < 2; i++) {
        int idx = tid + i * 256;
        int m = idx >> 3, c = idx & 7;
        cp_async16(sbA + m * 144 + c * 16, Ah + (size_t)(rowbase + m) * 768 + c * 8);
    }
    CP_COMMIT();
    const uint32_t* pb = (const uint32_t*)projh_l;
#pragma unroll
    for (int i = 0; i < 36; i++) {
        int w = tid + i * 256;
        Bs[(w >> 5) * 36 + (w & 31)] = pb[w];
    }
    CP_WAIT0();
    __syncthreads();

    float acc[2][9][4];
#pragma unroll
    for (int mt = 0; mt < 2; mt++)
#pragma unroll
        for (int nt = 0; nt < 9; nt++)
#pragma unroll
            for (int j = 0; j < 4; j++) acc[mt][nt][j] = 0.0f;

#pragma unroll
    for (int ks = 0; ks < 4; ks++) {
        int k0 = ks * 8;
        uint32_t af[2][4], bf[9][2];
#pragma unroll
        for (int mt = 0; mt < 2; mt++) {
            int r0 = wm + mt * 16 + g;
            af[mt][0] = As[r0 * 36 + k0 + t];
            af[mt][1] = As[(r0 + 8) * 36 + k0 + t];
            af[mt][2] = As[r0 * 36 + k0 + t + 4];
            af[mt][3] = As[(r0 + 8) * 36 + k0 + t + 4];
        }
#pragma unroll
        for (int nt = 0; nt < 9; nt++) {
            int n0 = wn + nt * 8 + g;
            bf[nt][0] = Bs[n0 * 36 + k0 + t];
            bf[nt][1] = Bs[n0 * 36 + k0 + t + 4];
        }
#pragma unroll
        for (int mt = 0; mt < 2; mt++)
#pragma unroll
            for (int nt = 0; nt < 9; nt++)
                mma_f16_16x8x16(acc[mt][nt], af[mt], bf[nt]);
    }

#pragma unroll
    for (int mt = 0; mt < 2; mt++) {
        int r = rowbase + wm + mt * 16 + g;
#pragma unroll
        for (int nt = 0; nt < 9; nt++) {
            int c0 = wn + nt * 8 + 2 * t;
            float v0 = fmaxf(acc[mt][nt][0], 0.0f) + 1e-3f;
            float v1 = fmaxf(acc[mt][nt][1], 0.0f) + 1e-3f;
            float v2 = fmaxf(acc[mt][nt][2], 0.0f) + 1e-3f;
            float v3 = fmaxf(acc[mt][nt][3], 0.0f) + 1e-3f;
            if (c0 >= M_) { v0 = 0.0f; v2 = 0.0f; }
            if (c0 + 1 >= M_) { v1 = 0.0f; v3 = 0.0f; }
            *reinterpret_cast<uint32_t*>(&outp[(size_t)r * 288 + c0]) = f2h2(v0, v1);
            *reinterpret_cast<uint32_t*>(&outp[(size_t)(r + 8) * 288 + c0]) = f2h2(v2, v3);
        }
    }
}

// ---------------- Performer stage 2: ctx partials via ldmatrix.trans ----------------
#define S2_KP_STRIDE 336
#define S2_VS_STRIDE 88
#define S2_VS_OFF    (64 * S2_KP_STRIDE * 2)
#define S2_SMEM_BYTES (64 * S2_KP_STRIDE * 2 + 64 * S2_VS_STRIDE * 2)

__global__ void __launch_bounds__(256) ctx_kernel(const __half* __restrict__ KP,
                                                  const __half* __restrict__ QKV,
                                                  float* __restrict__ CTX) {
    extern __shared__ uint32_t sw[];
    __half* kp_h = (__half*)sw;
    __half* vs_h = (__half*)((char*)sw + S2_VS_OFF);
    const int tid = threadIdx.x;
    const int lane = tid & 31, wid = tid >> 5;
    const int g = lane >> 2, t = lane & 3;
    const int wm = (wid & 3) * 80;
    const int wn = (wid >> 2) * 40;
    const int part = blockIdx.x >> 8;
    const int bh = blockIdx.x & 255;
    const int b = bh >> 2, h = bh & 3;
    const uint32_t sb = smem_u32(sw);
    const int l7 = lane & 7, l8 = (lane >> 3) & 1, l16 = (lane >> 4) & 1;

    for (int i = tid; i < 64 * 48; i += 256) {
        int n = i / 48, c = 288 + i % 48;
        kp_h[n * S2_KP_STRIDE + c] = __float2half(0.0f);
    }
    for (int i = tid; i < 64 * 24; i += 256) {
        int n = i / 24, c = 64 + i % 24;
        vs_h[n * S2_VS_STRIDE + c] = __float2half(c == 64 ? 1.0f : 0.0f);
    }

    uint32_t aBase = sb + ((l16 * 8 + l7) * S2_KP_STRIDE + wm + l8 * 8) * 2;
    int bl = lane & 15;
    uint32_t bBase = sb + S2_VS_OFF + (((bl >> 3) * 8 + (bl & 7)) * S2_VS_STRIDE + wn) * 2;

    float acc[5][5][4];
#pragma unroll
    for (int mt = 0; mt < 5; mt++)
#pragma unroll
        for (int nt = 0; nt < 5; nt++)
#pragma unroll
            for (int j = 0; j < 4; j++) acc[mt][nt][j] = 0.0f;

    const __half* kp_g = KP + (size_t)h * TN * 288;

    for (int c = 0; c < 4; c++) {
        __syncthreads();
        int base = b * 512 + (part * 4 + c) * 64;
#pragma unroll
        for (int i = 0; i < 9; i++) {
            int idx = tid + i * 256;
            int n = idx / 36, cc = idx - n * 36;
            cp_async16(sb + (n * S2_KP_STRIDE + cc * 8) * 2,
                       kp_g + (size_t)(base + n) * 288 + cc * 8);
        }
#pragma unroll
        for (int i = 0; i < 2; i++) {
            int idx = tid + i * 256;
            int n = idx >> 3, cc = idx & 7;
            cp_async16(sb + S2_VS_OFF + (n * S2_VS_STRIDE + cc * 8) * 2,
                       QKV + (size_t)(base + n) * 768 + 512 + h * 64 + cc * 8);
        }
        CP_COMMIT();
        CP_WAIT0();
        __syncthreads();
#pragma unroll
        for (int ks = 0; ks < 4; ks++) {
            uint32_t af[5][4], bf[5][2];
            uint32_t aK = aBase + ks * 16 * S2_KP_STRIDE * 2;
            uint32_t bK = bBase + ks * 16 * S2_VS_STRIDE * 2;
#pragma unroll
            for (int mt = 0; mt < 5; mt++) ldsm_x4_t(af[mt], aK + mt * 32);
#pragma unroll
            for (int nt = 0; nt < 5; nt++) ldsm_x2_t(bf[nt], bK + nt * 16);
#pragma unroll
            for (int mt = 0; mt < 5; mt++)
#pragma unroll
                for (int nt = 0; nt < 5; nt++)
                    mma_f16_16x8x16(acc[mt][nt], af[mt], bf[nt]);
        }
    }

    float* outc = CTX + ((size_t)part * 256 + bh) * 80 * 320;
#pragma unroll
    for (int mt = 0; mt < 5; mt++) {
        int m0 = wm + mt * 16 + g;
#pragma unroll
        for (int nt = 0; nt < 5; nt++) {
            int c0 = wn + nt * 8 + 2 * t;
            outc[(size_t)c0 * 320 + m0] = acc[mt][nt][0];
            outc[(size_t)(c0 + 1) * 320 + m0] = acc[mt][nt][1];
            outc[(size_t)c0 * 320 + m0 + 8] = acc[mt][nt][2];
            outc[(size_t)(c0 + 1) * 320 + m0 + 8] = acc[mt][nt][3];
        }
    }
}

// ---------------- Performer stage 3 ----------------
#define S3_W_CTX (80 * 164)
#define S3_W_AS  (64 * 148)
#define S3_W_ATT (64 * 80)
#define S3_SMEM_BYTES ((S3_W_CTX + S3_W_AS + S3_W_ATT) * 4)

__global__ void __launch_bounds__(256) att_kernel(const __half* __restrict__ QP,
                                                  const float* __restrict__ CTX,
                                                  __half* __restrict__ Att) {
    extern __shared__ uint32_t sw[];
    uint32_t* ctxT = sw;
    uint32_t* As = sw + S3_W_CTX;
    float* att_s = (float*)(sw + S3_W_CTX + S3_W_AS);
    const int tid = threadIdx.x;
    const int lane = tid & 31, wid = tid >> 5;
    const int g = lane >> 2, t = lane & 3;
    const int wm = (wid & 3) * 16;
    const int wn = (wid >> 2) * 40;
    const int cta = blockIdx.x;
    const int bh = cta >> 1, half = cta & 1;
    const int b = bh >> 2, h = bh & 3;

    const float* cg0 = CTX + (size_t)bh * 80 * 320;
    const float* cg1 = CTX + ((size_t)256 + bh) * 80 * 320;
#pragma unroll
    for (int i = 0; i < 50; i++) {
        int idx = tid + i * 256;
        int d = idx / 160, m2 = idx - d * 160;
        size_t o = (size_t)d * 320 + m2 * 2;
        float2 v0 = *reinterpret_cast<const float2*>(&cg0[o]);
        float2 v1 = *reinterpret_cast<const float2*>(&cg1[o]);
        ctxT[d * 164 + m2] = f2h2(v0.x + v1.x, v0.y + v1.y);
    }
    const uint32_t* qp2 = (const uint32_t*)(QP + (size_t)h * TN * 288);
    const int rowg0 = b * 512 + half * 256;

    for (int ch = 0; ch < 4; ch++) {
        __syncthreads();
        int rbase = rowg0 + ch * 64;
#pragma unroll
        for (int i = 0; i < 36; i++) {
            int idx = tid + i * 256;
            int n = idx / 144, m2 = idx - n * 144;
            As[n * 148 + m2] = qp2[(size_t)(rbase + n) * 144 + m2];
        }
        __syncthreads();
        float acc[5][4];
#pragma unroll
        for (int nt = 0; nt < 5; nt++)
#pragma unroll
            for (int j = 0; j < 4; j++) acc[nt][j] = 0.0f;
#pragma unroll
        for (int ks = 0; ks < 17; ks++) {
            int k0 = ks * 8;
            uint32_t af[4], bf[5][2];
            int r0 = wm + g;
            af[0] = As[r0 * 148 + k0 + t];
            af[1] = As[(r0 + 8) * 148 + k0 + t];
            af[2] = As[r0 * 148 + k0 + t + 4];
            af[3] = As[(r0 + 8) * 148 + k0 + t + 4];
#pragma unroll
            for (int nt = 0; nt < 5; nt++) {
                int n0 = wn + nt * 8 + g;
                bf[nt][0] = ctxT[n0 * 164 + k0 + t];
                bf[nt][1] = ctxT[n0 * 164 + k0 + t + 4];
            }
#pragma unroll
            for (int nt = 0; nt < 5; nt++)
                mma_f16_16x8x16(acc[nt], af, bf[nt]);
        }
#pragma unroll
        for (int nt = 0; nt < 5; nt++) {
            int c0 = wn + nt * 8 + 2 * t;
            att_s[(wm + g) * 80 + c0] = acc[nt][0];
            att_s[(wm + g) * 80 + c0 + 1] = acc[nt][1];
            att_s[(wm + g + 8) * 80 + c0] = acc[nt][2];
            att_s[(wm + g + 8) * 80 + c0 + 1] = acc[nt][3];
        }
        __syncthreads();
#pragma unroll
        for (int i = 0; i < 16; i++) {
            int idx = tid + i * 256;
            int n = idx >> 6, d = idx & 63;
            float den = att_s[n * 80 + 64];
            Att[(size_t)(rbase + n) * 256 + h * 64 + d] = __float2half_rn(att_s[n * 80 + d] / den);
        }
    }
}

// ---------------- node embedding ----------------
__global__ void node_embed_kernel(const float* __restrict__ x,
                                  const float* __restrict__ w,
                                  const float* __restrict__ b) {
    __shared__ float lx[11];
    int row = blockIdx.x;
    int t = threadIdx.x;
    if (t < 11) lx[t] = log1pf(x[row * 11 + t]);
    __syncthreads();
    float s = b[t];
#pragma unroll
    for (int j = 0; j < 11; j++) s += lx[j] * w[j * C_ + t];
    g_atoms[row * C_ + t] = s;
    g_atoms16[row * C_ + t] = __float2half_rn(s);
}

// ---------------- CSR build ----------------
__global__ void count_deg_kernel(const int* __restrict__ dst) {
    int e = blockIdx.x * blockDim.x + threadIdx.x;
    if (e < E_) atomicAdd(&g_deg[dst[e]], 1);
}
__global__ void scan_deg_kernel() {
    __shared__ int sh[1024];
    __shared__ int carry;
    int t = threadIdx.x;
    if (t == 0) carry = 0;
    __syncthreads();
    for (int base = 0; base < TN; base += 1024) {
        int v = g_deg[base + t];
        sh[t] = v;
        __syncthreads();
        for (int off = 1; off < 1024; off <<= 1) {
            int add = (t >= off) ? sh[t - off] : 0;
            __syncthreads();
            sh[t] += add;
            __syncthreads();
        }
        int ip = carry + sh[t] - v;
        g_indptr[base + t] = ip;
        g_cursor[base + t] = ip;
        __syncthreads();
        if (t == 0) carry += sh[1023];
        __syncthreads();
    }
    if (t == 0) g_indptr[TN] = carry;
}
__global__ void fill_adj_kernel(const int* __restrict__ src,
                                const int* __restrict__ dst,
                                const float* __restrict__ eattr) {
    int e = blockIdx.x * blockDim.x + threadIdx.x;
    if (e < E_) {
        int p = atomicAdd(&g_cursor[dst[e]], 1);
        g_esrc[p] = src[e];
        g_ea4[p] = *reinterpret_cast<const float4*>(&eattr[e * 4]);
    }
}

// ---------------- GINE aggregation: CSR payloads + 4-edge unroll ----------------
__global__ void __launch_bounds__(256) gine_kernel(const float* __restrict__ ew,
                                                   const float* __restrict__ eb) {
    int tid = threadIdx.x;
    int warp = tid >> 5, lane = tid & 31;
    int v = blockIdx.x * 8 + warp;
    const int c0 = lane * 8;

    float ewr[4][8], ebr[8];
#pragma unroll
    for (int j = 0; j < 4; j++) {
        float4 w0 = *reinterpret_cast<const float4*>(&ew[j * C_ + c0]);
        float4 w1 = *reinterpret_cast<const float4*>(&ew[j * C_ + c0 + 4]);
        ewr[j][0] = w0.x; ewr[j][1] = w0.y; ewr[j][2] = w0.z; ewr[j][3] = w0.w;
        ewr[j][4] = w1.x; ewr[j][5] = w1.y; ewr[j][6] = w1.z; ewr[j][7] = w1.w;
    }
    {
        float4 b0 = *reinterpret_cast<const float4*>(&eb[c0]);
        float4 b1 = *reinterpret_cast<const float4*>(&eb[c0 + 4]);
        ebr[0] = b0.x; ebr[1] = b0.y; ebr[2] = b0.z; ebr[3] = b0.w;
        ebr[4] = b1.x; ebr[5] = b1.y; ebr[6] = b1.z; ebr[7] = b1.w;
    }

    float acc[8];
    {
        float4 a0 = *reinterpret_cast<const float4*>(&g_atoms[(size_t)v * C_ + c0]);
        float4 a1 = *reinterpret_cast<const float4*>(&g_atoms[(size_t)v * C_ + c0 + 4]);
        acc[0] = a0.x; acc[1] = a0.y; acc[2] = a0.z; acc[3] = a0.w;
        acc[4] = a1.x; acc[5] = a1.y; acc[6] = a1.z; acc[7] = a1.w;
    }

    int p0 = g_indptr[v], p1 = g_indptr[v + 1];
    int p = p0;
    for (; p + 3 < p1; p += 4) {
        int s[4];
        float4 ea[4];
        uint4 hv[4];
#pragma unroll
        for (int q = 0; q < 4; q++) { s[q] = g_esrc[p + q]; ea[q] = g_ea4[p + q]; }
#pragma unroll
        for (int q = 0; q < 4; q++)
            hv[q] = *reinterpret_cast<const uint4*>(&g_atoms16[(size_t)s[q] * C_ + c0]);
#pragma unroll
        for (int q = 0; q < 4; q++) {
            float2 f0 = __half22float2(*reinterpret_cast<__half2*>(&hv[q].x));
            float2 f1 = __half22float2(*reinterpret_cast<__half2*>(&hv[q].y));
            float2 f2 = __half22float2(*reinterpret_cast<__half2*>(&hv[q].z));
            float2 f3 = __half22float2(*reinterpret_cast<__half2*>(&hv[q].w));
            float av[8] = {f0.x, f0.y, f1.x, f1.y, f2.x, f2.y, f3.x, f3.y};
#pragma unroll
            for (int i = 0; i < 8; i++) {
                float eac = ebr[i] + ea[q].x * ewr[0][i] + ea[q].y * ewr[1][i]
                                   + ea[q].z * ewr[2][i] + ea[q].w * ewr[3][i];
                acc[i] += fmaxf(av[i] + eac, 0.0f);
            }
        }
    }
    for (; p < p1; p++) {
        int s = g_esrc[p];
        float4 ea4 = g_ea4[p];
        uint4 hv = *reinterpret_cast<const uint4*>(&g_atoms16[(size_t)s * C_ + c0]);
        float2 f0 = __half22float2(*reinterpret_cast<__half2*>(&hv.x));
        float2 f1 = __half22float2(*reinterpret_cast<__half2*>(&hv.y));
        float2 f2 = __half22float2(*reinterpret_cast<__half2*>(&hv.z));
        float2 f3 = __half22float2(*reinterpret_cast<__half2*>(&hv.w));
        float av[8] = {f0.x, f0.y, f1.x, f1.y, f2.x, f2.y, f3.x, f3.y};
#pragma unroll
        for (int i = 0; i < 8; i++) {
            float eac = ebr[i] + ea4.x * ewr[0][i] + ea4.y * ewr[1][i]
                               + ea4.z * ewr[2][i] + ea4.w * ewr[3][i];
            acc[i] += fmaxf(av[i] + eac, 0.0f);
        }
    }
    uint4 hout;
    hout.x = f2h2(acc[0], acc[1]);
    hout.y = f2h2(acc[2], acc[3]);
    hout.z = f2h2(acc[4], acc[5]);
    hout.w = f2h2(acc[6], acc[7]);
    *reinterpret_cast<uint4*>(&g_h016[(size_t)v * C_ + c0]) = hout;
}

// ---------------- final mean pool ----------------
__global__ void pool_kernel(float* __restrict__ out) {
    int b = blockIdx.x;
    int cix = threadIdx.x;
    float s = 0.0f;
    for (int n = 0; n < N_; n++) s += g_atoms[(b * N_ + n) * C_ + cix];
    out[b * C_ + cix] = s * (1.0f / (float)N_);
}

// ---------------- host launcher ----------------
extern "C" void kernel_launch(void* const* d_in, const int* in_sizes, int n_in,
                              void* d_out, int out_size) {
    const float* x      = (const float*)d_in[0];
    const float* eattr  = (const float*)d_in[1];
    const int*   eidx   = (const int*)d_in[2];
    const float* node_w = (const float*)d_in[4];
    const float* node_b = (const float*)d_in[5];
    const float* edge_w = (const float*)d_in[6];
    const float* edge_b = (const float*)d_in[7];
    const float* gw1    = (const float*)d_in[8];
    const float* gb1    = (const float*)d_in[9];
    const float* gw2    = (const float*)d_in[10];
    const float* gb2    = (const float*)d_in[11];
    const float* qw     = (const float*)d_in[12];
    const float* kw     = (const float*)d_in[13];
    const float* vw     = (const float*)d_in[14];
    const float* ow     = (const float*)d_in[15];
    const float* ob     = (const float*)d_in[16];
    const float* proj   = (const float*)d_in[17];
    const float* n1g    = (const float*)d_in[18];
    const float* n1b    = (const float*)d_in[19];
    const float* n2g    = (const float*)d_in[20];
    const float* n2b    = (const float*)d_in[21];
    const float* n3g    = (const float*)d_in[22];
    const float* n3b    = (const float*)d_in[23];
    const float* mw1    = (const float*)d_in[24];
    const float* mb1    = (const float*)d_in[25];
    const float* mw2    = (const float*)d_in[26];
    const float* mb2    = (const float*)d_in[27];

    const int* src = eidx;
    const int* dst = eidx + E_;

    float *p_atoms, *p_hloc, *p_out, *p_ctx;
    __half *p_atoms16, *p_h016, *p_t116, *p_out16, *p_qkv16, *p_att16;
    __half *p_wt, *p_projh, *p_kp, *p_qp;
    int* p_deg;
    cudaGetSymbolAddress((void**)&p_atoms,   g_atoms);
    cudaGetSymbolAddress((void**)&p_atoms16, g_atoms16);
    cudaGetSymbolAddress((void**)&p_h016,    g_h016);
    cudaGetSymbolAddress((void**)&p_t116,    g_t116);
    cudaGetSymbolAddress((void**)&p_hloc,    g_hloc);
    cudaGetSymbolAddress((void**)&p_out,     g_out);
    cudaGetSymbolAddress((void**)&p_out16,   g_out16);
    cudaGetSymbolAddress((void**)&p_qkv16,   g_qkv16);
    cudaGetSymbolAddress((void**)&p_att16,   g_att16);
    cudaGetSymbolAddress((void**)&p_ctx,     g_ctx);
    cudaGetSymbolAddress((void**)&p_wt,      g_wt);
    cudaGetSymbolAddress((void**)&p_projh,   g_projh);
    cudaGetSymbolAddress((void**)&p_kp,      g_kp);
    cudaGetSymbolAddress((void**)&p_qp,      g_qp);
    cudaGetSymbolAddress((void**)&p_deg,     g_deg);

    cudaFuncSetAttribute((const void*)mma_gemm<0, 4>, cudaFuncAttributeMaxDynamicSharedMemorySize, GEMM_SMEM_BYTES);
    cudaFuncSetAttribute((const void*)mma_gemm<1, 4>, cudaFuncAttributeMaxDynamicSharedMemorySize, GEMM_SMEM_BYTES);
    cudaFuncSetAttribute((const void*)mma_gemm<2, 4>, cudaFuncAttributeMaxDynamicSharedMemorySize, GEMM_SMEM_BYTES);
    cudaFuncSetAttribute((const void*)mma_gemm<2, 8>, cudaFuncAttributeMaxDynamicSharedMemorySize, GEMM_SMEM_BYTES);
    cudaFuncSetAttribute(phi_kernel, cudaFuncAttributeMaxDynamicSharedMemorySize, S1_SMEM_BYTES);
    cudaFuncSetAttribute(ctx_kernel, cudaFuncAttributeMaxDynamicSharedMemorySize, S2_SMEM_BYTES);
    cudaFuncSetAttribute(att_kernel, cudaFuncAttributeMaxDynamicSharedMemorySize, S3_SMEM_BYTES);

    // side stream + events (created per call; joined into the capture DAG via events)
    cudaStream_t sB;
    cudaStreamCreateWithFlags(&sB, cudaStreamNonBlocking);
    cudaEvent_t evF[L_ + 1], evJ[L_];
    for (int i = 0; i <= L_; i++) cudaEventCreateWithFlags(&evF[i], cudaEventDisableTiming);
    for (int i = 0; i < L_; i++) cudaEventCreateWithFlags(&evJ[i], cudaEventDisableTiming);

    WPtrs wp;
    wp.p[0] = gw1; wp.p[1] = gw2; wp.p[2] = qw; wp.p[3] = kw;
    wp.p[4] = vw;  wp.p[5] = ow;  wp.p[6] = mw1; wp.p[7] = mw2;
    transpose_kernel<<<dim3(16, 16, 40), dim3(32, 8)>>>(wp);
    proj_prep_kernel<<<(L_ * 288 * 64 + 255) / 256, 256>>>(proj);
    node_embed_kernel<<<TN, 256>>>(x, node_w, node_b);
    cudaEventRecord(evF[0], 0);

    // CSR build on side stream (downstream of fork event)
    cudaStreamWaitEvent(sB, evF[0], 0);
    cudaMemsetAsync(p_deg, 0, TN * sizeof(int), sB);
    count_deg_kernel<<<E_ / 256, 256, 0, sB>>>(dst);
    scan_deg_kernel<<<1, 1024, 0, sB>>>();
    fill_adj_kernel<<<E_ / 256, 256, 0, sB>>>(src, dst, eattr);

    dim3 g1(TN / 64, 1), g2(TN / 64, 2), g3(TN / 64, 3);

    for (int l = 0; l < L_; l++) {
        const __half* wt_l = p_wt + l * 655360;
        // ---- chain A (main stream): QKV -> performer ----
        mma_gemm<0, 4><<<g3, 256, GEMM_SMEM_BYTES>>>(p_atoms16, wt_l + 131072, nullptr, nullptr,
                                                     nullptr, nullptr, nullptr, nullptr, p_qkv16, 768);
        phi_kernel<<<dim3(512, 8), 256, S1_SMEM_BYTES>>>(p_qkv16, p_projh + l * 288 * 64, p_kp, p_qp);
        ctx_kernel<<<512, 256, S2_SMEM_BYTES>>>(p_kp, p_qkv16, p_ctx);
        att_kernel<<<512, 256, S3_SMEM_BYTES>>>(p_qp, p_ctx, p_att16);
        // ---- chain B (side stream): GINE -> MLP -> LN (produces hloc) ----
        if (l > 0) cudaStreamWaitEvent(sB, evF[l], 0);
        gine_kernel<<<TN / 8, 256, 0, sB>>>(edge_w, edge_b);
        mma_gemm<1, 4><<<g1, 256, GEMM_SMEM_BYTES, sB>>>(p_h016, wt_l + 0, gb1 + l * C_, nullptr,
                                                         nullptr, nullptr, nullptr, nullptr, p_t116, 256);
        mma_gemm<2, 4><<<g1, 256, GEMM_SMEM_BYTES, sB>>>(p_t116, wt_l + 65536, gb2 + l * C_, p_atoms,
                                                         nullptr, n1g + l * C_, n1b + l * C_,
                                                         p_hloc, nullptr, 256);
        cudaEventRecord(evJ[l], sB);
        cudaStreamWaitEvent(0, evJ[l], 0);
        // ---- join: O-proj + LN + combine, FFN ----
        mma_gemm<2, 4><<<g1, 256, GEMM_SMEM_BYTES>>>(p_att16, wt_l + 327680, ob + l * C_, p_atoms,
                                                     p_hloc, n2g + l * C_, n2b + l * C_,
                                                     p_out, p_out16, 256);
        mma_gemm<1, 4><<<g2, 256, GEMM_SMEM_BYTES>>>(p_out16, wt_l + 393216, mb1 + l * 2 * C_, nullptr,
                                                     nullptr, nullptr, nullptr, nullptr, p_t116, 512);
        mma_gemm<2, 8><<<g1, 256, GEMM_SMEM_BYTES>>>(p_t116, wt_l + 524288, mb2 + l * C_, p_out,
                                                     nullptr, n3g + l * C_, n3b + l * C_,
                                                     p_atoms, p_atoms16, 256);
        cudaEventRecord(evF[l + 1], 0);
    }
    pool_kernel<<<B_, 256>>>((float*)d_out);
}

// round 16
// speedup vs baseline: 6.0897x; 1.0269x over previous
#include <cuda_runtime.h>
#include <cuda_fp16.h>
#include <math.h>
#include <stdint.h>

#define TN   32768
#define C_   256
#define B_   64
#define N_   512
#define H_   4
#define DH_  64
#define M_   266
#define E_   524288
#define L_   5

// ---------------- scratch ----------------
__device__ float  g_atoms[TN * C_];
__device__ __half g_atoms16[TN * C_];
__device__ __half g_h016[TN * C_];
__device__ __half g_t116[TN * 2 * C_];
__device__ float  g_hloc[TN * C_];
__device__ float  g_out[TN * C_];
__device__ __half g_out16[TN * C_];
__device__ __half g_qkv16[(size_t)TN * 3 * C_];
__device__ __half g_att16[TN * C_];
__device__ __half g_wt[L_ * 655360];          // transposed fp16 weights, [n][k]
__device__ __half g_projh[L_ * 288 * 64];     // fp16 proj, rows >=266 zero
__device__ __half g_qp[(size_t)H_ * TN * 288];
__device__ float  g_ctx[2 * 256 * 80 * 320];  // [part][bh][d'][m]
__device__ int    g_deg[TN];
__device__ int    g_indptr[TN + 1];
__device__ int    g_cursor[TN];
__device__ int    g_esrc[E_];                 // CSR-ordered edge source
__device__ float4 g_ea4[E_];                  // CSR-ordered edge attributes

// ---------------- helpers ----------------
__device__ __forceinline__ float gelu_exact(float x) {
    return 0.5f * x * (1.0f + erff(x * 0.70710678118654752f));
}
__device__ __forceinline__ uint32_t f2h2(float a, float b) {
    __half2 h = __floats2half2_rn(a, b);
    return *reinterpret_cast<uint32_t*>(&h);
}
__device__ __forceinline__ uint32_t smem_u32(const void* p) {
    uint32_t a;
    asm("{ .reg .u64 t; cvta.to.shared.u64 t, %1; cvt.u32.u64 %0, t; }" : "=r"(a) : "l"(p));
    return a;
}
__device__ __forceinline__ void mma_f16_16x8x16(float* d, const uint32_t* a, const uint32_t* b) {
    asm volatile(
        "mma.sync.aligned.m16n8k16.row.col.f32.f16.f16.f32 "
        "{%0,%1,%2,%3}, {%4,%5,%6,%7}, {%8,%9}, {%0,%1,%2,%3};"
        : "+f"(d[0]), "+f"(d[1]), "+f"(d[2]), "+f"(d[3])
        : "r"(a[0]), "r"(a[1]), "r"(a[2]), "r"(a[3]), "r"(b[0]), "r"(b[1]));
}
__device__ __forceinline__ void ldsm_x4(uint32_t* r, uint32_t saddr) {
    asm volatile("ldmatrix.sync.aligned.m8n8.x4.shared.b16 {%0,%1,%2,%3}, [%4];"
                 : "=r"(r[0]), "=r"(r[1]), "=r"(r[2]), "=r"(r[3]) : "r"(saddr));
}
__device__ __forceinline__ void ldsm_x4_t(uint32_t* r, uint32_t saddr) {
    asm volatile("ldmatrix.sync.aligned.m8n8.x4.trans.shared.b16 {%0,%1,%2,%3}, [%4];"
                 : "=r"(r[0]), "=r"(r[1]), "=r"(r[2]), "=r"(r[3]) : "r"(saddr));
}
__device__ __forceinline__ void ldsm_x2_t(uint32_t* r, uint32_t saddr) {
    asm volatile("ldmatrix.sync.aligned.m8n8.x2.trans.shared.b16 {%0,%1}, [%2];"
                 : "=r"(r[0]), "=r"(r[1]) : "r"(saddr));
}
__device__ __forceinline__ void cp_async16(uint32_t saddr, const void* gptr) {
    asm volatile("cp.async.cg.shared.global [%0], [%1], 16;" :: "r"(saddr), "l"(gptr));
}
#define CP_COMMIT() asm volatile("cp.async.commit_group;" ::: "memory")
#define CP_WAIT0()  asm volatile("cp.async.wait_group 0;" ::: "memory")

// ---------------- weight transpose (once): WT[n*K+k] = half(W[k*N+n]) ----------------
struct WPtrs { const float* p[8]; };

__global__ void transpose_kernel(WPtrs wp) {
    int z = blockIdx.z;
    int t = z & 7, l = z >> 3;
    int K = (t == 7) ? 512 : 256;
    int N = (t == 6) ? 512 : 256;
    int n0 = blockIdx.x * 32, k0 = blockIdx.y * 32;
    if (n0 >= N || k0 >= K) return;
    const float* src = wp.p[t] + ((t >= 6) ? l * 131072 : l * 65536);
    int doff = (t < 6) ? t * 65536 : (t == 6 ? 393216 : 524288);
    __half* dst = g_wt + l * 655360 + doff;
    __shared__ float s[32][33];
    int tx = threadIdx.x, ty = threadIdx.y;
#pragma unroll
    for (int i = 0; i < 4; i++)
        s[ty + 8 * i][tx] = src[(k0 + ty + 8 * i) * N + n0 + tx];
    __syncthreads();
#pragma unroll
    for (int i = 0; i < 4; i++)
        dst[(n0 + ty + 8 * i) * K + k0 + tx] = __float2half_rn(s[tx][ty + 8 * i]);
}

// ---------------- proj -> fp16, padded to 288 rows ----------------
__global__ void proj_prep_kernel(const float* __restrict__ proj) {
    int idx = blockIdx.x * 256 + threadIdx.x;
    if (idx >= L_ * 288 * 64) return;
    int l = idx / (288 * 64);
    int r = idx - l * (288 * 64);
    int m = r >> 6, d = r & 63;
    g_projh[idx] = (m < M_) ? __float2half_rn(proj[(l * M_ + m) * 64 + d]) : __half(0.f);
}

// ---------------- fp16 mma GEMM, ldmatrix + cp.async, fused LN epilogue ----------------
#define GEMM_SMEM_MAIN  (2 * 9216 + 2 * 36864)
#define GEMM_SMEM_BYTES (GEMM_SMEM_MAIN + 512)

template <int MODE, int NK>
__global__ void __launch_bounds__(256, 2) mma_gemm(const __half* __restrict__ A,
                                                   const __half* __restrict__ WT,
                                                   const float* __restrict__ bias,
                                                   const float* __restrict__ res,
                                                   const float* __restrict__ add2,
                                                   const float* __restrict__ lng,
                                                   const float* __restrict__ lnb,
                                                   float* __restrict__ Out32,
                                                   __half* __restrict__ Out16,
                                                   int Ntot) {
    extern __shared__ uint32_t smw[];
    const int K = NK * 64;
    const int tid = threadIdx.x;
    const int lane = tid & 31, wid = tid >> 5;
    const int g = lane >> 2, t = lane & 3;
    const int wm = (wid & 1) * 32;
    const int wn = (wid >> 1) * 64;
    const int rowbase = blockIdx.x * 64;
    const int colbase = blockIdx.y * 256;
    const uint32_t sb = smem_u32(smw);

    const int l7 = lane & 7, l8 = (lane >> 3) & 1, l16 = (lane >> 4) & 1;
    uint32_t aAddr[2], bAddr[4];
#pragma unroll
    for (int mt = 0; mt < 2; mt++)
        aAddr[mt] = sb + (wm + mt * 16 + l7 + l8 * 8) * 144 + l16 * 16;
#pragma unroll
    for (int p = 0; p < 4; p++)
        bAddr[p] = sb + 18432 + (wn + p * 16 + l7 + l16 * 8) * 144 + l8 * 16;

    float acc[2][8][4];
#pragma unroll
    for (int mt = 0; mt < 2; mt++)
#pragma unroll
        for (int nt = 0; nt < 8; nt++)
#pragma unroll
            for (int j = 0; j < 4; j++) acc[mt][nt][j] = 0.0f;

#pragma unroll
    for (int i = 0; i < 2; i++) {
        int idx = tid + i * 256;
        int m = idx >> 3, c = idx & 7;
        cp_async16(sb + m * 144 + c * 16, A + (size_t)(rowbase + m) * K + c * 8);
    }
#pragma unroll
    for (int i = 0; i < 8; i++) {
        int idx = tid + i * 256;
        int n = idx >> 3, c = idx & 7;
        cp_async16(sb + 18432 + n * 144 + c * 16, WT + (size_t)(colbase + n) * K + c * 8);
    }
    CP_COMMIT();
    CP_WAIT0();
    __syncthreads();

#pragma unroll
    for (int kb = 0; kb < NK; kb++) {
        const int cur = kb & 1;
        const bool nxt = (kb + 1 < NK);
        if (nxt) {
            int k0g = (kb + 1) * 64;
            int sB = cur ^ 1;
#pragma unroll
            for (int i = 0; i < 2; i++) {
                int idx = tid + i * 256;
                int m = idx >> 3, c = idx & 7;
                cp_async16(sb + sB * 9216 + m * 144 + c * 16,
                           A + (size_t)(rowbase + m) * K + k0g + c * 8);
            }
#pragma unroll
            for (int i = 0; i < 8; i++) {
                int idx = tid + i * 256;
                int n = idx >> 3, c = idx & 7;
                cp_async16(sb + 18432 + sB * 36864 + n * 144 + c * 16,
                           WT + (size_t)(colbase + n) * K + k0g + c * 8);
            }
            CP_COMMIT();
        }
        const uint32_t aoff = cur * 9216, boff = cur * 36864;
#pragma unroll
        for (int ks = 0; ks < 4; ks++) {
            uint32_t ar[2][4], br[4][4];
            ldsm_x4(ar[0], aAddr[0] + aoff + ks * 32);
            ldsm_x4(ar[1], aAddr[1] + aoff + ks * 32);
#pragma unroll
            for (int p = 0; p < 4; p++) ldsm_x4(br[p], bAddr[p] + boff + ks * 32);
#pragma unroll
            for (int mt = 0; mt < 2; mt++)
#pragma unroll
                for (int p = 0; p < 4; p++) {
                    mma_f16_16x8x16(acc[mt][2 * p],     ar[mt], &br[p][0]);
                    mma_f16_16x8x16(acc[mt][2 * p + 1], ar[mt], &br[p][2]);
                }
        }
        if (nxt) {
            CP_WAIT0();
            __syncthreads();
        }
    }

    if (MODE <= 1) {
#pragma unroll
        for (int mt = 0; mt < 2; mt++) {
            int r0 = rowbase + wm + mt * 16 + g;
#pragma unroll
            for (int nt = 0; nt < 8; nt++) {
                int col = colbase + wn + nt * 8 + 2 * t;
                float b0 = 0.0f, b1 = 0.0f;
                if (bias) { b0 = bias[col]; b1 = bias[col + 1]; }
                float v0 = acc[mt][nt][0] + b0, v1 = acc[mt][nt][1] + b1;
                float v2 = acc[mt][nt][2] + b0, v3 = acc[mt][nt][3] + b1;
                if (MODE == 1) {
                    v0 = gelu_exact(v0); v1 = gelu_exact(v1);
                    v2 = gelu_exact(v2); v3 = gelu_exact(v3);
                }
                *reinterpret_cast<uint32_t*>(&Out16[(size_t)r0 * Ntot + col]) = f2h2(v0, v1);
                *reinterpret_cast<uint32_t*>(&Out16[(size_t)(r0 + 8) * Ntot + col]) = f2h2(v2, v3);
            }
        }
    } else {
        float* sums = (float*)(smw + GEMM_SMEM_MAIN / 4);   // 64 rows x {s1,s2}
        if (tid < 128) sums[tid] = 0.0f;
        float gg[8][2], bb[8][2];
#pragma unroll
        for (int mt = 0; mt < 2; mt++) {
            int r0 = rowbase + wm + mt * 16 + g;
#pragma unroll
            for (int nt = 0; nt < 8; nt++) {
                int col = wn + nt * 8 + 2 * t;
                float b0 = bias[col], b1 = bias[col + 1];
                float2 r01 = *reinterpret_cast<const float2*>(&res[(size_t)r0 * 256 + col]);
                float2 r23 = *reinterpret_cast<const float2*>(&res[(size_t)(r0 + 8) * 256 + col]);
                acc[mt][nt][0] += b0 + r01.x; acc[mt][nt][1] += b1 + r01.y;
                acc[mt][nt][2] += b0 + r23.x; acc[mt][nt][3] += b1 + r23.y;
            }
        }
        __syncthreads();
#pragma unroll
        for (int mt = 0; mt < 2; mt++)
#pragma unroll
            for (int rh = 0; rh < 2; rh++) {
                float s1 = 0.0f, s2 = 0.0f;
#pragma unroll
                for (int nt = 0; nt < 8; nt++) {
                    float v0 = acc[mt][nt][2 * rh], v1 = acc[mt][nt][2 * rh + 1];
                    s1 += v0 + v1; s2 += v0 * v0 + v1 * v1;
                }
                s1 += __shfl_xor_sync(0xffffffffu, s1, 1);
                s1 += __shfl_xor_sync(0xffffffffu, s1, 2);
                s2 += __shfl_xor_sync(0xffffffffu, s2, 1);
                s2 += __shfl_xor_sync(0xffffffffu, s2, 2);
                if (t == 0) {
                    int rl = wm + mt * 16 + g + rh * 8;
                    atomicAdd(&sums[2 * rl], s1);
                    atomicAdd(&sums[2 * rl + 1], s2);
                }
            }
#pragma unroll
        for (int nt = 0; nt < 8; nt++) {
            int col = wn + nt * 8 + 2 * t;
            gg[nt][0] = lng[col]; gg[nt][1] = lng[col + 1];
            bb[nt][0] = lnb[col]; bb[nt][1] = lnb[col + 1];
        }
        __syncthreads();
#pragma unroll
        for (int mt = 0; mt < 2; mt++) {
#pragma unroll
            for (int rh = 0; rh < 2; rh++) {
                int rl = wm + mt * 16 + g + rh * 8;
                int grow = rowbase + rl;
                float mean = sums[2 * rl] * (1.0f / 256.0f);
                float var = sums[2 * rl + 1] * (1.0f / 256.0f) - mean * mean;
                float rstd = rsqrtf(var + 1e-5f);
#pragma unroll
                for (int nt = 0; nt < 8; nt++) {
                    int col = wn + nt * 8 + 2 * t;
                    float y0 = (acc[mt][nt][2 * rh] - mean) * rstd * gg[nt][0] + bb[nt][0];
                    float y1 = (acc[mt][nt][2 * rh + 1] - mean) * rstd * gg[nt][1] + bb[nt][1];
                    if (add2) {
                        float2 a2 = *reinterpret_cast<const float2*>(&add2[(size_t)grow * 256 + col]);
                        y0 += a2.x; y1 += a2.y;
                    }
                    *reinterpret_cast<float2*>(&Out32[(size_t)grow * 256 + col]) = make_float2(y0, y1);
                    if (Out16)
                        *reinterpret_cast<uint32_t*>(&Out16[(size_t)grow * 256 + col]) = f2h2(y0, y1);
                }
            }
        }
    }
}

// ---------------- Performer stage 1 (qp only now) ----------------
#define S1_SMEM_BYTES ((2304 + 10368) * 4)

__global__ void __launch_bounds__(256) phi_kernel(const __half* __restrict__ QKV,
                                                  const __half* __restrict__ projh_l,
                                                  __half* __restrict__ QP) {
    extern __shared__ uint32_t sw[];
    uint32_t* As = sw;
    uint32_t* Bs = sw + 2304;
    const int tid = threadIdx.x;
    const int lane = tid & 31, wid = tid >> 5;
    const int g = lane >> 2, t = lane & 3;
    const int wm = (wid & 1) * 32;
    const int wn = (wid >> 1) * 72;
    const int rowbase = blockIdx.x * 64;
    const int h = blockIdx.y;
    const __half* Ah = QKV + h * 64;
    __half* outp = QP + (size_t)h * TN * 288;
    const uint32_t sbA = smem_u32(As);

#pragma unroll
    for (int i = 0; i < 2; i++) {
        int idx = tid + i * 256;
        int m = idx >> 3, c = idx & 7;
        cp_async16(sbA + m * 144 + c * 16, Ah + (size_t)(rowbase + m) * 768 + c * 8);
    }
    CP_COMMIT();
    const uint32_t* pb = (const uint32_t*)projh_l;
#pragma unroll
    for (int i = 0; i < 36; i++) {
        int w = tid + i * 256;
        Bs[(w >> 5) * 36 + (w & 31)] = pb[w];
    }
    CP_WAIT0();
    __syncthreads();

    float acc[2][9][4];
#pragma unroll
    for (int mt = 0; mt < 2; mt++)
#pragma unroll
        for (int nt = 0; nt < 9; nt++)
#pragma unroll
            for (int j = 0; j < 4; j++) acc[mt][nt][j] = 0.0f;

#pragma unroll
    for (int ks = 0; ks < 4; ks++) {
        int k0 = ks * 8;
        uint32_t af[2][4], bf[9][2];
#pragma unroll
        for (int mt = 0; mt < 2; mt++) {
            int r0 = wm + mt * 16 + g;
            af[mt][0] = As[r0 * 36 + k0 + t];
            af[mt][1] = As[(r0 + 8) * 36 + k0 + t];
            af[mt][2] = As[r0 * 36 + k0 + t + 4];
            af[mt][3] = As[(r0 + 8) * 36 + k0 + t + 4];
        }
#pragma unroll
        for (int nt = 0; nt < 9; nt++) {
            int n0 = wn + nt * 8 + g;
            bf[nt][0] = Bs[n0 * 36 + k0 + t];
            bf[nt][1] = Bs[n0 * 36 + k0 + t + 4];
        }
#pragma unroll
        for (int mt = 0; mt < 2; mt++)
#pragma unroll
            for (int nt = 0; nt < 9; nt++)
                mma_f16_16x8x16(acc[mt][nt], af[mt], bf[nt]);
    }

#pragma unroll
    for (int mt = 0; mt < 2; mt++) {
        int r = rowbase + wm + mt * 16 + g;
#pragma unroll
        for (int nt = 0; nt < 9; nt++) {
            int c0 = wn + nt * 8 + 2 * t;
            float v0 = fmaxf(acc[mt][nt][0], 0.0f) + 1e-3f;
            float v1 = fmaxf(acc[mt][nt][1], 0.0f) + 1e-3f;
            float v2 = fmaxf(acc[mt][nt][2], 0.0f) + 1e-3f;
            float v3 = fmaxf(acc[mt][nt][3], 0.0f) + 1e-3f;
            if (c0 >= M_) { v0 = 0.0f; v2 = 0.0f; }
            if (c0 + 1 >= M_) { v1 = 0.0f; v3 = 0.0f; }
            *reinterpret_cast<uint32_t*>(&outp[(size_t)r * 288 + c0]) = f2h2(v0, v1);
            *reinterpret_cast<uint32_t*>(&outp[(size_t)(r + 8) * 288 + c0]) = f2h2(v2, v3);
        }
    }
}

// ---------------- Performer stage 2: fused kp compute + ctx partials ----------------
// smem: proj_s 288x36 words | k_s 64x36 words | kp_s 64x336 halves | vs 64x88 halves
#define S2_PROJ_WORDS (288 * 36)
#define S2_K_OFF_W    S2_PROJ_WORDS
#define S2_KP_OFF_B   ((S2_PROJ_WORDS + 2304) * 4)     // 50688
#define S2_VS_OFF_B   (S2_KP_OFF_B + 64 * 336 * 2)     // 93696
#define S2_SMEM_BYTES (S2_VS_OFF_B + 64 * 88 * 2)      // 104960

__global__ void __launch_bounds__(256) ctx_kernel(const __half* __restrict__ QKV,
                                                  const __half* __restrict__ projh_l,
                                                  float* __restrict__ CTX) {
    extern __shared__ uint32_t sw[];
    uint32_t* proj_s = sw;
    uint32_t* k_s = sw + S2_K_OFF_W;
    __half* kp_h = (__half*)((char*)sw + S2_KP_OFF_B);
    __half* vs_h = (__half*)((char*)sw + S2_VS_OFF_B);
    const int tid = threadIdx.x;
    const int lane = tid & 31, wid = tid >> 5;
    const int g = lane >> 2, t = lane & 3;
    // ctx-phase warp layout
    const int wm = (wid & 3) * 80;
    const int wn = (wid >> 2) * 40;
    // kp-phase warp layout
    const int wmP = (wid & 1) * 32;
    const int wnP = (wid >> 1) * 72;
    const int part = blockIdx.x >> 8;
    const int bh = blockIdx.x & 255;
    const int b = bh >> 2, h = bh & 3;
    const uint32_t sb = smem_u32(sw);
    const uint32_t kpB = sb + S2_KP_OFF_B;
    const uint32_t vsB = sb + S2_VS_OFF_B;
    const int l7 = lane & 7, l8 = (lane >> 3) & 1, l16 = (lane >> 4) & 1;

    // load proj (once)
    const uint32_t* pb = (const uint32_t*)projh_l;
#pragma unroll
    for (int i = 0; i < 36; i++) {
        int w = tid + i * 256;
        proj_s[(w >> 5) * 36 + (w & 31)] = pb[w];
    }
    // pads (once): kp cols 288..335, vs cols 64..87 (col 64 = ones)
    for (int i = tid; i < 64 * 48; i += 256) {
        int n = i / 48, c = 288 + i % 48;
        kp_h[n * 336 + c] = __float2half(0.0f);
    }
    for (int i = tid; i < 64 * 24; i += 256) {
        int n = i / 24, c = 64 + i % 24;
        vs_h[n * 88 + c] = __float2half(c == 64 ? 1.0f : 0.0f);
    }

    uint32_t aBase = kpB + ((l16 * 8 + l7) * 336 + wm + l8 * 8) * 2;
    int bl = lane & 15;
    uint32_t bBase = vsB + (((bl >> 3) * 8 + (bl & 7)) * 88 + wn) * 2;

    float acc[5][5][4];
#pragma unroll
    for (int mt = 0; mt < 5; mt++)
#pragma unroll
        for (int nt = 0; nt < 5; nt++)
#pragma unroll
            for (int j = 0; j < 4; j++) acc[mt][nt][j] = 0.0f;

    for (int c = 0; c < 4; c++) {
        __syncthreads();
        int base = b * 512 + (part * 4 + c) * 64;
        // stage K and V rows for this chunk
#pragma unroll
        for (int i = 0; i < 2; i++) {
            int idx = tid + i * 256;
            int n = idx >> 3, cc = idx & 7;
            cp_async16(sb + (S2_K_OFF_W + n * 36 + cc * 4) * 4,
                       QKV + (size_t)(base + n) * 768 + 256 + h * 64 + cc * 8);
        }
#pragma unroll
        for (int i = 0; i < 2; i++) {
            int idx = tid + i * 256;
            int n = idx >> 3, cc = idx & 7;
            cp_async16(vsB + (n * 88 + cc * 8) * 2,
                       QKV + (size_t)(base + n) * 768 + 512 + h * 64 + cc * 8);
        }
        CP_COMMIT();
        CP_WAIT0();
        __syncthreads();

        // ---- kp = relu(K @ projT) + eps, into kp_s ----
        {
            float ac2[2][9][4];
#pragma unroll
            for (int mt = 0; mt < 2; mt++)
#pragma unroll
                for (int nt = 0; nt < 9; nt++)
#pragma unroll
                    for (int j = 0; j < 4; j++) ac2[mt][nt][j] = 0.0f;
#pragma unroll
            for (int ks = 0; ks < 4; ks++) {
                int k0 = ks * 8;
                uint32_t af[2][4], bf[9][2];
#pragma unroll
                for (int mt = 0; mt < 2; mt++) {
                    int r0 = wmP + mt * 16 + g;
                    af[mt][0] = k_s[r0 * 36 + k0 + t];
                    af[mt][1] = k_s[(r0 + 8) * 36 + k0 + t];
                    af[mt][2] = k_s[r0 * 36 + k0 + t + 4];
                    af[mt][3] = k_s[(r0 + 8) * 36 + k0 + t + 4];
                }
#pragma unroll
                for (int nt = 0; nt < 9; nt++) {
                    int n0 = wnP + nt * 8 + g;
                    bf[nt][0] = proj_s[n0 * 36 + k0 + t];
                    bf[nt][1] = proj_s[n0 * 36 + k0 + t + 4];
                }
#pragma unroll
                for (int mt = 0; mt < 2; mt++)
#pragma unroll
                    for (int nt = 0; nt < 9; nt++)
                        mma_f16_16x8x16(ac2[mt][nt], af[mt], bf[nt]);
            }
#pragma unroll
            for (int mt = 0; mt < 2; mt++) {
                int r = wmP + mt * 16 + g;
#pragma unroll
                for (int nt = 0; nt < 9; nt++) {
                    int c0 = wnP + nt * 8 + 2 * t;
                    float v0 = fmaxf(ac2[mt][nt][0], 0.0f) + 1e-3f;
                    float v1 = fmaxf(ac2[mt][nt][1], 0.0f) + 1e-3f;
                    float v2 = fmaxf(ac2[mt][nt][2], 0.0f) + 1e-3f;
                    float v3 = fmaxf(ac2[mt][nt][3], 0.0f) + 1e-3f;
                    if (c0 >= M_) { v0 = 0.0f; v2 = 0.0f; }
                    if (c0 + 1 >= M_) { v1 = 0.0f; v3 = 0.0f; }
                    *reinterpret_cast<uint32_t*>(&kp_h[r * 336 + c0]) = f2h2(v0, v1);
                    *reinterpret_cast<uint32_t*>(&kp_h[(r + 8) * 336 + c0]) = f2h2(v2, v3);
                }
            }
        }
        __syncthreads();

        // ---- ctx += kp^T @ V' ----
#pragma unroll
        for (int ks = 0; ks < 4; ks++) {
            uint32_t af[5][4], bf[5][2];
            uint32_t aK = aBase + ks * 16 * 336 * 2;
            uint32_t bK = bBase + ks * 16 * 88 * 2;
#pragma unroll
            for (int mt = 0; mt < 5; mt++) ldsm_x4_t(af[mt], aK + mt * 32);
#pragma unroll
            for (int nt = 0; nt < 5; nt++) ldsm_x2_t(bf[nt], bK + nt * 16);
#pragma unroll
            for (int mt = 0; mt < 5; mt++)
#pragma unroll
                for (int nt = 0; nt < 5; nt++)
                    mma_f16_16x8x16(acc[mt][nt], af[mt], bf[nt]);
        }
    }

    float* outc = CTX + ((size_t)part * 256 + bh) * 80 * 320;
#pragma unroll
    for (int mt = 0; mt < 5; mt++) {
        int m0 = wm + mt * 16 + g;
#pragma unroll
        for (int nt = 0; nt < 5; nt++) {
            int c0 = wn + nt * 8 + 2 * t;
            outc[(size_t)c0 * 320 + m0] = acc[mt][nt][0];
            outc[(size_t)(c0 + 1) * 320 + m0] = acc[mt][nt][1];
            outc[(size_t)c0 * 320 + m0 + 8] = acc[mt][nt][2];
            outc[(size_t)(c0 + 1) * 320 + m0 + 8] = acc[mt][nt][3];
        }
    }
}

// ---------------- Performer stage 3 ----------------
#define S3_W_CTX (80 * 164)
#define S3_W_AS  (64 * 148)
#define S3_W_ATT (64 * 80)
#define S3_SMEM_BYTES ((S3_W_CTX + S3_W_AS + S3_W_ATT) * 4)

__global__ void __launch_bounds__(256) att_kernel(const __half* __restrict__ QP,
                                                  const float* __restrict__ CTX,
                                                  __half* __restrict__ Att) {
    extern __shared__ uint32_t sw[];
    uint32_t* ctxT = sw;
    uint32_t* As = sw + S3_W_CTX;
    float* att_s = (float*)(sw + S3_W_CTX + S3_W_AS);
    const int tid = threadIdx.x;
    const int lane = tid & 31, wid = tid >> 5;
    const int g = lane >> 2, t = lane & 3;
    const int wm = (wid & 3) * 16;
    const int wn = (wid >> 2) * 40;
    const int cta = blockIdx.x;
    const int bh = cta >> 1, half = cta & 1;
    const int b = bh >> 2, h = bh & 3;

    const float* cg0 = CTX + (size_t)bh * 80 * 320;
    const float* cg1 = CTX + ((size_t)256 + bh) * 80 * 320;
#pragma unroll
    for (int i = 0; i < 50; i++) {
        int idx = tid + i * 256;
        int d = idx / 160, m2 = idx - d * 160;
        size_t o = (size_t)d * 320 + m2 * 2;
        float2 v0 = *reinterpret_cast<const float2*>(&cg0[o]);
        float2 v1 = *reinterpret_cast<const float2*>(&cg1[o]);
        ctxT[d * 164 + m2] = f2h2(v0.x + v1.x, v0.y + v1.y);
    }
    const uint32_t* qp2 = (const uint32_t*)(QP + (size_t)h * TN * 288);
    const int rowg0 = b * 512 + half * 256;

    for (int ch = 0; ch < 4; ch++) {
        __syncthreads();
        int rbase = rowg0 + ch * 64;
#pragma unroll
        for (int i = 0; i < 36; i++) {
            int idx = tid + i * 256;
            int n = idx / 144, m2 = idx - n * 144;
            As[n * 148 + m2] = qp2[(size_t)(rbase + n) * 144 + m2];
        }
        __syncthreads();
        float acc[5][4];
#pragma unroll
        for (int nt = 0; nt < 5; nt++)
#pragma unroll
            for (int j = 0; j < 4; j++) acc[nt][j] = 0.0f;
#pragma unroll
        for (int ks = 0; ks < 17; ks++) {
            int k0 = ks * 8;
            uint32_t af[4], bf[5][2];
            int r0 = wm + g;
            af[0] = As[r0 * 148 + k0 + t];
            af[1] = As[(r0 + 8) * 148 + k0 + t];
            af[2] = As[r0 * 148 + k0 + t + 4];
            af[3] = As[(r0 + 8) * 148 + k0 + t + 4];
#pragma unroll
            for (int nt = 0; nt < 5; nt++) {
                int n0 = wn + nt * 8 + g;
                bf[nt][0] = ctxT[n0 * 164 + k0 + t];
                bf[nt][1] = ctxT[n0 * 164 + k0 + t + 4];
            }
#pragma unroll
            for (int nt = 0; nt < 5; nt++)
                mma_f16_16x8x16(acc[nt], af, bf[nt]);
        }
#pragma unroll
        for (int nt = 0; nt < 5; nt++) {
            int c0 = wn + nt * 8 + 2 * t;
            att_s[(wm + g) * 80 + c0] = acc[nt][0];
            att_s[(wm + g) * 80 + c0 + 1] = acc[nt][1];
            att_s[(wm + g + 8) * 80 + c0] = acc[nt][2];
            att_s[(wm + g + 8) * 80 + c0 + 1] = acc[nt][3];
        }
        __syncthreads();
#pragma unroll
        for (int i = 0; i < 16; i++) {
            int idx = tid + i * 256;
            int n = idx >> 6, d = idx & 63;
            float den = att_s[n * 80 + 64];
            Att[(size_t)(rbase + n) * 256 + h * 64 + d] = __float2half_rn(att_s[n * 80 + d] / den);
        }
    }
}

// ---------------- node embedding ----------------
__global__ void node_embed_kernel(const float* __restrict__ x,
                                  const float* __restrict__ w,
                                  const float* __restrict__ b) {
    __shared__ float lx[11];
    int row = blockIdx.x;
    int t = threadIdx.x;
    if (t < 11) lx[t] = log1pf(x[row * 11 + t]);
    __syncthreads();
    float s = b[t];
#pragma unroll
    for (int j = 0; j < 11; j++) s += lx[j] * w[j * C_ + t];
    g_atoms[row * C_ + t] = s;
    g_atoms16[row * C_ + t] = __float2half_rn(s);
}

// ---------------- CSR build ----------------
__global__ void count_deg_kernel(const int* __restrict__ dst) {
    int e = blockIdx.x * blockDim.x + threadIdx.x;
    if (e < E_) atomicAdd(&g_deg[dst[e]], 1);
}
__global__ void scan_deg_kernel() {
    __shared__ int sh[1024];
    __shared__ int carry;
    int t = threadIdx.x;
    if (t == 0) carry = 0;
    __syncthreads();
    for (int base = 0; base < TN; base += 1024) {
        int v = g_deg[base + t];
        sh[t] = v;
        __syncthreads();
        for (int off = 1; off < 1024; off <<= 1) {
            int add = (t >= off) ? sh[t - off] : 0;
            __syncthreads();
            sh[t] += add;
            __syncthreads();
        }
        int ip = carry + sh[t] - v;
        g_indptr[base + t] = ip;
        g_cursor[base + t] = ip;
        __syncthreads();
        if (t == 0) carry += sh[1023];
        __syncthreads();
    }
    if (t == 0) g_indptr[TN] = carry;
}
__global__ void fill_adj_kernel(const int* __restrict__ src,
                                const int* __restrict__ dst,
                                const float* __restrict__ eattr) {
    int e = blockIdx.x * blockDim.x + threadIdx.x;
    if (e < E_) {
        int p = atomicAdd(&g_cursor[dst[e]], 1);
        g_esrc[p] = src[e];
        g_ea4[p] = *reinterpret_cast<const float4*>(&eattr[e * 4]);
    }
}

// ---------------- GINE aggregation: CSR payloads + 4-edge unroll ----------------
__global__ void __launch_bounds__(256) gine_kernel(const float* __restrict__ ew,
                                                   const float* __restrict__ eb) {
    int tid = threadIdx.x;
    int warp = tid >> 5, lane = tid & 31;
    int v = blockIdx.x * 8 + warp;
    const int c0 = lane * 8;

    float ewr[4][8], ebr[8];
#pragma unroll
    for (int j = 0; j < 4; j++) {
        float4 w0 = *reinterpret_cast<const float4*>(&ew[j * C_ + c0]);
        float4 w1 = *reinterpret_cast<const float4*>(&ew[j * C_ + c0 + 4]);
        ewr[j][0] = w0.x; ewr[j][1] = w0.y; ewr[j][2] = w0.z; ewr[j][3] = w0.w;
        ewr[j][4] = w1.x; ewr[j][5] = w1.y; ewr[j][6] = w1.z; ewr[j][7] = w1.w;
    }
    {
        float4 b0 = *reinterpret_cast<const float4*>(&eb[c0]);
        float4 b1 = *reinterpret_cast<const float4*>(&eb[c0 + 4]);
        ebr[0] = b0.x; ebr[1] = b0.y; ebr[2] = b0.z; ebr[3] = b0.w;
        ebr[4] = b1.x; ebr[5] = b1.y; ebr[6] = b1.z; ebr[7] = b1.w;
    }

    float acc[8];
    {
        float4 a0 = *reinterpret_cast<const float4*>(&g_atoms[(size_t)v * C_ + c0]);
        float4 a1 = *reinterpret_cast<const float4*>(&g_atoms[(size_t)v * C_ + c0 + 4]);
        acc[0] = a0.x; acc[1] = a0.y; acc[2] = a0.z; acc[3] = a0.w;
        acc[4] = a1.x; acc[5] = a1.y; acc[6] = a1.z; acc[7] = a1.w;
    }

    int p0 = g_indptr[v], p1 = g_indptr[v + 1];
    int p = p0;
    for (; p + 3 < p1; p += 4) {
        int s[4];
        float4 ea[4];
        uint4 hv[4];
#pragma unroll
        for (int q = 0; q < 4; q++) { s[q] = g_esrc[p + q]; ea[q] = g_ea4[p + q]; }
#pragma unroll
        for (int q = 0; q < 4; q++)
            hv[q] = *reinterpret_cast<const uint4*>(&g_atoms16[(size_t)s[q] * C_ + c0]);
#pragma unroll
        for (int q = 0; q < 4; q++) {
            float2 f0 = __half22float2(*reinterpret_cast<__half2*>(&hv[q].x));
            float2 f1 = __half22float2(*reinterpret_cast<__half2*>(&hv[q].y));
            float2 f2 = __half22float2(*reinterpret_cast<__half2*>(&hv[q].z));
            float2 f3 = __half22float2(*reinterpret_cast<__half2*>(&hv[q].w));
            float av[8] = {f0.x, f0.y, f1.x, f1.y, f2.x, f2.y, f3.x, f3.y};
#pragma unroll
            for (int i = 0; i < 8; i++) {
                float eac = ebr[i] + ea[q].x * ewr[0][i] + ea[q].y * ewr[1][i]
                                   + ea[q].z * ewr[2][i] + ea[q].w * ewr[3][i];
                acc[i] += fmaxf(av[i] + eac, 0.0f);
            }
        }
    }
    for (; p < p1; p++) {
        int s = g_esrc[p];
        float4 ea4 = g_ea4[p];
        uint4 hv = *reinterpret_cast<const uint4*>(&g_atoms16[(size_t)s * C_ + c0]);
        float2 f0 = __half22float2(*reinterpret_cast<__half2*>(&hv.x));
        float2 f1 = __half22float2(*reinterpret_cast<__half2*>(&hv.y));
        float2 f2 = __half22float2(*reinterpret_cast<__half2*>(&hv.z));
        float2 f3 = __half22float2(*reinterpret_cast<__half2*>(&hv.w));
        float av[8] = {f0.x, f0.y, f1.x, f1.y, f2.x, f2.y, f3.x, f3.y};
#pragma unroll
        for (int i = 0; i < 8; i++) {
            float eac = ebr[i] + ea4.x * ewr[0][i] + ea4.y * ewr[1][i]
                               + ea4.z * ewr[2][i] + ea4.w * ewr[3][i];
            acc[i] += fmaxf(av[i] + eac, 0.0f);
        }
    }
    uint4 hout;
    hout.x = f2h2(acc[0], acc[1]);
    hout.y = f2h2(acc[2], acc[3]);
    hout.z = f2h2(acc[4], acc[5]);
    hout.w = f2h2(acc[6], acc[7]);
    *reinterpret_cast<uint4*>(&g_h016[(size_t)v * C_ + c0]) = hout;
}

// ---------------- final mean pool ----------------
__global__ void pool_kernel(float* __restrict__ out) {
    int b = blockIdx.x;
    int cix = threadIdx.x;
    float s = 0.0f;
    for (int n = 0; n < N_; n++) s += g_atoms[(b * N_ + n) * C_ + cix];
    out[b * C_ + cix] = s * (1.0f / (float)N_);
}

// ---------------- host launcher ----------------
extern "C" void kernel_launch(void* const* d_in, const int* in_sizes, int n_in,
                              void* d_out, int out_size) {
    const float* x      = (const float*)d_in[0];
    const float* eattr  = (const float*)d_in[1];
    const int*   eidx   = (const int*)d_in[2];
    const float* node_w = (const float*)d_in[4];
    const float* node_b = (const float*)d_in[5];
    const float* edge_w = (const float*)d_in[6];
    const float* edge_b = (const float*)d_in[7];
    const float* gw1    = (const float*)d_in[8];
    const float* gb1    = (const float*)d_in[9];
    const float* gw2    = (const float*)d_in[10];
    const float* gb2    = (const float*)d_in[11];
    const float* qw     = (const float*)d_in[12];
    const float* kw     = (const float*)d_in[13];
    const float* vw     = (const float*)d_in[14];
    const float* ow     = (const float*)d_in[15];
    const float* ob     = (const float*)d_in[16];
    const float* proj   = (const float*)d_in[17];
    const float* n1g    = (const float*)d_in[18];
    const float* n1b    = (const float*)d_in[19];
    const float* n2g    = (const float*)d_in[20];
    const float* n2b    = (const float*)d_in[21];
    const float* n3g    = (const float*)d_in[22];
    const float* n3b    = (const float*)d_in[23];
    const float* mw1    = (const float*)d_in[24];
    const float* mb1    = (const float*)d_in[25];
    const float* mw2    = (const float*)d_in[26];
    const float* mb2    = (const float*)d_in[27];

    const int* src = eidx;
    const int* dst = eidx + E_;

    float *p_atoms, *p_hloc, *p_out, *p_ctx;
    __half *p_atoms16, *p_h016, *p_t116, *p_out16, *p_qkv16, *p_att16;
    __half *p_wt, *p_projh, *p_qp;
    int* p_deg;
    cudaGetSymbolAddress((void**)&p_atoms,   g_atoms);
    cudaGetSymbolAddress((void**)&p_atoms16, g_atoms16);
    cudaGetSymbolAddress((void**)&p_h016,    g_h016);
    cudaGetSymbolAddress((void**)&p_t116,    g_t116);
    cudaGetSymbolAddress((void**)&p_hloc,    g_hloc);
    cudaGetSymbolAddress((void**)&p_out,     g_out);
    cudaGetSymbolAddress((void**)&p_out16,   g_out16);
    cudaGetSymbolAddress((void**)&p_qkv16,   g_qkv16);
    cudaGetSymbolAddress((void**)&p_att16,   g_att16);
    cudaGetSymbolAddress((void**)&p_ctx,     g_ctx);
    cudaGetSymbolAddress((void**)&p_wt,      g_wt);
    cudaGetSymbolAddress((void**)&p_projh,   g_projh);
    cudaGetSymbolAddress((void**)&p_qp,      g_qp);
    cudaGetSymbolAddress((void**)&p_deg,     g_deg);

    cudaFuncSetAttribute((const void*)mma_gemm<0, 4>, cudaFuncAttributeMaxDynamicSharedMemorySize, GEMM_SMEM_BYTES);
    cudaFuncSetAttribute((const void*)mma_gemm<1, 4>, cudaFuncAttributeMaxDynamicSharedMemorySize, GEMM_SMEM_BYTES);
    cudaFuncSetAttribute((const void*)mma_gemm<2, 4>, cudaFuncAttributeMaxDynamicSharedMemorySize, GEMM_SMEM_BYTES);
    cudaFuncSetAttribute((const void*)mma_gemm<2, 8>, cudaFuncAttributeMaxDynamicSharedMemorySize, GEMM_SMEM_BYTES);
    cudaFuncSetAttribute(phi_kernel, cudaFuncAttributeMaxDynamicSharedMemorySize, S1_SMEM_BYTES);
    cudaFuncSetAttribute(ctx_kernel, cudaFuncAttributeMaxDynamicSharedMemorySize, S2_SMEM_BYTES);
    cudaFuncSetAttribute(att_kernel, cudaFuncAttributeMaxDynamicSharedMemorySize, S3_SMEM_BYTES);

    cudaStream_t sB;
    cudaStreamCreateWithFlags(&sB, cudaStreamNonBlocking);
    cudaEvent_t evF[L_ + 1], evJ[L_], evK[L_], evQ[L_];
    for (int i = 0; i <= L_; i++) cudaEventCreateWithFlags(&evF[i], cudaEventDisableTiming);
    for (int i = 0; i < L_; i++) {
        cudaEventCreateWithFlags(&evJ[i], cudaEventDisableTiming);
        cudaEventCreateWithFlags(&evK[i], cudaEventDisableTiming);
        cudaEventCreateWithFlags(&evQ[i], cudaEventDisableTiming);
    }

    WPtrs wp;
    wp.p[0] = gw1; wp.p[1] = gw2; wp.p[2] = qw; wp.p[3] = kw;
    wp.p[4] = vw;  wp.p[5] = ow;  wp.p[6] = mw1; wp.p[7] = mw2;
    transpose_kernel<<<dim3(16, 16, 40), dim3(32, 8)>>>(wp);
    proj_prep_kernel<<<(L_ * 288 * 64 + 255) / 256, 256>>>(proj);
    node_embed_kernel<<<TN, 256>>>(x, node_w, node_b);
    cudaEventRecord(evF[0], 0);

    // CSR build on side stream
    cudaStreamWaitEvent(sB, evF[0], 0);
    cudaMemsetAsync(p_deg, 0, TN * sizeof(int), sB);
    count_deg_kernel<<<E_ / 256, 256, 0, sB>>>(dst);
    scan_deg_kernel<<<1, 1024, 0, sB>>>();
    fill_adj_kernel<<<E_ / 256, 256, 0, sB>>>(src, dst, eattr);

    dim3 g1(TN / 64, 1), g2(TN / 64, 2), g3(TN / 64, 3);

    for (int l = 0; l < L_; l++) {
        const __half* wt_l = p_wt + l * 655360;
        const __half* projh_l = p_projh + l * 288 * 64;
        // ---- main: QKV -> ctx (fused kp) ----
        mma_gemm<0, 4><<<g3, 256, GEMM_SMEM_BYTES>>>(p_atoms16, wt_l + 131072, nullptr, nullptr,
                                                     nullptr, nullptr, nullptr, nullptr, p_qkv16, 768);
        cudaEventRecord(evK[l], 0);
        ctx_kernel<<<512, 256, S2_SMEM_BYTES>>>(p_qkv16, projh_l, p_ctx);
        // ---- side: GINE -> phi(q) -> MLP1 -> MLP2-LN ----
        if (l > 0) cudaStreamWaitEvent(sB, evF[l], 0);
        gine_kernel<<<TN / 8, 256, 0, sB>>>(edge_w, edge_b);
        cudaStreamWaitEvent(sB, evK[l], 0);
        phi_kernel<<<dim3(512, 4), 256, S1_SMEM_BYTES, sB>>>(p_qkv16, projh_l, p_qp);
        cudaEventRecord(evQ[l], sB);
        mma_gemm<1, 4><<<g1, 256, GEMM_SMEM_BYTES, sB>>>(p_h016, wt_l + 0, gb1 + l * C_, nullptr,
                                                         nullptr, nullptr, nullptr, nullptr, p_t116, 256);
        mma_gemm<2, 4><<<g1, 256, GEMM_SMEM_BYTES, sB>>>(p_t116, wt_l + 65536, gb2 + l * C_, p_atoms,
                                                         nullptr, n1g + l * C_, n1b + l * C_,
                                                         p_hloc, nullptr, 256);
        cudaEventRecord(evJ[l], sB);
        // ---- main: att (needs qp), then join ----
        cudaStreamWaitEvent(0, evQ[l], 0);
        att_kernel<<<512, 256, S3_SMEM_BYTES>>>(p_qp, p_ctx, p_att16);
        cudaStreamWaitEvent(0, evJ[l], 0);
        mma_gemm<2, 4><<<g1, 256, GEMM_SMEM_BYTES>>>(p_att16, wt_l + 327680, ob + l * C_, p_atoms,
                                                     p_hloc, n2g + l * C_, n2b + l * C_,
                                                     p_out, p_out16, 256);
        mma_gemm<1, 4><<<g2, 256, GEMM_SMEM_BYTES>>>(p_out16, wt_l + 393216, mb1 + l * 2 * C_, nullptr,
                                                     nullptr, nullptr, nullptr, nullptr, p_t116, 512);
        mma_gemm<2, 8><<<g1, 256, GEMM_SMEM_BYTES>>>(p_t116, wt_l + 524288, mb2 + l * C_, p_out,
                                                     nullptr, n3g + l * C_, n3b + l * C_,
                                                     p_atoms, p_atoms16, 256);
        cudaEventRecord(evF[l + 1], 0);
    }
    pool_kernel<<<B_, 256>>>((float*)d_out);
}